// round 7
// baseline (speedup 1.0000x reference)
#include <cuda_runtime.h>
#include <cuda_bf16.h>
#include <cstdint>
#include <math.h>

// ---------------- problem constants ----------------
#define BB     4
#define SS     4096
#define HIDD   1024
#define NHH    16
#define DD     64
#define WINN   512
#define CHUNKK 128
#define NWW    8
#define NCC    32
#define SCALEF 0.125f
#define MTOK   (BB*SS)   // 16384
#define GK     1024
#define GN     1024

// ---------------- scratch (device globals) ----------------
__device__ float g_q[MTOK*HIDD];
__device__ float g_k[MTOK*HIDD];
__device__ float g_v[MTOK*HIDD];
__device__ float g_attn[MTOK*HIDD];
__device__ float g_rfak[BB*NHH*NCC*DD];
__device__ float g_rfav[BB*NHH*NCC*DD];
// pre-split bf16 operands
__device__ __nv_bfloat16 g_hid_h[MTOK*HIDD];
__device__ __nv_bfloat16 g_hid_l[MTOK*HIDD];
__device__ __nv_bfloat16 g_ao_h[MTOK*HIDD];
__device__ __nv_bfloat16 g_ao_l[MTOK*HIDD];
__device__ __nv_bfloat16 g_w_h[4*HIDD*HIDD];
__device__ __nv_bfloat16 g_w_l[4*HIDD*HIDD];

// ================= helpers =================
__device__ __forceinline__ uint32_t smem_u32(const void* p) {
    uint32_t a;
    asm("{ .reg .u64 t; cvta.to.shared.u64 t, %1; cvt.u32.u64 %0, t; }" : "=r"(a) : "l"(p));
    return a;
}

#define LDSM_X4(r, a)                                                          \
    asm volatile("ldmatrix.sync.aligned.m8n8.x4.shared.b16 {%0,%1,%2,%3}, [%4];" \
        : "=r"((r)[0]), "=r"((r)[1]), "=r"((r)[2]), "=r"((r)[3]) : "r"(a))

#define LDSM_X4T(r, a)                                                         \
    asm volatile("ldmatrix.sync.aligned.m8n8.x4.trans.shared.b16 {%0,%1,%2,%3}, [%4];" \
        : "=r"((r)[0]), "=r"((r)[1]), "=r"((r)[2]), "=r"((r)[3]) : "r"(a))

#define MMA16816(c, a, b0, b1)                                                 \
    asm volatile("mma.sync.aligned.m16n8k16.row.col.f32.bf16.bf16.f32 "        \
        "{%0,%1,%2,%3}, {%4,%5,%6,%7}, {%8,%9}, {%0,%1,%2,%3};"                \
        : "+f"((c)[0]), "+f"((c)[1]), "+f"((c)[2]), "+f"((c)[3])               \
        : "r"((a)[0]), "r"((a)[1]), "r"((a)[2]), "r"((a)[3]), "r"(b0), "r"(b1))

#define MMA16816R(c, a0, a1, a2, a3, b0, b1)                                   \
    asm volatile("mma.sync.aligned.m16n8k16.row.col.f32.bf16.bf16.f32 "        \
        "{%0,%1,%2,%3}, {%4,%5,%6,%7}, {%8,%9}, {%0,%1,%2,%3};"                \
        : "+f"((c)[0]), "+f"((c)[1]), "+f"((c)[2]), "+f"((c)[3])               \
        : "r"(a0), "r"(a1), "r"(a2), "r"(a3), "r"(b0), "r"(b1))

#define CPASYNC16(dst, src) \
    asm volatile("cp.async.cg.shared.global [%0], [%1], 16;" :: "r"(dst), "l"(src) : "memory")
#define CPCOMMIT() asm volatile("cp.async.commit_group;" ::: "memory")
#define CPWAIT2()  asm volatile("cp.async.wait_group 2;" ::: "memory")

__device__ __forceinline__ void cvtsts(float4 f, uint32_t dhi, uint32_t dlo) {
    __nv_bfloat162 h0, h1, l0, l1;
    h0.x = __float2bfloat16(f.x); h0.y = __float2bfloat16(f.y);
    h1.x = __float2bfloat16(f.z); h1.y = __float2bfloat16(f.w);
    l0.x = __float2bfloat16(f.x - __bfloat162float(h0.x));
    l0.y = __float2bfloat16(f.y - __bfloat162float(h0.y));
    l1.x = __float2bfloat16(f.z - __bfloat162float(h1.x));
    l1.y = __float2bfloat16(f.w - __bfloat162float(h1.y));
    asm volatile("st.shared.v2.b32 [%0], {%1, %2};"
                 :: "r"(dhi), "r"(*(uint32_t*)&h0), "r"(*(uint32_t*)&h1) : "memory");
    asm volatile("st.shared.v2.b32 [%0], {%1, %2};"
                 :: "r"(dlo), "r"(*(uint32_t*)&l0), "r"(*(uint32_t*)&l1) : "memory");
}

__device__ __forceinline__ void packsplit(float x, float y, uint32_t& hi, uint32_t& lo) {
    __nv_bfloat162 h, l;
    h.x = __float2bfloat16(x); h.y = __float2bfloat16(y);
    l.x = __float2bfloat16(x - __bfloat162float(h.x));
    l.y = __float2bfloat16(y - __bfloat162float(h.y));
    hi = *(uint32_t*)&h; lo = *(uint32_t*)&l;
}

// ================= split kernel: fp32 -> hi/lo bf16 =================
__global__ void split_kernel(const float* __restrict__ src, __nv_bfloat16* __restrict__ hi,
                             __nv_bfloat16* __restrict__ lo, int n4) {
    int i = blockIdx.x * blockDim.x + threadIdx.x;
    if (i >= n4) return;
    float4 f = ((const float4*)src)[i];
    __nv_bfloat162 h0, h1, l0, l1;
    h0.x = __float2bfloat16(f.x); h0.y = __float2bfloat16(f.y);
    h1.x = __float2bfloat16(f.z); h1.y = __float2bfloat16(f.w);
    l0.x = __float2bfloat16(f.x - __bfloat162float(h0.x));
    l0.y = __float2bfloat16(f.y - __bfloat162float(h0.y));
    l1.x = __float2bfloat16(f.z - __bfloat162float(h1.x));
    l1.y = __float2bfloat16(f.w - __bfloat162float(h1.y));
    ((uint2*)hi)[i] = make_uint2(*(uint32_t*)&h0, *(uint32_t*)&h1);
    ((uint2*)lo)[i] = make_uint2(*(uint32_t*)&l0, *(uint32_t*)&l1);
}

// ============ pipelined split-bf16 GEMM: C = A[M,K]*B[N,K]^T, pre-split inputs ============
// smem per stage: Ah|Al|Bh|Bl tiles, each 128 rows x 32 bf16, padded rows of 80B
#define PSTAGE 4
#define PTILE  10240
#define PBUF   (4 * PTILE)     // 40960
#define PSMEM  (PSTAGE * PBUF) // 163840

__global__ void __launch_bounds__(256)
gemm_pre(const __nv_bfloat16* __restrict__ Ah, const __nv_bfloat16* __restrict__ Al,
         const __nv_bfloat16* __restrict__ Bh, const __nv_bfloat16* __restrict__ Bl,
         float* __restrict__ C) {
    extern __shared__ char dsm[];
    const uint32_t sbase = smem_u32(dsm);

    const int tid  = threadIdx.x;
    const int lane = tid & 31;
    const int wid  = tid >> 5;
    const int wm   = wid >> 2;
    const int wn   = wid & 3;
    const int m0   = blockIdx.y * 128;
    const int n0   = blockIdx.x * 128;

    const int rowoff = ((lane >> 3) & 1) * 8 + (lane & 7);
    const int koff   = (lane >> 4) * 8;

    // cp.async mapping: chunk = tid + t*256; row = chunk>>2 (0..127); c = chunk&3
    const int r0c = tid >> 2, cc = tid & 3;
    const int r1c = r0c + 64;
    const __nv_bfloat16* tsrc[4] = {Ah, Al, Bh, Bl};
    const int trow0[4] = {m0 + r0c, m0 + r0c, n0 + r0c, n0 + r0c};
    const int trow1[4] = {m0 + r1c, m0 + r1c, n0 + r1c, n0 + r1c};
    const uint32_t d0 = (uint32_t)r0c * 80 + cc * 16;
    const uint32_t d1 = (uint32_t)r1c * 80 + cc * 16;

    float acc[4][4][4];
#pragma unroll
    for (int i = 0; i < 4; i++)
#pragma unroll
        for (int j = 0; j < 4; j++)
#pragma unroll
            for (int r = 0; r < 4; r++) acc[i][j][r] = 0.f;

    // prologue: issue first PSTAGE-1 chunks
#pragma unroll
    for (int s = 0; s < PSTAGE - 1; s++) {
        uint32_t base = sbase + s * PBUF;
        int kcol = s * 32 + cc * 8;
#pragma unroll
        for (int t4 = 0; t4 < 4; t4++) {
            CPASYNC16(base + t4 * PTILE + d0, tsrc[t4] + (size_t)trow0[t4] * GK + kcol);
            CPASYNC16(base + t4 * PTILE + d1, tsrc[t4] + (size_t)trow1[t4] * GK + kcol);
        }
        CPCOMMIT();
    }

    for (int kc = 0; kc < GK / 32; kc++) {
        CPWAIT2();
        __syncthreads();

        if (kc + PSTAGE - 1 < GK / 32) {
            int kn = kc + PSTAGE - 1;
            uint32_t base = sbase + (kn & (PSTAGE - 1)) * PBUF;
            int kcol = kn * 32 + cc * 8;
#pragma unroll
            for (int t4 = 0; t4 < 4; t4++) {
                CPASYNC16(base + t4 * PTILE + d0, tsrc[t4] + (size_t)trow0[t4] * GK + kcol);
                CPASYNC16(base + t4 * PTILE + d1, tsrc[t4] + (size_t)trow1[t4] * GK + kcol);
            }
        }
        CPCOMMIT();

        const uint32_t smA = sbase + (kc & (PSTAGE - 1)) * PBUF;
        const uint32_t smB = smA + 2 * PTILE;

#pragma unroll
        for (int ks = 0; ks < 2; ks++) {
            uint32_t af[4][4], bh[2][4], bl[2][4];
#pragma unroll
            for (int mf = 0; mf < 4; mf++) {
                uint32_t a = smA + ((uint32_t)(wm * 64 + mf * 16 + rowoff) * 40 + ks * 16 + koff) * 2;
                LDSM_X4(af[mf], a);
            }
#pragma unroll
            for (int nb = 0; nb < 2; nb++) {
                uint32_t b = smB + ((uint32_t)(wn * 32 + nb * 16 + rowoff) * 40 + ks * 16 + koff) * 2;
                LDSM_X4(bh[nb], b);
                LDSM_X4(bl[nb], b + PTILE);
            }
#pragma unroll
            for (int mf = 0; mf < 4; mf++)
#pragma unroll
                for (int nf = 0; nf < 4; nf++) {
                    MMA16816(acc[mf][nf], af[mf], bh[nf >> 1][nf & 1], bh[nf >> 1][(nf & 1) + 2]);
                    MMA16816(acc[mf][nf], af[mf], bl[nf >> 1][nf & 1], bl[nf >> 1][(nf & 1) + 2]);
                }
#pragma unroll
            for (int mf = 0; mf < 4; mf++) {
                uint32_t a = smA + PTILE + ((uint32_t)(wm * 64 + mf * 16 + rowoff) * 40 + ks * 16 + koff) * 2;
                LDSM_X4(af[mf], a);
            }
#pragma unroll
            for (int mf = 0; mf < 4; mf++)
#pragma unroll
                for (int nf = 0; nf < 4; nf++)
                    MMA16816(acc[mf][nf], af[mf], bh[nf >> 1][nf & 1], bh[nf >> 1][(nf & 1) + 2]);
        }
    }

#pragma unroll
    for (int mf = 0; mf < 4; mf++) {
        int r0 = m0 + wm * 64 + mf * 16 + (lane >> 2);
#pragma unroll
        for (int nf = 0; nf < 4; nf++) {
            int c0 = n0 + wn * 32 + nf * 8 + (lane & 3) * 2;
            float2 v0 = make_float2(acc[mf][nf][0], acc[mf][nf][1]);
            float2 v1 = make_float2(acc[mf][nf][2], acc[mf][nf][3]);
            *(float2*)(C + (size_t)r0 * GN + c0)       = v0;
            *(float2*)(C + (size_t)(r0 + 8) * GN + c0) = v1;
        }
    }
}

// ================= RoPE ((b,s,h,d) layout) =================
__global__ void rope_kernel(float* __restrict__ q, float* __restrict__ k,
                            const float* __restrict__ cosT, const float* __restrict__ sinT) {
    int idx = blockIdx.x * blockDim.x + threadIdx.x;
    if (idx >= BB * SS * NHH * 32) return;
    int d = idx & 31;
    int r = idx >> 5;
    int s = (r >> 4) & (SS - 1);
    size_t base = (size_t)r * DD;
    float c1 = cosT[s * DD + d],      s1 = sinT[s * DD + d];
    float c2 = cosT[s * DD + d + 32], s2 = sinT[s * DD + d + 32];
    float x1 = q[base + d], x2 = q[base + d + 32];
    q[base + d]      = x1 * c1 - x2 * s1;
    q[base + d + 32] = x2 * c2 + x1 * s2;
    x1 = k[base + d]; x2 = k[base + d + 32];
    k[base + d]      = x1 * c1 - x2 * s1;
    k[base + d + 32] = x2 * c2 + x1 * s2;
}

// ================= per-chunk RFA summaries ((b,s,h,d)) =================
__global__ void __launch_bounds__(128) rfa_kernel(const float* __restrict__ k,
                                                  const float* __restrict__ v,
                                                  const float* __restrict__ mu,
                                                  const float* __restrict__ phi,
                                                  float* __restrict__ rk,
                                                  float* __restrict__ rv) {
    int bh = blockIdx.x / NCC;
    int c  = blockIdx.x % NCC;
    int b  = bh / NHH, h = bh % NHH;
    int j  = threadIdx.x;
    __shared__ float sb[CHUNKK], sg[CHUNKK];
    const float* kbase = k + (((size_t)b * SS + c * CHUNKK) * NHH + h) * DD;
    const float* vbase = v + (((size_t)b * SS + c * CHUNKK) * NHH + h) * DD;
    const float* kr = kbase + (size_t)j * HIDD;
    float dm = 0.f, dp = 0.f, nn = 0.f;
#pragma unroll
    for (int d = 0; d < DD; d++) {
        float kv = kr[d];
        dm += kv * mu[h * DD + d];
        dp += kv * phi[h * DD + d];
        nn += kv * kv;
    }
    float halfn = 0.5f * SCALEF * nn;
    sb[j] = SCALEF * dm - halfn;
    sg[j] = SCALEF * dp - halfn;
    __syncthreads();
    float mb = -1e30f, mg = -1e30f;
    for (int t = 0; t < CHUNKK; t++) { mb = fmaxf(mb, sb[t]); mg = fmaxf(mg, sg[t]); }
    float eb = expf(sb[j] - mb), eg = expf(sg[j] - mg);
    __syncthreads();
    sb[j] = eb; sg[j] = eg;
    __syncthreads();
    float zb = 0.f, zg = 0.f;
    for (int t = 0; t < CHUNKK; t++) { zb += sb[t]; zg += sg[t]; }
    float invb = 1.f / zb, invg = 1.f / zg;
    if (j < DD) {
        int d = j;
        float acc = 0.f;
        for (int t = 0; t < CHUNKK; t++) acc += sb[t] * kbase[(size_t)t * HIDD + d];
        rk[((size_t)bh * NCC + c) * DD + d] = acc * invb;
    } else {
        int d = j - DD;
        float acc = 0.f;
        for (int t = 0; t < CHUNKK; t++) acc += sg[t] * vbase[(size_t)t * HIDD + d];
        rv[((size_t)bh * NCC + c) * DD + d] = acc * invg;
    }
}

// ================= MMA flash attention =================
#define AQ_H 0
#define AQ_L 18432
#define AK_H 36864
#define AK_L 46080
#define AV_H 55296
#define AV_L 64512
#define AT_SMEM 73728

__device__ __forceinline__ void fill_split(const float* __restrict__ src, int rstride,
                                           int rows, int rlimit,
                                           uint32_t dhi, uint32_t dlo, int tid, float scale) {
    const int col4 = tid & 15;
    const int r0   = tid >> 4;
    for (int r = r0; r < rows; r += 8) {
        float4 f;
        if (r < rlimit) {
            f = *(const float4*)(src + (size_t)r * rstride + col4 * 4);
            f.x *= scale; f.y *= scale; f.z *= scale; f.w *= scale;
        } else {
            f = make_float4(0.f, 0.f, 0.f, 0.f);
        }
        uint32_t off = (uint32_t)r * 144 + col4 * 8;
        cvtsts(f, dhi + off, dlo + off);
    }
}

__global__ void __launch_bounds__(128, 2)
attn_mma(const float* __restrict__ q, const float* __restrict__ k,
         const float* __restrict__ v, const float* __restrict__ rk,
         const float* __restrict__ rv, float* __restrict__ out) {
    extern __shared__ char dsm[];
    const uint32_t sb = smem_u32(dsm);

    const int qt  = blockIdx.x;
    const int w   = blockIdx.y;
    const int bh  = blockIdx.z;
    const int b   = bh >> 4, h = bh & 15;
    const int tid = threadIdx.x, lane = tid & 31, wq = tid >> 5;

    const int rowoff = ((lane >> 3) & 1) * 8 + (lane & 7);
    const int koff   = (lane >> 4) * 8;
    const int vrow   = lane & 15;
    const int vnadd  = (lane >> 4) * 8;

    const float* qg = q + (((size_t)b * SS + w * WINN + qt * 128) * NHH + h) * DD;
    fill_split(qg, HIDD, 128, 128, sb + AQ_H, sb + AQ_L, tid, SCALEF);

    float OA[2][8][4];
#pragma unroll
    for (int mf = 0; mf < 2; mf++)
#pragma unroll
        for (int nf = 0; nf < 8; nf++)
#pragma unroll
            for (int r = 0; r < 4; r++) OA[mf][nf][r] = 0.f;
    float mrow[2][2] = {{-1e30f, -1e30f}, {-1e30f, -1e30f}};
    float lrow[2][2] = {{0.f, 0.f}, {0.f, 0.f}};

    const float* kwin = k + (((size_t)b * SS + w * WINN) * NHH + h) * DD;
    const float* vwin = v + (((size_t)b * SS + w * WINN) * NHH + h) * DD;
    const float* rkb  = rk + (size_t)bh * NCC * DD;
    const float* rvb  = rv + (size_t)bh * NCC * DD;

    const int nwt    = 2 * qt + 2;
    const int nch    = 4 * w;
    const int ntile  = nwt + (nch > 0 ? 1 : 0);

    for (int t = 0; t < ntile; t++) {
        const bool ischunk = (t == nwt);
        const int kt0 = t * 64;
        __syncthreads();
        if (!ischunk) {
            fill_split(kwin + (size_t)kt0 * HIDD, HIDD, 64, 64, sb + AK_H, sb + AK_L, tid, 1.f);
            fill_split(vwin + (size_t)kt0 * HIDD, HIDD, 64, 64, sb + AV_H, sb + AV_L, tid, 1.f);
        } else {
            fill_split(rkb, DD, 64, nch, sb + AK_H, sb + AK_L, tid, 1.f);
            fill_split(rvb, DD, 64, nch, sb + AV_H, sb + AV_L, tid, 1.f);
        }
        __syncthreads();

        float SA[2][8][4];
#pragma unroll
        for (int mf = 0; mf < 2; mf++)
#pragma unroll
            for (int nf = 0; nf < 8; nf++)
#pragma unroll
                for (int r = 0; r < 4; r++) SA[mf][nf][r] = 0.f;

#pragma unroll
        for (int pass = 0; pass < 3; pass++) {
            const uint32_t Ab = sb + ((pass == 2) ? AQ_L : AQ_H);
            const uint32_t Bb = sb + ((pass == 1) ? AK_L : AK_H);
#pragma unroll
            for (int ks = 0; ks < 4; ks++) {
                uint32_t af[2][4], bf[4][4];
#pragma unroll
                for (int mf = 0; mf < 2; mf++)
                    LDSM_X4(af[mf], Ab + ((uint32_t)(wq * 32 + mf * 16 + rowoff) * 72 + ks * 16 + koff) * 2);
#pragma unroll
                for (int nb = 0; nb < 4; nb++)
                    LDSM_X4(bf[nb], Bb + ((uint32_t)(nb * 16 + rowoff) * 72 + ks * 16 + koff) * 2);
#pragma unroll
                for (int mf = 0; mf < 2; mf++)
#pragma unroll
                    for (int nf = 0; nf < 8; nf++)
                        MMA16816(SA[mf][nf], af[mf], bf[nf >> 1][nf & 1], bf[nf >> 1][(nf & 1) + 2]);
            }
        }

        if (ischunk) {
#pragma unroll
            for (int mf = 0; mf < 2; mf++)
#pragma unroll
                for (int nf = 0; nf < 8; nf++) {
                    int colb = nf * 8 + (lane & 3) * 2;
                    if (colb     >= nch) { SA[mf][nf][0] = -1e30f; SA[mf][nf][2] = -1e30f; }
                    if (colb + 1 >= nch) { SA[mf][nf][1] = -1e30f; SA[mf][nf][3] = -1e30f; }
                }
        } else if (t >= 2 * qt) {
#pragma unroll
            for (int mf = 0; mf < 2; mf++)
#pragma unroll
                for (int nf = 0; nf < 8; nf++) {
                    int colb = kt0 + nf * 8 + (lane & 3) * 2;
#pragma unroll
                    for (int hf = 0; hf < 2; hf++) {
                        int rowq = qt * 128 + wq * 32 + mf * 16 + (lane >> 2) + hf * 8;
                        if (colb     > rowq) SA[mf][nf][hf * 2]     = -1e30f;
                        if (colb + 1 > rowq) SA[mf][nf][hf * 2 + 1] = -1e30f;
                    }
                }
        }

#pragma unroll
        for (int mf = 0; mf < 2; mf++)
#pragma unroll
            for (int hf = 0; hf < 2; hf++) {
                float tm = -1e30f;
#pragma unroll
                for (int nf = 0; nf < 8; nf++) {
                    tm = fmaxf(tm, SA[mf][nf][hf * 2]);
                    tm = fmaxf(tm, SA[mf][nf][hf * 2 + 1]);
                }
                tm = fmaxf(tm, __shfl_xor_sync(0xFFFFFFFF, tm, 1));
                tm = fmaxf(tm, __shfl_xor_sync(0xFFFFFFFF, tm, 2));
                float mold = mrow[mf][hf];
                float mnew = fmaxf(mold, tm);
                float f = __expf(mold - mnew);
                float rs = 0.f;
#pragma unroll
                for (int nf = 0; nf < 8; nf++) {
                    float p0 = __expf(SA[mf][nf][hf * 2]     - mnew);
                    float p1 = __expf(SA[mf][nf][hf * 2 + 1] - mnew);
                    SA[mf][nf][hf * 2]     = p0;
                    SA[mf][nf][hf * 2 + 1] = p1;
                    rs += p0 + p1;
                }
                rs += __shfl_xor_sync(0xFFFFFFFF, rs, 1);
                rs += __shfl_xor_sync(0xFFFFFFFF, rs, 2);
                lrow[mf][hf] = lrow[mf][hf] * f + rs;
                mrow[mf][hf] = mnew;
#pragma unroll
                for (int nf = 0; nf < 8; nf++) {
                    OA[mf][nf][hf * 2]     *= f;
                    OA[mf][nf][hf * 2 + 1] *= f;
                }
            }

#pragma unroll
        for (int kc = 0; kc < 4; kc++) {
            uint32_t ah[2][4], al[2][4];
#pragma unroll
            for (int mf = 0; mf < 2; mf++) {
                packsplit(SA[mf][2 * kc][0],     SA[mf][2 * kc][1],     ah[mf][0], al[mf][0]);
                packsplit(SA[mf][2 * kc][2],     SA[mf][2 * kc][3],     ah[mf][1], al[mf][1]);
                packsplit(SA[mf][2 * kc + 1][0], SA[mf][2 * kc + 1][1], ah[mf][2], al[mf][2]);
                packsplit(SA[mf][2 * kc + 1][2], SA[mf][2 * kc + 1][3], ah[mf][3], al[mf][3]);
            }
#pragma unroll
            for (int nq = 0; nq < 4; nq++) {
                uint32_t off = ((uint32_t)(kc * 16 + vrow) * 72 + nq * 16 + vnadd) * 2;
                uint32_t bv[4];
                LDSM_X4T(bv, sb + AV_H + off);
#pragma unroll
                for (int mf = 0; mf < 2; mf++) {
                    MMA16816R(OA[mf][2 * nq],     ah[mf][0], ah[mf][1], ah[mf][2], ah[mf][3], bv[0], bv[1]);
                    MMA16816R(OA[mf][2 * nq + 1], ah[mf][0], ah[mf][1], ah[mf][2], ah[mf][3], bv[2], bv[3]);
                    MMA16816R(OA[mf][2 * nq],     al[mf][0], al[mf][1], al[mf][2], al[mf][3], bv[0], bv[1]);
                    MMA16816R(OA[mf][2 * nq + 1], al[mf][0], al[mf][1], al[mf][2], al[mf][3], bv[2], bv[3]);
                }
                LDSM_X4T(bv, sb + AV_L + off);
#pragma unroll
                for (int mf = 0; mf < 2; mf++) {
                    MMA16816R(OA[mf][2 * nq],     ah[mf][0], ah[mf][1], ah[mf][2], ah[mf][3], bv[0], bv[1]);
                    MMA16816R(OA[mf][2 * nq + 1], ah[mf][0], ah[mf][1], ah[mf][2], ah[mf][3], bv[2], bv[3]);
                }
            }
        }
    }

#pragma unroll
    for (int mf = 0; mf < 2; mf++)
#pragma unroll
        for (int hf = 0; hf < 2; hf++) {
            float inv = 1.f / lrow[mf][hf];
            int row = w * WINN + qt * 128 + wq * 32 + mf * 16 + (lane >> 2) + hf * 8;
            float* orow = out + ((size_t)b * SS + row) * HIDD + h * DD;
#pragma unroll
            for (int nf = 0; nf < 8; nf++) {
                int d = nf * 8 + (lane & 3) * 2;
                float2 vv = make_float2(OA[mf][nf][hf * 2] * inv, OA[mf][nf][hf * 2 + 1] * inv);
                *(float2*)(orow + d) = vv;
            }
        }
}

// ---------------- launch ----------------
extern "C" void kernel_launch(void* const* d_in, const int* in_sizes, int n_in,
                              void* d_out, int out_size) {
    const float* hidden = (const float*)d_in[0];
    const float* Wq     = (const float*)d_in[1];
    const float* Wk     = (const float*)d_in[2];
    const float* Wv     = (const float*)d_in[3];
    const float* Wo     = (const float*)d_in[4];
    const float* mu     = (const float*)d_in[5];
    const float* phi    = (const float*)d_in[6];
    const float* cosT   = (const float*)d_in[7];
    const float* sinT   = (const float*)d_in[8];

    float *qb, *kb, *vb, *ab, *rkb, *rvb;
    __nv_bfloat16 *hidh, *hidl, *aoh, *aol, *wh, *wl;
    cudaGetSymbolAddress((void**)&qb,   g_q);
    cudaGetSymbolAddress((void**)&kb,   g_k);
    cudaGetSymbolAddress((void**)&vb,   g_v);
    cudaGetSymbolAddress((void**)&ab,   g_attn);
    cudaGetSymbolAddress((void**)&rkb,  g_rfak);
    cudaGetSymbolAddress((void**)&rvb,  g_rfav);
    cudaGetSymbolAddress((void**)&hidh, g_hid_h);
    cudaGetSymbolAddress((void**)&hidl, g_hid_l);
    cudaGetSymbolAddress((void**)&aoh,  g_ao_h);
    cudaGetSymbolAddress((void**)&aol,  g_ao_l);
    cudaGetSymbolAddress((void**)&wh,   g_w_h);
    cudaGetSymbolAddress((void**)&wl,   g_w_l);

    static bool attr_set = false;
    if (!attr_set) {
        cudaFuncSetAttribute((const void*)gemm_pre,
                             cudaFuncAttributeMaxDynamicSharedMemorySize, PSMEM);
        cudaFuncSetAttribute((const void*)attn_mma,
                             cudaFuncAttributeMaxDynamicSharedMemorySize, AT_SMEM);
        attr_set = true;
    }

    const int WSZ = HIDD * HIDD;          // 1M elems
    const int HN4 = MTOK * HIDD / 4;      // hidden float4 count
    const int WN4 = WSZ / 4;

    // pre-split inputs
    split_kernel<<<(HN4 + 255) / 256, 256>>>(hidden, hidh, hidl, HN4);
    split_kernel<<<(WN4 + 255) / 256, 256>>>(Wq, wh + 0 * WSZ, wl + 0 * WSZ, WN4);
    split_kernel<<<(WN4 + 255) / 256, 256>>>(Wk, wh + 1 * WSZ, wl + 1 * WSZ, WN4);
    split_kernel<<<(WN4 + 255) / 256, 256>>>(Wv, wh + 2 * WSZ, wl + 2 * WSZ, WN4);
    split_kernel<<<(WN4 + 255) / 256, 256>>>(Wo, wh + 3 * WSZ, wl + 3 * WSZ, WN4);

    dim3 ggrid(GN / 128, MTOK / 128);
    gemm_pre<<<ggrid, 256, PSMEM>>>(hidh, hidl, wh + 0 * WSZ, wl + 0 * WSZ, qb);
    gemm_pre<<<ggrid, 256, PSMEM>>>(hidh, hidl, wh + 1 * WSZ, wl + 1 * WSZ, kb);
    gemm_pre<<<ggrid, 256, PSMEM>>>(hidh, hidl, wh + 2 * WSZ, wl + 2 * WSZ, vb);

    rope_kernel<<<(BB * SS * NHH * 32) / 256, 256>>>(qb, kb, cosT, sinT);

    rfa_kernel<<<BB * NHH * NCC, 128>>>(kb, vb, mu, phi, rkb, rvb);

    attn_mma<<<dim3(4, NWW, BB * NHH), 128, AT_SMEM>>>(qb, kb, vb, rkb, rvb, ab);

    split_kernel<<<(HN4 + 255) / 256, 256>>>(ab, aoh, aol, HN4);
    gemm_pre<<<ggrid, 256, PSMEM>>>(aoh, aol, wh + 3 * WSZ, wl + 3 * WSZ, (float*)d_out);
}

// round 8
// speedup vs baseline: 1.0391x; 1.0391x over previous
#include <cuda_runtime.h>
#include <cuda_bf16.h>
#include <cstdint>
#include <math.h>

// ---------------- problem constants ----------------
#define BB     4
#define SS     4096
#define HIDD   1024
#define NHH    16
#define DD     64
#define WINN   512
#define CHUNKK 128
#define NWW    8
#define NCC    32
#define SCALEF 0.125f
#define MTOK   (BB*SS)   // 16384
#define GK     1024

// ---------------- scratch (device globals) ----------------
__device__ float g_q[MTOK*HIDD];
__device__ float g_k[MTOK*HIDD];
__device__ float g_v[MTOK*HIDD];
__device__ float g_rfak[BB*NHH*NCC*DD];
__device__ float g_rfav[BB*NHH*NCC*DD];
// pre-split bf16 operands
__device__ __nv_bfloat16 g_hid_h[MTOK*HIDD];
__device__ __nv_bfloat16 g_hid_l[MTOK*HIDD];
__device__ __nv_bfloat16 g_ao_h[MTOK*HIDD];
__device__ __nv_bfloat16 g_ao_l[MTOK*HIDD];
__device__ __nv_bfloat16 g_w_h[4*HIDD*HIDD];
__device__ __nv_bfloat16 g_w_l[4*HIDD*HIDD];

// ================= helpers =================
__device__ __forceinline__ uint32_t smem_u32(const void* p) {
    uint32_t a;
    asm("{ .reg .u64 t; cvta.to.shared.u64 t, %1; cvt.u32.u64 %0, t; }" : "=r"(a) : "l"(p));
    return a;
}

#define LDSM_X4(r, a)                                                          \
    asm volatile("ldmatrix.sync.aligned.m8n8.x4.shared.b16 {%0,%1,%2,%3}, [%4];" \
        : "=r"((r)[0]), "=r"((r)[1]), "=r"((r)[2]), "=r"((r)[3]) : "r"(a))

#define LDSM_X4T(r, a)                                                         \
    asm volatile("ldmatrix.sync.aligned.m8n8.x4.trans.shared.b16 {%0,%1,%2,%3}, [%4];" \
        : "=r"((r)[0]), "=r"((r)[1]), "=r"((r)[2]), "=r"((r)[3]) : "r"(a))

#define MMA16816(c, a, b0, b1)                                                 \
    asm volatile("mma.sync.aligned.m16n8k16.row.col.f32.bf16.bf16.f32 "        \
        "{%0,%1,%2,%3}, {%4,%5,%6,%7}, {%8,%9}, {%0,%1,%2,%3};"                \
        : "+f"((c)[0]), "+f"((c)[1]), "+f"((c)[2]), "+f"((c)[3])               \
        : "r"((a)[0]), "r"((a)[1]), "r"((a)[2]), "r"((a)[3]), "r"(b0), "r"(b1))

#define MMA16816R(c, a0, a1, a2, a3, b0, b1)                                   \
    asm volatile("mma.sync.aligned.m16n8k16.row.col.f32.bf16.bf16.f32 "        \
        "{%0,%1,%2,%3}, {%4,%5,%6,%7}, {%8,%9}, {%0,%1,%2,%3};"                \
        : "+f"((c)[0]), "+f"((c)[1]), "+f"((c)[2]), "+f"((c)[3])               \
        : "r"(a0), "r"(a1), "r"(a2), "r"(a3), "r"(b0), "r"(b1))

#define CPASYNC16(dst, src) \
    asm volatile("cp.async.cg.shared.global [%0], [%1], 16;" :: "r"(dst), "l"(src) : "memory")
#define CPCOMMIT() asm volatile("cp.async.commit_group;" ::: "memory")
#define CPWAIT1()  asm volatile("cp.async.wait_group 1;" ::: "memory")

__device__ __forceinline__ void cvtsts(float4 f, uint32_t dhi, uint32_t dlo) {
    __nv_bfloat162 h0, h1, l0, l1;
    h0.x = __float2bfloat16(f.x); h0.y = __float2bfloat16(f.y);
    h1.x = __float2bfloat16(f.z); h1.y = __float2bfloat16(f.w);
    l0.x = __float2bfloat16(f.x - __bfloat162float(h0.x));
    l0.y = __float2bfloat16(f.y - __bfloat162float(h0.y));
    l1.x = __float2bfloat16(f.z - __bfloat162float(h1.x));
    l1.y = __float2bfloat16(f.w - __bfloat162float(h1.y));
    asm volatile("st.shared.v2.b32 [%0], {%1, %2};"
                 :: "r"(dhi), "r"(*(uint32_t*)&h0), "r"(*(uint32_t*)&h1) : "memory");
    asm volatile("st.shared.v2.b32 [%0], {%1, %2};"
                 :: "r"(dlo), "r"(*(uint32_t*)&l0), "r"(*(uint32_t*)&l1) : "memory");
}

__device__ __forceinline__ void packsplit(float x, float y, uint32_t& hi, uint32_t& lo) {
    __nv_bfloat162 h, l;
    h.x = __float2bfloat16(x); h.y = __float2bfloat16(y);
    l.x = __float2bfloat16(x - __bfloat162float(h.x));
    l.y = __float2bfloat16(y - __bfloat162float(h.y));
    hi = *(uint32_t*)&h; lo = *(uint32_t*)&l;
}

// ================= split kernel: fp32 -> hi/lo bf16 =================
__global__ void split_kernel(const float* __restrict__ src, __nv_bfloat16* __restrict__ hi,
                             __nv_bfloat16* __restrict__ lo, int n4) {
    int i = blockIdx.x * blockDim.x + threadIdx.x;
    if (i >= n4) return;
    float4 f = ((const float4*)src)[i];
    __nv_bfloat162 h0, h1, l0, l1;
    h0.x = __float2bfloat16(f.x); h0.y = __float2bfloat16(f.y);
    h1.x = __float2bfloat16(f.z); h1.y = __float2bfloat16(f.w);
    l0.x = __float2bfloat16(f.x - __bfloat162float(h0.x));
    l0.y = __float2bfloat16(f.y - __bfloat162float(h0.y));
    l1.x = __float2bfloat16(f.z - __bfloat162float(h1.x));
    l1.y = __float2bfloat16(f.w - __bfloat162float(h1.y));
    ((uint2*)hi)[i] = make_uint2(*(uint32_t*)&h0, *(uint32_t*)&h1);
    ((uint2*)lo)[i] = make_uint2(*(uint32_t*)&l0, *(uint32_t*)&l1);
}

// ============ split-bf16 GEMM, CTA 128x256, warp 64x64, 3-stage cp.async ============
// stage layout: Ah[128][40] | Al | Bh[256][40] | Bl  (bf16, 80B padded rows)
#define QSTAGE 3
#define ATILE  10240
#define BTILE  20480
#define QBUF   (2 * ATILE + 2 * BTILE)  // 61440
#define QSMEM  (QSTAGE * QBUF)          // 184320

__global__ void __launch_bounds__(256, 1)
gemm_qkv(const __nv_bfloat16* __restrict__ Ah, const __nv_bfloat16* __restrict__ Al,
         const __nv_bfloat16* __restrict__ Bh, const __nv_bfloat16* __restrict__ Bl,
         float* __restrict__ C0, float* __restrict__ C1, float* __restrict__ C2) {
    extern __shared__ char dsm[];
    const uint32_t sbase = smem_u32(dsm);

    const int tid  = threadIdx.x;
    const int lane = tid & 31;
    const int wid  = tid >> 5;
    const int wm   = wid >> 2;      // 0..1 (64-row stripes)
    const int wn   = wid & 3;       // 0..3 (64-col stripes)
    const int m0   = blockIdx.y * 128;
    const int n0   = blockIdx.x * 256;

    const int sel = n0 >> 10;
    float* C = (sel == 0) ? C0 : (sel == 1) ? C1 : C2;
    const int nc0 = n0 & 1023;

    const int rowoff = ((lane >> 3) & 1) * 8 + (lane & 7);
    const int koff   = (lane >> 4) * 8;

    // cp.async mapping
    const int arow = tid >> 2, acc4 = tid & 3;       // A: 2 iters of 256 chunks
    const uint32_t adst = (uint32_t)arow * 80 + acc4 * 16;

    float acc[4][8][4];
#pragma unroll
    for (int i = 0; i < 4; i++)
#pragma unroll
        for (int j = 0; j < 8; j++)
#pragma unroll
            for (int r = 0; r < 4; r++) acc[i][j][r] = 0.f;

    auto issue_stage = [&](int kc) {
        uint32_t base = sbase + (kc % QSTAGE) * QBUF;
        int kcol = kc * 32 + acc4 * 8;
#pragma unroll
        for (int i = 0; i < 2; i++) {
            int r = arow + i * 64;
            CPASYNC16(base + adst + (uint32_t)i * 64 * 80,
                      Ah + (size_t)(m0 + r) * GK + kcol);
            CPASYNC16(base + ATILE + adst + (uint32_t)i * 64 * 80,
                      Al + (size_t)(m0 + r) * GK + kcol);
        }
#pragma unroll
        for (int i = 0; i < 4; i++) {
            int r = arow + i * 64;
            CPASYNC16(base + 2 * ATILE + adst + (uint32_t)i * 64 * 80,
                      Bh + (size_t)(n0 + r) * GK + kcol);
            CPASYNC16(base + 2 * ATILE + BTILE + adst + (uint32_t)i * 64 * 80,
                      Bl + (size_t)(n0 + r) * GK + kcol);
        }
        CPCOMMIT();
    };

    issue_stage(0);
    issue_stage(1);

    for (int kc = 0; kc < GK / 32; kc++) {
        CPWAIT1();
        __syncthreads();
        if (kc + 2 < GK / 32) issue_stage(kc + 2);
        else CPCOMMIT();

        const uint32_t smA = sbase + (kc % QSTAGE) * QBUF;
        const uint32_t smB = smA + 2 * ATILE;

#pragma unroll
        for (int ks = 0; ks < 2; ks++) {
            uint32_t af[4][4], bh[4][4], bl[4][4];
#pragma unroll
            for (int mf = 0; mf < 4; mf++)
                LDSM_X4(af[mf], smA + ((uint32_t)(wm * 64 + mf * 16 + rowoff) * 40 + ks * 16 + koff) * 2);
#pragma unroll
            for (int nb = 0; nb < 4; nb++)
                LDSM_X4(bh[nb], smB + ((uint32_t)(wn * 64 + nb * 16 + rowoff) * 40 + ks * 16 + koff) * 2);
            // pass 1: Ah * Bh
#pragma unroll
            for (int mf = 0; mf < 4; mf++)
#pragma unroll
                for (int nf = 0; nf < 8; nf++)
                    MMA16816(acc[mf][nf], af[mf], bh[nf >> 1][nf & 1], bh[nf >> 1][(nf & 1) + 2]);
            // pass 2: Ah * Bl
#pragma unroll
            for (int nb = 0; nb < 4; nb++)
                LDSM_X4(bl[nb], smB + BTILE + ((uint32_t)(wn * 64 + nb * 16 + rowoff) * 40 + ks * 16 + koff) * 2);
#pragma unroll
            for (int mf = 0; mf < 4; mf++)
#pragma unroll
                for (int nf = 0; nf < 8; nf++)
                    MMA16816(acc[mf][nf], af[mf], bl[nf >> 1][nf & 1], bl[nf >> 1][(nf & 1) + 2]);
            // pass 3: Al * Bh (reload A-lo into af)
#pragma unroll
            for (int mf = 0; mf < 4; mf++)
                LDSM_X4(af[mf], smA + ATILE + ((uint32_t)(wm * 64 + mf * 16 + rowoff) * 40 + ks * 16 + koff) * 2);
#pragma unroll
            for (int mf = 0; mf < 4; mf++)
#pragma unroll
                for (int nf = 0; nf < 8; nf++)
                    MMA16816(acc[mf][nf], af[mf], bh[nf >> 1][nf & 1], bh[nf >> 1][(nf & 1) + 2]);
        }
    }

#pragma unroll
    for (int mf = 0; mf < 4; mf++) {
        int r0 = m0 + wm * 64 + mf * 16 + (lane >> 2);
#pragma unroll
        for (int nf = 0; nf < 8; nf++) {
            int c0 = nc0 + wn * 64 + nf * 8 + (lane & 3) * 2;
            *(float2*)(C + (size_t)r0 * HIDD + c0)       = make_float2(acc[mf][nf][0], acc[mf][nf][1]);
            *(float2*)(C + (size_t)(r0 + 8) * HIDD + c0) = make_float2(acc[mf][nf][2], acc[mf][nf][3]);
        }
    }
}

// ================= RoPE ((b,s,h,d) layout) =================
__global__ void rope_kernel(float* __restrict__ q, float* __restrict__ k,
                            const float* __restrict__ cosT, const float* __restrict__ sinT) {
    int idx = blockIdx.x * blockDim.x + threadIdx.x;
    if (idx >= BB * SS * NHH * 32) return;
    int d = idx & 31;
    int r = idx >> 5;
    int s = (r >> 4) & (SS - 1);
    size_t base = (size_t)r * DD;
    float c1 = cosT[s * DD + d],      s1 = sinT[s * DD + d];
    float c2 = cosT[s * DD + d + 32], s2 = sinT[s * DD + d + 32];
    float x1 = q[base + d], x2 = q[base + d + 32];
    q[base + d]      = x1 * c1 - x2 * s1;
    q[base + d + 32] = x2 * c2 + x1 * s2;
    x1 = k[base + d]; x2 = k[base + d + 32];
    k[base + d]      = x1 * c1 - x2 * s1;
    k[base + d + 32] = x2 * c2 + x1 * s2;
}

// ================= per-chunk RFA summaries ((b,s,h,d)) =================
__global__ void __launch_bounds__(128) rfa_kernel(const float* __restrict__ k,
                                                  const float* __restrict__ v,
                                                  const float* __restrict__ mu,
                                                  const float* __restrict__ phi,
                                                  float* __restrict__ rk,
                                                  float* __restrict__ rv) {
    int bh = blockIdx.x / NCC;
    int c  = blockIdx.x % NCC;
    int b  = bh / NHH, h = bh % NHH;
    int j  = threadIdx.x;
    __shared__ float sb[CHUNKK], sg[CHUNKK];
    const float* kbase = k + (((size_t)b * SS + c * CHUNKK) * NHH + h) * DD;
    const float* vbase = v + (((size_t)b * SS + c * CHUNKK) * NHH + h) * DD;
    const float* kr = kbase + (size_t)j * HIDD;
    float dm = 0.f, dp = 0.f, nn = 0.f;
#pragma unroll
    for (int d = 0; d < DD; d++) {
        float kv = kr[d];
        dm += kv * mu[h * DD + d];
        dp += kv * phi[h * DD + d];
        nn += kv * kv;
    }
    float halfn = 0.5f * SCALEF * nn;
    sb[j] = SCALEF * dm - halfn;
    sg[j] = SCALEF * dp - halfn;
    __syncthreads();
    float mb = -1e30f, mg = -1e30f;
    for (int t = 0; t < CHUNKK; t++) { mb = fmaxf(mb, sb[t]); mg = fmaxf(mg, sg[t]); }
    float eb = expf(sb[j] - mb), eg = expf(sg[j] - mg);
    __syncthreads();
    sb[j] = eb; sg[j] = eg;
    __syncthreads();
    float zb = 0.f, zg = 0.f;
    for (int t = 0; t < CHUNKK; t++) { zb += sb[t]; zg += sg[t]; }
    float invb = 1.f / zb, invg = 1.f / zg;
    if (j < DD) {
        int d = j;
        float acc = 0.f;
        for (int t = 0; t < CHUNKK; t++) acc += sb[t] * kbase[(size_t)t * HIDD + d];
        rk[((size_t)bh * NCC + c) * DD + d] = acc * invb;
    } else {
        int d = j - DD;
        float acc = 0.f;
        for (int t = 0; t < CHUNKK; t++) acc += sg[t] * vbase[(size_t)t * HIDD + d];
        rv[((size_t)bh * NCC + c) * DD + d] = acc * invg;
    }
}

// ================= MMA flash attention (epilogue -> split bf16) =================
#define AQ_H 0
#define AQ_L 18432
#define AK_H 36864
#define AK_L 46080
#define AV_H 55296
#define AV_L 64512
#define AT_SMEM 73728

__device__ __forceinline__ void fill_split(const float* __restrict__ src, int rstride,
                                           int rows, int rlimit,
                                           uint32_t dhi, uint32_t dlo, int tid, float scale) {
    const int col4 = tid & 15;
    const int r0   = tid >> 4;
    for (int r = r0; r < rows; r += 8) {
        float4 f;
        if (r < rlimit) {
            f = *(const float4*)(src + (size_t)r * rstride + col4 * 4);
            f.x *= scale; f.y *= scale; f.z *= scale; f.w *= scale;
        } else {
            f = make_float4(0.f, 0.f, 0.f, 0.f);
        }
        uint32_t off = (uint32_t)r * 144 + col4 * 8;
        cvtsts(f, dhi + off, dlo + off);
    }
}

__global__ void __launch_bounds__(128, 2)
attn_mma(const float* __restrict__ q, const float* __restrict__ k,
         const float* __restrict__ v, const float* __restrict__ rk,
         const float* __restrict__ rv,
         __nv_bfloat16* __restrict__ oh, __nv_bfloat16* __restrict__ ol) {
    extern __shared__ char dsm[];
    const uint32_t sb = smem_u32(dsm);

    const int qt  = blockIdx.x;
    const int w   = blockIdx.y;
    const int bh  = blockIdx.z;
    const int b   = bh >> 4, h = bh & 15;
    const int tid = threadIdx.x, lane = tid & 31, wq = tid >> 5;

    const int rowoff = ((lane >> 3) & 1) * 8 + (lane & 7);
    const int koff   = (lane >> 4) * 8;
    const int vrow   = lane & 15;
    const int vnadd  = (lane >> 4) * 8;

    const float* qg = q + (((size_t)b * SS + w * WINN + qt * 128) * NHH + h) * DD;
    fill_split(qg, HIDD, 128, 128, sb + AQ_H, sb + AQ_L, tid, SCALEF);

    float OA[2][8][4];
#pragma unroll
    for (int mf = 0; mf < 2; mf++)
#pragma unroll
        for (int nf = 0; nf < 8; nf++)
#pragma unroll
            for (int r = 0; r < 4; r++) OA[mf][nf][r] = 0.f;
    float mrow[2][2] = {{-1e30f, -1e30f}, {-1e30f, -1e30f}};
    float lrow[2][2] = {{0.f, 0.f}, {0.f, 0.f}};

    const float* kwin = k + (((size_t)b * SS + w * WINN) * NHH + h) * DD;
    const float* vwin = v + (((size_t)b * SS + w * WINN) * NHH + h) * DD;
    const float* rkb  = rk + (size_t)bh * NCC * DD;
    const float* rvb  = rv + (size_t)bh * NCC * DD;

    const int nwt    = 2 * qt + 2;
    const int nch    = 4 * w;
    const int ntile  = nwt + (nch > 0 ? 1 : 0);

    for (int t = 0; t < ntile; t++) {
        const bool ischunk = (t == nwt);
        const int kt0 = t * 64;
        __syncthreads();
        if (!ischunk) {
            fill_split(kwin + (size_t)kt0 * HIDD, HIDD, 64, 64, sb + AK_H, sb + AK_L, tid, 1.f);
            fill_split(vwin + (size_t)kt0 * HIDD, HIDD, 64, 64, sb + AV_H, sb + AV_L, tid, 1.f);
        } else {
            fill_split(rkb, DD, 64, nch, sb + AK_H, sb + AK_L, tid, 1.f);
            fill_split(rvb, DD, 64, nch, sb + AV_H, sb + AV_L, tid, 1.f);
        }
        __syncthreads();

        float SA[2][8][4];
#pragma unroll
        for (int mf = 0; mf < 2; mf++)
#pragma unroll
            for (int nf = 0; nf < 8; nf++)
#pragma unroll
                for (int r = 0; r < 4; r++) SA[mf][nf][r] = 0.f;

#pragma unroll
        for (int pass = 0; pass < 3; pass++) {
            const uint32_t Ab = sb + ((pass == 2) ? AQ_L : AQ_H);
            const uint32_t Bb = sb + ((pass == 1) ? AK_L : AK_H);
#pragma unroll
            for (int ks = 0; ks < 4; ks++) {
                uint32_t af[2][4], bf[4][4];
#pragma unroll
                for (int mf = 0; mf < 2; mf++)
                    LDSM_X4(af[mf], Ab + ((uint32_t)(wq * 32 + mf * 16 + rowoff) * 72 + ks * 16 + koff) * 2);
#pragma unroll
                for (int nb = 0; nb < 4; nb++)
                    LDSM_X4(bf[nb], Bb + ((uint32_t)(nb * 16 + rowoff) * 72 + ks * 16 + koff) * 2);
#pragma unroll
                for (int mf = 0; mf < 2; mf++)
#pragma unroll
                    for (int nf = 0; nf < 8; nf++)
                        MMA16816(SA[mf][nf], af[mf], bf[nf >> 1][nf & 1], bf[nf >> 1][(nf & 1) + 2]);
            }
        }

        if (ischunk) {
#pragma unroll
            for (int mf = 0; mf < 2; mf++)
#pragma unroll
                for (int nf = 0; nf < 8; nf++) {
                    int colb = nf * 8 + (lane & 3) * 2;
                    if (colb     >= nch) { SA[mf][nf][0] = -1e30f; SA[mf][nf][2] = -1e30f; }
                    if (colb + 1 >= nch) { SA[mf][nf][1] = -1e30f; SA[mf][nf][3] = -1e30f; }
                }
        } else if (t >= 2 * qt) {
#pragma unroll
            for (int mf = 0; mf < 2; mf++)
#pragma unroll
                for (int nf = 0; nf < 8; nf++) {
                    int colb = kt0 + nf * 8 + (lane & 3) * 2;
#pragma unroll
                    for (int hf = 0; hf < 2; hf++) {
                        int rowq = qt * 128 + wq * 32 + mf * 16 + (lane >> 2) + hf * 8;
                        if (colb     > rowq) SA[mf][nf][hf * 2]     = -1e30f;
                        if (colb + 1 > rowq) SA[mf][nf][hf * 2 + 1] = -1e30f;
                    }
                }
        }

#pragma unroll
        for (int mf = 0; mf < 2; mf++)
#pragma unroll
            for (int hf = 0; hf < 2; hf++) {
                float tm = -1e30f;
#pragma unroll
                for (int nf = 0; nf < 8; nf++) {
                    tm = fmaxf(tm, SA[mf][nf][hf * 2]);
                    tm = fmaxf(tm, SA[mf][nf][hf * 2 + 1]);
                }
                tm = fmaxf(tm, __shfl_xor_sync(0xFFFFFFFF, tm, 1));
                tm = fmaxf(tm, __shfl_xor_sync(0xFFFFFFFF, tm, 2));
                float mold = mrow[mf][hf];
                float mnew = fmaxf(mold, tm);
                float f = __expf(mold - mnew);
                float rs = 0.f;
#pragma unroll
                for (int nf = 0; nf < 8; nf++) {
                    float p0 = __expf(SA[mf][nf][hf * 2]     - mnew);
                    float p1 = __expf(SA[mf][nf][hf * 2 + 1] - mnew);
                    SA[mf][nf][hf * 2]     = p0;
                    SA[mf][nf][hf * 2 + 1] = p1;
                    rs += p0 + p1;
                }
                rs += __shfl_xor_sync(0xFFFFFFFF, rs, 1);
                rs += __shfl_xor_sync(0xFFFFFFFF, rs, 2);
                lrow[mf][hf] = lrow[mf][hf] * f + rs;
                mrow[mf][hf] = mnew;
#pragma unroll
                for (int nf = 0; nf < 8; nf++) {
                    OA[mf][nf][hf * 2]     *= f;
                    OA[mf][nf][hf * 2 + 1] *= f;
                }
            }

#pragma unroll
        for (int kc = 0; kc < 4; kc++) {
            uint32_t ah[2][4], al[2][4];
#pragma unroll
            for (int mf = 0; mf < 2; mf++) {
                packsplit(SA[mf][2 * kc][0],     SA[mf][2 * kc][1],     ah[mf][0], al[mf][0]);
                packsplit(SA[mf][2 * kc][2],     SA[mf][2 * kc][3],     ah[mf][1], al[mf][1]);
                packsplit(SA[mf][2 * kc + 1][0], SA[mf][2 * kc + 1][1], ah[mf][2], al[mf][2]);
                packsplit(SA[mf][2 * kc + 1][2], SA[mf][2 * kc + 1][3], ah[mf][3], al[mf][3]);
            }
#pragma unroll
            for (int nq = 0; nq < 4; nq++) {
                uint32_t off = ((uint32_t)(kc * 16 + vrow) * 72 + nq * 16 + vnadd) * 2;
                uint32_t bv[4];
                LDSM_X4T(bv, sb + AV_H + off);
#pragma unroll
                for (int mf = 0; mf < 2; mf++) {
                    MMA16816R(OA[mf][2 * nq],     ah[mf][0], ah[mf][1], ah[mf][2], ah[mf][3], bv[0], bv[1]);
                    MMA16816R(OA[mf][2 * nq + 1], ah[mf][0], ah[mf][1], ah[mf][2], ah[mf][3], bv[2], bv[3]);
                    MMA16816R(OA[mf][2 * nq],     al[mf][0], al[mf][1], al[mf][2], al[mf][3], bv[0], bv[1]);
                    MMA16816R(OA[mf][2 * nq + 1], al[mf][0], al[mf][1], al[mf][2], al[mf][3], bv[2], bv[3]);
                }
                LDSM_X4T(bv, sb + AV_L + off);
#pragma unroll
                for (int mf = 0; mf < 2; mf++) {
                    MMA16816R(OA[mf][2 * nq],     ah[mf][0], ah[mf][1], ah[mf][2], ah[mf][3], bv[0], bv[1]);
                    MMA16816R(OA[mf][2 * nq + 1], ah[mf][0], ah[mf][1], ah[mf][2], ah[mf][3], bv[2], bv[3]);
                }
            }
        }
    }

    // ---- epilogue: write pre-split bf16 hi/lo ----
#pragma unroll
    for (int mf = 0; mf < 2; mf++)
#pragma unroll
        for (int hf = 0; hf < 2; hf++) {
            float inv = 1.f / lrow[mf][hf];
            int row = w * WINN + qt * 128 + wq * 32 + mf * 16 + (lane >> 2) + hf * 8;
            size_t base = ((size_t)b * SS + row) * HIDD + h * DD;
#pragma unroll
            for (int nf = 0; nf < 8; nf++) {
                int d = nf * 8 + (lane & 3) * 2;
                uint32_t hi, lo;
                packsplit(OA[mf][nf][hf * 2] * inv, OA[mf][nf][hf * 2 + 1] * inv, hi, lo);
                *(uint32_t*)(oh + base + d) = hi;
                *(uint32_t*)(ol + base + d) = lo;
            }
        }
}

// ---------------- launch ----------------
extern "C" void kernel_launch(void* const* d_in, const int* in_sizes, int n_in,
                              void* d_out, int out_size) {
    const float* hidden = (const float*)d_in[0];
    const float* Wq     = (const float*)d_in[1];
    const float* Wk     = (const float*)d_in[2];
    const float* Wv     = (const float*)d_in[3];
    const float* Wo     = (const float*)d_in[4];
    const float* mu     = (const float*)d_in[5];
    const float* phi    = (const float*)d_in[6];
    const float* cosT   = (const float*)d_in[7];
    const float* sinT   = (const float*)d_in[8];

    float *qb, *kb, *vb, *rkb, *rvb;
    __nv_bfloat16 *hidh, *hidl, *aoh, *aol, *wh, *wl;
    cudaGetSymbolAddress((void**)&qb,   g_q);
    cudaGetSymbolAddress((void**)&kb,   g_k);
    cudaGetSymbolAddress((void**)&vb,   g_v);
    cudaGetSymbolAddress((void**)&rkb,  g_rfak);
    cudaGetSymbolAddress((void**)&rvb,  g_rfav);
    cudaGetSymbolAddress((void**)&hidh, g_hid_h);
    cudaGetSymbolAddress((void**)&hidl, g_hid_l);
    cudaGetSymbolAddress((void**)&aoh,  g_ao_h);
    cudaGetSymbolAddress((void**)&aol,  g_ao_l);
    cudaGetSymbolAddress((void**)&wh,   g_w_h);
    cudaGetSymbolAddress((void**)&wl,   g_w_l);

    static bool attr_set = false;
    if (!attr_set) {
        cudaFuncSetAttribute((const void*)gemm_qkv,
                             cudaFuncAttributeMaxDynamicSharedMemorySize, QSMEM);
        cudaFuncSetAttribute((const void*)attn_mma,
                             cudaFuncAttributeMaxDynamicSharedMemorySize, AT_SMEM);
        attr_set = true;
    }

    const int WSZ = HIDD * HIDD;
    const int HN4 = MTOK * HIDD / 4;
    const int WN4 = WSZ / 4;

    // launches 1-5: splits (ncu -s 5 lands on launch 6 = big GEMM)
    split_kernel<<<(HN4 + 255) / 256, 256>>>(hidden, hidh, hidl, HN4);
    split_kernel<<<(WN4 + 255) / 256, 256>>>(Wq, wh + 0 * WSZ, wl + 0 * WSZ, WN4);
    split_kernel<<<(WN4 + 255) / 256, 256>>>(Wk, wh + 1 * WSZ, wl + 1 * WSZ, WN4);
    split_kernel<<<(WN4 + 255) / 256, 256>>>(Wv, wh + 2 * WSZ, wl + 2 * WSZ, WN4);
    split_kernel<<<(WN4 + 255) / 256, 256>>>(Wo, wh + 3 * WSZ, wl + 3 * WSZ, WN4);

    // launch 6: fused QKV GEMM (M=16384, N=3072)
    gemm_qkv<<<dim3(3072 / 256, MTOK / 128), 256, QSMEM>>>(hidh, hidl, wh, wl, qb, kb, vb);

    rope_kernel<<<(BB * SS * NHH * 32) / 256, 256>>>(qb, kb, cosT, sinT);

    rfa_kernel<<<BB * NHH * NCC, 128>>>(kb, vb, mu, phi, rkb, rvb);

    attn_mma<<<dim3(4, NWW, BB * NHH), 128, AT_SMEM>>>(qb, kb, vb, rkb, rvb, aoh, aol);

    // O projection (N=1024)
    gemm_qkv<<<dim3(1024 / 256, MTOK / 128), 256, QSMEM>>>(aoh, aol, wh + 3 * WSZ, wl + 3 * WSZ,
                                                           (float*)d_out, (float*)d_out, (float*)d_out);
}

// round 10
// speedup vs baseline: 1.3621x; 1.3108x over previous
#include <cuda_runtime.h>
#include <cuda_bf16.h>
#include <cuda_fp16.h>
#include <cstdint>
#include <math.h>

// ---------------- problem constants ----------------
#define BB     4
#define SS     4096
#define HIDD   1024
#define NHH    16
#define DD     64
#define WINN   512
#define CHUNKK 128
#define NWW    8
#define NCC    32
#define SCALEF 0.125f
#define MTOK   (BB*SS)   // 16384
#define GK     1024

// ---------------- scratch (device globals) ----------------
__device__ float g_q[MTOK*HIDD];
__device__ float g_k[MTOK*HIDD];
__device__ float g_v[MTOK*HIDD];
__device__ float g_rfak[BB*NHH*NCC*DD];
__device__ float g_rfav[BB*NHH*NCC*DD];
// pre-split fp16 operands
__device__ __half g_hid_h[MTOK*HIDD];
__device__ __half g_hid_l[MTOK*HIDD];
__device__ __half g_ao_h[MTOK*HIDD];
__device__ __half g_ao_l[MTOK*HIDD];
__device__ __half g_w16[4*HIDD*HIDD];

// ================= helpers =================
__device__ __forceinline__ uint32_t smem_u32(const void* p) {
    uint32_t a;
    asm("{ .reg .u64 t; cvta.to.shared.u64 t, %1; cvt.u32.u64 %0, t; }" : "=r"(a) : "l"(p));
    return a;
}

#define LDSM_X4(r, a)                                                          \
    asm volatile("ldmatrix.sync.aligned.m8n8.x4.shared.b16 {%0,%1,%2,%3}, [%4];" \
        : "=r"((r)[0]), "=r"((r)[1]), "=r"((r)[2]), "=r"((r)[3]) : "r"(a))

#define LDSM_X4T(r, a)                                                         \
    asm volatile("ldmatrix.sync.aligned.m8n8.x4.trans.shared.b16 {%0,%1,%2,%3}, [%4];" \
        : "=r"((r)[0]), "=r"((r)[1]), "=r"((r)[2]), "=r"((r)[3]) : "r"(a))

// bf16 mma (attention)
#define MMA16816(c, a, b0, b1)                                                 \
    asm volatile("mma.sync.aligned.m16n8k16.row.col.f32.bf16.bf16.f32 "        \
        "{%0,%1,%2,%3}, {%4,%5,%6,%7}, {%8,%9}, {%0,%1,%2,%3};"                \
        : "+f"((c)[0]), "+f"((c)[1]), "+f"((c)[2]), "+f"((c)[3])               \
        : "r"((a)[0]), "r"((a)[1]), "r"((a)[2]), "r"((a)[3]), "r"(b0), "r"(b1))

#define MMA16816R(c, a0, a1, a2, a3, b0, b1)                                   \
    asm volatile("mma.sync.aligned.m16n8k16.row.col.f32.bf16.bf16.f32 "        \
        "{%0,%1,%2,%3}, {%4,%5,%6,%7}, {%8,%9}, {%0,%1,%2,%3};"                \
        : "+f"((c)[0]), "+f"((c)[1]), "+f"((c)[2]), "+f"((c)[3])               \
        : "r"(a0), "r"(a1), "r"(a2), "r"(a3), "r"(b0), "r"(b1))

// fp16 mma (GEMM)
#define MMAH16816(c, a, b0, b1)                                                \
    asm volatile("mma.sync.aligned.m16n8k16.row.col.f32.f16.f16.f32 "          \
        "{%0,%1,%2,%3}, {%4,%5,%6,%7}, {%8,%9}, {%0,%1,%2,%3};"                \
        : "+f"((c)[0]), "+f"((c)[1]), "+f"((c)[2]), "+f"((c)[3])               \
        : "r"((a)[0]), "r"((a)[1]), "r"((a)[2]), "r"((a)[3]), "r"(b0), "r"(b1))

#define CPASYNC16(dst, src) \
    asm volatile("cp.async.cg.shared.global [%0], [%1], 16;" :: "r"(dst), "l"(src) : "memory")
#define CPCOMMIT() asm volatile("cp.async.commit_group;" ::: "memory")
#define CPWAIT2()  asm volatile("cp.async.wait_group 2;" ::: "memory")

__device__ __forceinline__ void cvtsts(float4 f, uint32_t dhi, uint32_t dlo) {
    __nv_bfloat162 h0, h1, l0, l1;
    h0.x = __float2bfloat16(f.x); h0.y = __float2bfloat16(f.y);
    h1.x = __float2bfloat16(f.z); h1.y = __float2bfloat16(f.w);
    l0.x = __float2bfloat16(f.x - __bfloat162float(h0.x));
    l0.y = __float2bfloat16(f.y - __bfloat162float(h0.y));
    l1.x = __float2bfloat16(f.z - __bfloat162float(h1.x));
    l1.y = __float2bfloat16(f.w - __bfloat162float(h1.y));
    asm volatile("st.shared.v2.b32 [%0], {%1, %2};"
                 :: "r"(dhi), "r"(*(uint32_t*)&h0), "r"(*(uint32_t*)&h1) : "memory");
    asm volatile("st.shared.v2.b32 [%0], {%1, %2};"
                 :: "r"(dlo), "r"(*(uint32_t*)&l0), "r"(*(uint32_t*)&l1) : "memory");
}

__device__ __forceinline__ void packsplit(float x, float y, uint32_t& hi, uint32_t& lo) {
    __nv_bfloat162 h, l;
    h.x = __float2bfloat16(x); h.y = __float2bfloat16(y);
    l.x = __float2bfloat16(x - __bfloat162float(h.x));
    l.y = __float2bfloat16(y - __bfloat162float(h.y));
    hi = *(uint32_t*)&h; lo = *(uint32_t*)&l;
}

__device__ __forceinline__ void packsplit_h(float x, float y, uint32_t& hi, uint32_t& lo) {
    __half2 h, l;
    h.x = __float2half(x); h.y = __float2half(y);
    l.x = __float2half(x - __half2float(h.x));
    l.y = __float2half(y - __half2float(h.y));
    hi = *(uint32_t*)&h; lo = *(uint32_t*)&l;
}

// ================= split (fp32 -> fp16 hi/lo) and convert (fp32 -> fp16) =================
__global__ void split_h_kernel(const float* __restrict__ src, __half* __restrict__ hi,
                               __half* __restrict__ lo, int n4) {
    int i = blockIdx.x * blockDim.x + threadIdx.x;
    if (i >= n4) return;
    float4 f = ((const float4*)src)[i];
    __half2 h0, h1, l0, l1;
    h0.x = __float2half(f.x); h0.y = __float2half(f.y);
    h1.x = __float2half(f.z); h1.y = __float2half(f.w);
    l0.x = __float2half(f.x - __half2float(h0.x));
    l0.y = __float2half(f.y - __half2float(h0.y));
    l1.x = __float2half(f.z - __half2float(h1.x));
    l1.y = __float2half(f.w - __half2float(h1.y));
    ((uint2*)hi)[i] = make_uint2(*(uint32_t*)&h0, *(uint32_t*)&h1);
    ((uint2*)lo)[i] = make_uint2(*(uint32_t*)&l0, *(uint32_t*)&l1);
}

__global__ void cvt16_kernel(const float* __restrict__ src, __half* __restrict__ dst, int n4) {
    int i = blockIdx.x * blockDim.x + threadIdx.x;
    if (i >= n4) return;
    float4 f = ((const float4*)src)[i];
    __half2 a, b;
    a.x = __float2half(f.x); a.y = __float2half(f.y);
    b.x = __float2half(f.z); b.y = __float2half(f.w);
    ((uint2*)dst)[i] = make_uint2(*(uint32_t*)&a, *(uint32_t*)&b);
}

// ============ fp16 2-pass GEMM: C = (Ah+Al)[M,K] * B16[N,K]^T ============
// CTA 128x256, warp 64x64, 4-stage cp.async
// stage: Ah[128][40] | Al[128][40] | B[256][40]  (fp16, 80B padded rows)
#define QSTAGE 4
#define ATILE  10240
#define BTILE  20480
#define QBUF   (2 * ATILE + BTILE)      // 40960
#define QSMEM  (QSTAGE * QBUF)          // 163840

__global__ void __launch_bounds__(256, 1)
gemm_f16(const __half* __restrict__ Ah, const __half* __restrict__ Al,
         const __half* __restrict__ Bw,
         float* __restrict__ C0, float* __restrict__ C1, float* __restrict__ C2) {
    extern __shared__ char dsm[];
    const uint32_t sbase = smem_u32(dsm);

    const int tid  = threadIdx.x;
    const int lane = tid & 31;
    const int wid  = tid >> 5;
    const int wm   = wid >> 2;      // 0..1
    const int wn   = wid & 3;       // 0..3
    const int m0   = blockIdx.y * 128;
    const int n0   = blockIdx.x * 256;

    const int sel = n0 >> 10;
    float* C = (sel == 0) ? C0 : (sel == 1) ? C1 : C2;
    const int nc0 = n0 & 1023;

    const int rowoff = ((lane >> 3) & 1) * 8 + (lane & 7);
    const int koff   = (lane >> 4) * 8;

    const int arow = tid >> 2, acc4 = tid & 3;
    const uint32_t adst = (uint32_t)arow * 80 + acc4 * 16;

    float acc[4][8][4];
#pragma unroll
    for (int i = 0; i < 4; i++)
#pragma unroll
        for (int j = 0; j < 8; j++)
#pragma unroll
            for (int r = 0; r < 4; r++) acc[i][j][r] = 0.f;

    auto issue_stage = [&](int kc) {
        uint32_t base = sbase + (kc & (QSTAGE - 1)) * QBUF;
        int kcol = kc * 32 + acc4 * 8;
#pragma unroll
        for (int i = 0; i < 2; i++) {
            int r = arow + i * 64;
            CPASYNC16(base + adst + (uint32_t)i * 64 * 80,
                      Ah + (size_t)(m0 + r) * GK + kcol);
            CPASYNC16(base + ATILE + adst + (uint32_t)i * 64 * 80,
                      Al + (size_t)(m0 + r) * GK + kcol);
        }
#pragma unroll
        for (int i = 0; i < 4; i++) {
            int r = arow + i * 64;
            CPASYNC16(base + 2 * ATILE + adst + (uint32_t)i * 64 * 80,
                      Bw + (size_t)(n0 + r) * GK + kcol);
        }
        CPCOMMIT();
    };

    issue_stage(0);
    issue_stage(1);
    issue_stage(2);

    for (int kc = 0; kc < GK / 32; kc++) {
        CPWAIT2();
        __syncthreads();
        if (kc + 3 < GK / 32) issue_stage(kc + 3);
        else CPCOMMIT();

        const uint32_t smA = sbase + (kc & (QSTAGE - 1)) * QBUF;
        const uint32_t smB = smA + 2 * ATILE;

#pragma unroll
        for (int ks = 0; ks < 2; ks++) {
            uint32_t af[4][4], bf[4][4];
#pragma unroll
            for (int nb = 0; nb < 4; nb++)
                LDSM_X4(bf[nb], smB + ((uint32_t)(wn * 64 + nb * 16 + rowoff) * 40 + ks * 16 + koff) * 2);
            // pass 1: Ah * B
#pragma unroll
            for (int mf = 0; mf < 4; mf++)
                LDSM_X4(af[mf], smA + ((uint32_t)(wm * 64 + mf * 16 + rowoff) * 40 + ks * 16 + koff) * 2);
#pragma unroll
            for (int mf = 0; mf < 4; mf++)
#pragma unroll
                for (int nf = 0; nf < 8; nf++)
                    MMAH16816(acc[mf][nf], af[mf], bf[nf >> 1][nf & 1], bf[nf >> 1][(nf & 1) + 2]);
            // pass 2: Al * B
#pragma unroll
            for (int mf = 0; mf < 4; mf++)
                LDSM_X4(af[mf], smA + ATILE + ((uint32_t)(wm * 64 + mf * 16 + rowoff) * 40 + ks * 16 + koff) * 2);
#pragma unroll
            for (int mf = 0; mf < 4; mf++)
#pragma unroll
                for (int nf = 0; nf < 8; nf++)
                    MMAH16816(acc[mf][nf], af[mf], bf[nf >> 1][nf & 1], bf[nf >> 1][(nf & 1) + 2]);
        }
    }

#pragma unroll
    for (int mf = 0; mf < 4; mf++) {
        int r0 = m0 + wm * 64 + mf * 16 + (lane >> 2);
#pragma unroll
        for (int nf = 0; nf < 8; nf++) {
            int c0 = nc0 + wn * 64 + nf * 8 + (lane & 3) * 2;
            *(float2*)(C + (size_t)r0 * HIDD + c0)       = make_float2(acc[mf][nf][0], acc[mf][nf][1]);
            *(float2*)(C + (size_t)(r0 + 8) * HIDD + c0) = make_float2(acc[mf][nf][2], acc[mf][nf][3]);
        }
    }
}

// ================= RoPE ((b,s,h,d) layout) =================
__global__ void rope_kernel(float* __restrict__ q, float* __restrict__ k,
                            const float* __restrict__ cosT, const float* __restrict__ sinT) {
    int idx = blockIdx.x * blockDim.x + threadIdx.x;
    if (idx >= BB * SS * NHH * 32) return;
    int d = idx & 31;
    int r = idx >> 5;
    int s = (r >> 4) & (SS - 1);
    size_t base = (size_t)r * DD;
    float c1 = cosT[s * DD + d],      s1 = sinT[s * DD + d];
    float c2 = cosT[s * DD + d + 32], s2 = sinT[s * DD + d + 32];
    float x1 = q[base + d], x2 = q[base + d + 32];
    q[base + d]      = x1 * c1 - x2 * s1;
    q[base + d + 32] = x2 * c2 + x1 * s2;
    x1 = k[base + d]; x2 = k[base + d + 32];
    k[base + d]      = x1 * c1 - x2 * s1;
    k[base + d + 32] = x2 * c2 + x1 * s2;
}

// ================= per-chunk RFA summaries ((b,s,h,d)) =================
__global__ void __launch_bounds__(128) rfa_kernel(const float* __restrict__ k,
                                                  const float* __restrict__ v,
                                                  const float* __restrict__ mu,
                                                  const float* __restrict__ phi,
                                                  float* __restrict__ rk,
                                                  float* __restrict__ rv) {
    int bh = blockIdx.x / NCC;
    int c  = blockIdx.x % NCC;
    int b  = bh / NHH, h = bh % NHH;
    int j  = threadIdx.x;
    __shared__ float sb[CHUNKK], sg[CHUNKK];
    const float* kbase = k + (((size_t)b * SS + c * CHUNKK) * NHH + h) * DD;
    const float* vbase = v + (((size_t)b * SS + c * CHUNKK) * NHH + h) * DD;
    const float* kr = kbase + (size_t)j * HIDD;
    float dm = 0.f, dp = 0.f, nn = 0.f;
#pragma unroll
    for (int d = 0; d < DD; d++) {
        float kv = kr[d];
        dm += kv * mu[h * DD + d];
        dp += kv * phi[h * DD + d];
        nn += kv * kv;
    }
    float halfn = 0.5f * SCALEF * nn;
    sb[j] = SCALEF * dm - halfn;
    sg[j] = SCALEF * dp - halfn;
    __syncthreads();
    float mb = -1e30f, mg = -1e30f;
    for (int t = 0; t < CHUNKK; t++) { mb = fmaxf(mb, sb[t]); mg = fmaxf(mg, sg[t]); }
    float eb = expf(sb[j] - mb), eg = expf(sg[j] - mg);
    __syncthreads();
    sb[j] = eb; sg[j] = eg;
    __syncthreads();
    float zb = 0.f, zg = 0.f;
    for (int t = 0; t < CHUNKK; t++) { zb += sb[t]; zg += sg[t]; }
    float invb = 1.f / zb, invg = 1.f / zg;
    if (j < DD) {
        int d = j;
        float acc = 0.f;
        for (int t = 0; t < CHUNKK; t++) acc += sb[t] * kbase[(size_t)t * HIDD + d];
        rk[((size_t)bh * NCC + c) * DD + d] = acc * invb;
    } else {
        int d = j - DD;
        float acc = 0.f;
        for (int t = 0; t < CHUNKK; t++) acc += sg[t] * vbase[(size_t)t * HIDD + d];
        rv[((size_t)bh * NCC + c) * DD + d] = acc * invg;
    }
}

// ================= MMA flash attention (bf16 3-pass core, fp16-split epilogue) =================
#define AQ_H 0
#define AQ_L 18432
#define AK_H 36864
#define AK_L 46080
#define AV_H 55296
#define AV_L 64512
#define AT_SMEM 73728

__device__ __forceinline__ void fill_split(const float* __restrict__ src, int rstride,
                                           int rows, int rlimit,
                                           uint32_t dhi, uint32_t dlo, int tid, float scale) {
    const int col4 = tid & 15;
    const int r0   = tid >> 4;
    for (int r = r0; r < rows; r += 8) {
        float4 f;
        if (r < rlimit) {
            f = *(const float4*)(src + (size_t)r * rstride + col4 * 4);
            f.x *= scale; f.y *= scale; f.z *= scale; f.w *= scale;
        } else {
            f = make_float4(0.f, 0.f, 0.f, 0.f);
        }
        uint32_t off = (uint32_t)r * 144 + col4 * 8;
        cvtsts(f, dhi + off, dlo + off);
    }
}

__global__ void __launch_bounds__(128, 2)
attn_mma(const float* __restrict__ q, const float* __restrict__ k,
         const float* __restrict__ v, const float* __restrict__ rk,
         const float* __restrict__ rv,
         __half* __restrict__ oh, __half* __restrict__ ol) {
    extern __shared__ char dsm[];
    const uint32_t sb = smem_u32(dsm);

    const int qt  = blockIdx.x;
    const int w   = blockIdx.y;
    const int bh  = blockIdx.z;
    const int b   = bh >> 4, h = bh & 15;
    const int tid = threadIdx.x, lane = tid & 31, wq = tid >> 5;

    const int rowoff = ((lane >> 3) & 1) * 8 + (lane & 7);
    const int koff   = (lane >> 4) * 8;
    const int vrow   = lane & 15;
    const int vnadd  = (lane >> 4) * 8;

    const float* qg = q + (((size_t)b * SS + w * WINN + qt * 128) * NHH + h) * DD;
    fill_split(qg, HIDD, 128, 128, sb + AQ_H, sb + AQ_L, tid, SCALEF);

    float OA[2][8][4];
#pragma unroll
    for (int mf = 0; mf < 2; mf++)
#pragma unroll
        for (int nf = 0; nf < 8; nf++)
#pragma unroll
            for (int r = 0; r < 4; r++) OA[mf][nf][r] = 0.f;
    float mrow[2][2] = {{-1e30f, -1e30f}, {-1e30f, -1e30f}};
    float lrow[2][2] = {{0.f, 0.f}, {0.f, 0.f}};

    const float* kwin = k + (((size_t)b * SS + w * WINN) * NHH + h) * DD;
    const float* vwin = v + (((size_t)b * SS + w * WINN) * NHH + h) * DD;
    const float* rkb  = rk + (size_t)bh * NCC * DD;
    const float* rvb  = rv + (size_t)bh * NCC * DD;

    const int nwt    = 2 * qt + 2;
    const int nch    = 4 * w;
    const int ntile  = nwt + (nch > 0 ? 1 : 0);

    for (int t = 0; t < ntile; t++) {
        const bool ischunk = (t == nwt);
        const int kt0 = t * 64;
        __syncthreads();
        if (!ischunk) {
            fill_split(kwin + (size_t)kt0 * HIDD, HIDD, 64, 64, sb + AK_H, sb + AK_L, tid, 1.f);
            fill_split(vwin + (size_t)kt0 * HIDD, HIDD, 64, 64, sb + AV_H, sb + AV_L, tid, 1.f);
        } else {
            fill_split(rkb, DD, 64, nch, sb + AK_H, sb + AK_L, tid, 1.f);
            fill_split(rvb, DD, 64, nch, sb + AV_H, sb + AV_L, tid, 1.f);
        }
        __syncthreads();

        float SA[2][8][4];
#pragma unroll
        for (int mf = 0; mf < 2; mf++)
#pragma unroll
            for (int nf = 0; nf < 8; nf++)
#pragma unroll
                for (int r = 0; r < 4; r++) SA[mf][nf][r] = 0.f;

#pragma unroll
        for (int pass = 0; pass < 3; pass++) {
            const uint32_t Ab = sb + ((pass == 2) ? AQ_L : AQ_H);
            const uint32_t Bb = sb + ((pass == 1) ? AK_L : AK_H);
#pragma unroll
            for (int ks = 0; ks < 4; ks++) {
                uint32_t af[2][4], bf[4][4];
#pragma unroll
                for (int mf = 0; mf < 2; mf++)
                    LDSM_X4(af[mf], Ab + ((uint32_t)(wq * 32 + mf * 16 + rowoff) * 72 + ks * 16 + koff) * 2);
#pragma unroll
                for (int nb = 0; nb < 4; nb++)
                    LDSM_X4(bf[nb], Bb + ((uint32_t)(nb * 16 + rowoff) * 72 + ks * 16 + koff) * 2);
#pragma unroll
                for (int mf = 0; mf < 2; mf++)
#pragma unroll
                    for (int nf = 0; nf < 8; nf++)
                        MMA16816(SA[mf][nf], af[mf], bf[nf >> 1][nf & 1], bf[nf >> 1][(nf & 1) + 2]);
            }
        }

        if (ischunk) {
#pragma unroll
            for (int mf = 0; mf < 2; mf++)
#pragma unroll
                for (int nf = 0; nf < 8; nf++) {
                    int colb = nf * 8 + (lane & 3) * 2;
                    if (colb     >= nch) { SA[mf][nf][0] = -1e30f; SA[mf][nf][2] = -1e30f; }
                    if (colb + 1 >= nch) { SA[mf][nf][1] = -1e30f; SA[mf][nf][3] = -1e30f; }
                }
        } else if (t >= 2 * qt) {
#pragma unroll
            for (int mf = 0; mf < 2; mf++)
#pragma unroll
                for (int nf = 0; nf < 8; nf++) {
                    int colb = kt0 + nf * 8 + (lane & 3) * 2;
#pragma unroll
                    for (int hf = 0; hf < 2; hf++) {
                        int rowq = qt * 128 + wq * 32 + mf * 16 + (lane >> 2) + hf * 8;
                        if (colb     > rowq) SA[mf][nf][hf * 2]     = -1e30f;
                        if (colb + 1 > rowq) SA[mf][nf][hf * 2 + 1] = -1e30f;
                    }
                }
        }

#pragma unroll
        for (int mf = 0; mf < 2; mf++)
#pragma unroll
            for (int hf = 0; hf < 2; hf++) {
                float tm = -1e30f;
#pragma unroll
                for (int nf = 0; nf < 8; nf++) {
                    tm = fmaxf(tm, SA[mf][nf][hf * 2]);
                    tm = fmaxf(tm, SA[mf][nf][hf * 2 + 1]);
                }
                tm = fmaxf(tm, __shfl_xor_sync(0xFFFFFFFF, tm, 1));
                tm = fmaxf(tm, __shfl_xor_sync(0xFFFFFFFF, tm, 2));
                float mold = mrow[mf][hf];
                float mnew = fmaxf(mold, tm);
                float f = __expf(mold - mnew);
                float rs = 0.f;
#pragma unroll
                for (int nf = 0; nf < 8; nf++) {
                    float p0 = __expf(SA[mf][nf][hf * 2]     - mnew);
                    float p1 = __expf(SA[mf][nf][hf * 2 + 1] - mnew);
                    SA[mf][nf][hf * 2]     = p0;
                    SA[mf][nf][hf * 2 + 1] = p1;
                    rs += p0 + p1;
                }
                rs += __shfl_xor_sync(0xFFFFFFFF, rs, 1);
                rs += __shfl_xor_sync(0xFFFFFFFF, rs, 2);
                lrow[mf][hf] = lrow[mf][hf] * f + rs;
                mrow[mf][hf] = mnew;
#pragma unroll
                for (int nf = 0; nf < 8; nf++) {
                    OA[mf][nf][hf * 2]     *= f;
                    OA[mf][nf][hf * 2 + 1] *= f;
                }
            }

#pragma unroll
        for (int kc = 0; kc < 4; kc++) {
            uint32_t ah[2][4], al[2][4];
#pragma unroll
            for (int mf = 0; mf < 2; mf++) {
                packsplit(SA[mf][2 * kc][0],     SA[mf][2 * kc][1],     ah[mf][0], al[mf][0]);
                packsplit(SA[mf][2 * kc][2],     SA[mf][2 * kc][3],     ah[mf][1], al[mf][1]);
                packsplit(SA[mf][2 * kc + 1][0], SA[mf][2 * kc + 1][1], ah[mf][2], al[mf][2]);
                packsplit(SA[mf][2 * kc + 1][2], SA[mf][2 * kc + 1][3], ah[mf][3], al[mf][3]);
            }
#pragma unroll
            for (int nq = 0; nq < 4; nq++) {
                uint32_t off = ((uint32_t)(kc * 16 + vrow) * 72 + nq * 16 + vnadd) * 2;
                uint32_t bv[4];
                LDSM_X4T(bv, sb + AV_H + off);
#pragma unroll
                for (int mf = 0; mf < 2; mf++) {
                    MMA16816R(OA[mf][2 * nq],     ah[mf][0], ah[mf][1], ah[mf][2], ah[mf][3], bv[0], bv[1]);
                    MMA16816R(OA[mf][2 * nq + 1], ah[mf][0], ah[mf][1], ah[mf][2], ah[mf][3], bv[2], bv[3]);
                    MMA16816R(OA[mf][2 * nq],     al[mf][0], al[mf][1], al[mf][2], al[mf][3], bv[0], bv[1]);
                    MMA16816R(OA[mf][2 * nq + 1], al[mf][0], al[mf][1], al[mf][2], al[mf][3], bv[2], bv[3]);
                }
                LDSM_X4T(bv, sb + AV_L + off);
#pragma unroll
                for (int mf = 0; mf < 2; mf++) {
                    MMA16816R(OA[mf][2 * nq],     ah[mf][0], ah[mf][1], ah[mf][2], ah[mf][3], bv[0], bv[1]);
                    MMA16816R(OA[mf][2 * nq + 1], ah[mf][0], ah[mf][1], ah[mf][2], ah[mf][3], bv[2], bv[3]);
                }
            }
        }
    }

    // ---- epilogue: write fp16 hi/lo for O-projection ----
#pragma unroll
    for (int mf = 0; mf < 2; mf++)
#pragma unroll
        for (int hf = 0; hf < 2; hf++) {
            float inv = 1.f / lrow[mf][hf];
            int row = w * WINN + qt * 128 + wq * 32 + mf * 16 + (lane >> 2) + hf * 8;
            size_t base = ((size_t)b * SS + row) * HIDD + h * DD;
#pragma unroll
            for (int nf = 0; nf < 8; nf++) {
                int d = nf * 8 + (lane & 3) * 2;
                uint32_t hi, lo;
                packsplit_h(OA[mf][nf][hf * 2] * inv, OA[mf][nf][hf * 2 + 1] * inv, hi, lo);
                *(uint32_t*)(oh + base + d) = hi;
                *(uint32_t*)(ol + base + d) = lo;
            }
        }
}

// ---------------- launch ----------------
extern "C" void kernel_launch(void* const* d_in, const int* in_sizes, int n_in,
                              void* d_out, int out_size) {
    const float* hidden = (const float*)d_in[0];
    const float* Wq     = (const float*)d_in[1];
    const float* Wk     = (const float*)d_in[2];
    const float* Wv     = (const float*)d_in[3];
    const float* Wo     = (const float*)d_in[4];
    const float* mu     = (const float*)d_in[5];
    const float* phi    = (const float*)d_in[6];
    const float* cosT   = (const float*)d_in[7];
    const float* sinT   = (const float*)d_in[8];

    float *qb, *kb, *vb, *rkb, *rvb;
    __half *hidh, *hidl, *aoh, *aol, *w16;
    cudaGetSymbolAddress((void**)&qb,   g_q);
    cudaGetSymbolAddress((void**)&kb,   g_k);
    cudaGetSymbolAddress((void**)&vb,   g_v);
    cudaGetSymbolAddress((void**)&rkb,  g_rfak);
    cudaGetSymbolAddress((void**)&rvb,  g_rfav);
    cudaGetSymbolAddress((void**)&hidh, g_hid_h);
    cudaGetSymbolAddress((void**)&hidl, g_hid_l);
    cudaGetSymbolAddress((void**)&aoh,  g_ao_h);
    cudaGetSymbolAddress((void**)&aol,  g_ao_l);
    cudaGetSymbolAddress((void**)&w16,  g_w16);

    static bool attr_set = false;
    if (!attr_set) {
        cudaFuncSetAttribute((const void*)gemm_f16,
                             cudaFuncAttributeMaxDynamicSharedMemorySize, QSMEM);
        cudaFuncSetAttribute((const void*)attn_mma,
                             cudaFuncAttributeMaxDynamicSharedMemorySize, AT_SMEM);
        attr_set = true;
    }

    const int WSZ = HIDD * HIDD;
    const int HN4 = MTOK * HIDD / 4;
    const int WN4 = WSZ / 4;

    split_h_kernel<<<(HN4 + 255) / 256, 256>>>(hidden, hidh, hidl, HN4);
    cvt16_kernel<<<(WN4 + 255) / 256, 256>>>(Wq, w16 + 0 * WSZ, WN4);
    cvt16_kernel<<<(WN4 + 255) / 256, 256>>>(Wk, w16 + 1 * WSZ, WN4);
    cvt16_kernel<<<(WN4 + 255) / 256, 256>>>(Wv, w16 + 2 * WSZ, WN4);
    cvt16_kernel<<<(WN4 + 255) / 256, 256>>>(Wo, w16 + 3 * WSZ, WN4);

    // fused QKV GEMM (M=16384, N=3072)
    gemm_f16<<<dim3(3072 / 256, MTOK / 128), 256, QSMEM>>>(hidh, hidl, w16, qb, kb, vb);

    rope_kernel<<<(BB * SS * NHH * 32) / 256, 256>>>(qb, kb, cosT, sinT);

    rfa_kernel<<<BB * NHH * NCC, 128>>>(kb, vb, mu, phi, rkb, rvb);

    attn_mma<<<dim3(4, NWW, BB * NHH), 128, AT_SMEM>>>(qb, kb, vb, rkb, rvb, aoh, aol);

    // O projection (N=1024)
    gemm_f16<<<dim3(1024 / 256, MTOK / 128), 256, QSMEM>>>(aoh, aol, w16 + 3 * WSZ,
                                                           (float*)d_out, (float*)d_out, (float*)d_out);
}

// round 11
// speedup vs baseline: 1.5792x; 1.1594x over previous
#include <cuda_runtime.h>
#include <cuda_bf16.h>
#include <cuda_fp16.h>
#include <cstdint>
#include <math.h>

// ---------------- problem constants ----------------
#define BB     4
#define SS     4096
#define HIDD   1024
#define NHH    16
#define DD     64
#define WINN   512
#define CHUNKK 128
#define NWW    8
#define NCC    32
#define SCALEF 0.125f
#define MTOK   (BB*SS)   // 16384
#define GK     1024

// ---------------- scratch (device globals) ----------------
__device__ float g_q[MTOK*HIDD];
__device__ float g_k[MTOK*HIDD];
__device__ float g_v[MTOK*HIDD];
__device__ float g_rfak[BB*NHH*NCC*DD];
__device__ float g_rfav[BB*NHH*NCC*DD];
__device__ __half g_hid_h[MTOK*HIDD];
__device__ __half g_hid_l[MTOK*HIDD];
__device__ __half g_ao_h[MTOK*HIDD];
__device__ __half g_w16[4*HIDD*HIDD];

// ================= helpers =================
__device__ __forceinline__ uint32_t smem_u32(const void* p) {
    uint32_t a;
    asm("{ .reg .u64 t; cvta.to.shared.u64 t, %1; cvt.u32.u64 %0, t; }" : "=r"(a) : "l"(p));
    return a;
}

#define LDSM_X4(r, a)                                                          \
    asm volatile("ldmatrix.sync.aligned.m8n8.x4.shared.b16 {%0,%1,%2,%3}, [%4];" \
        : "=r"((r)[0]), "=r"((r)[1]), "=r"((r)[2]), "=r"((r)[3]) : "r"(a))

#define LDSM_X4T(r, a)                                                         \
    asm volatile("ldmatrix.sync.aligned.m8n8.x4.trans.shared.b16 {%0,%1,%2,%3}, [%4];" \
        : "=r"((r)[0]), "=r"((r)[1]), "=r"((r)[2]), "=r"((r)[3]) : "r"(a))

#define MMA16816(c, a, b0, b1)                                                 \
    asm volatile("mma.sync.aligned.m16n8k16.row.col.f32.bf16.bf16.f32 "        \
        "{%0,%1,%2,%3}, {%4,%5,%6,%7}, {%8,%9}, {%0,%1,%2,%3};"                \
        : "+f"((c)[0]), "+f"((c)[1]), "+f"((c)[2]), "+f"((c)[3])               \
        : "r"((a)[0]), "r"((a)[1]), "r"((a)[2]), "r"((a)[3]), "r"(b0), "r"(b1))

#define MMA16816R(c, a0, a1, a2, a3, b0, b1)                                   \
    asm volatile("mma.sync.aligned.m16n8k16.row.col.f32.bf16.bf16.f32 "        \
        "{%0,%1,%2,%3}, {%4,%5,%6,%7}, {%8,%9}, {%0,%1,%2,%3};"                \
        : "+f"((c)[0]), "+f"((c)[1]), "+f"((c)[2]), "+f"((c)[3])               \
        : "r"(a0), "r"(a1), "r"(a2), "r"(a3), "r"(b0), "r"(b1))

#define MMAH16816(c, a, b0, b1)                                                \
    asm volatile("mma.sync.aligned.m16n8k16.row.col.f32.f16.f16.f32 "          \
        "{%0,%1,%2,%3}, {%4,%5,%6,%7}, {%8,%9}, {%0,%1,%2,%3};"                \
        : "+f"((c)[0]), "+f"((c)[1]), "+f"((c)[2]), "+f"((c)[3])               \
        : "r"((a)[0]), "r"((a)[1]), "r"((a)[2]), "r"((a)[3]), "r"(b0), "r"(b1))

#define CPASYNC16(dst, src) \
    asm volatile("cp.async.cg.shared.global [%0], [%1], 16;" :: "r"(dst), "l"(src) : "memory")
#define CPCOMMIT() asm volatile("cp.async.commit_group;" ::: "memory")
#define CPWAIT2()  asm volatile("cp.async.wait_group 2;" ::: "memory")
#define CPWAIT0()  asm volatile("cp.async.wait_group 0;" ::: "memory")

__device__ __forceinline__ void cvtsts(float4 f, uint32_t dhi, uint32_t dlo) {
    __nv_bfloat162 h0, h1, l0, l1;
    h0.x = __float2bfloat16(f.x); h0.y = __float2bfloat16(f.y);
    h1.x = __float2bfloat16(f.z); h1.y = __float2bfloat16(f.w);
    l0.x = __float2bfloat16(f.x - __bfloat162float(h0.x));
    l0.y = __float2bfloat16(f.y - __bfloat162float(h0.y));
    l1.x = __float2bfloat16(f.z - __bfloat162float(h1.x));
    l1.y = __float2bfloat16(f.w - __bfloat162float(h1.y));
    asm volatile("st.shared.v2.b32 [%0], {%1, %2};"
                 :: "r"(dhi), "r"(*(uint32_t*)&h0), "r"(*(uint32_t*)&h1) : "memory");
    asm volatile("st.shared.v2.b32 [%0], {%1, %2};"
                 :: "r"(dlo), "r"(*(uint32_t*)&l0), "r"(*(uint32_t*)&l1) : "memory");
}

__device__ __forceinline__ void packsplit(float x, float y, uint32_t& hi, uint32_t& lo) {
    __nv_bfloat162 h, l;
    h.x = __float2bfloat16(x); h.y = __float2bfloat16(y);
    l.x = __float2bfloat16(x - __bfloat162float(h.x));
    l.y = __float2bfloat16(y - __bfloat162float(h.y));
    hi = *(uint32_t*)&h; lo = *(uint32_t*)&l;
}

// ================= convert kernels =================
__global__ void split_h_kernel(const float* __restrict__ src, __half* __restrict__ hi,
                               __half* __restrict__ lo, int n4) {
    int i = blockIdx.x * blockDim.x + threadIdx.x;
    if (i >= n4) return;
    float4 f = ((const float4*)src)[i];
    __half2 h0, h1, l0, l1;
    h0.x = __float2half(f.x); h0.y = __float2half(f.y);
    h1.x = __float2half(f.z); h1.y = __float2half(f.w);
    l0.x = __float2half(f.x - __half2float(h0.x));
    l0.y = __float2half(f.y - __half2float(h0.y));
    l1.x = __float2half(f.z - __half2float(h1.x));
    l1.y = __float2half(f.w - __half2float(h1.y));
    ((uint2*)hi)[i] = make_uint2(*(uint32_t*)&h0, *(uint32_t*)&h1);
    ((uint2*)lo)[i] = make_uint2(*(uint32_t*)&l0, *(uint32_t*)&l1);
}

__global__ void cvt16_all(const float* __restrict__ W0, const float* __restrict__ W1,
                          const float* __restrict__ W2, const float* __restrict__ W3,
                          __half* __restrict__ dst, int n4) {
    int i = blockIdx.x * blockDim.x + threadIdx.x;
    if (i >= n4) return;
    const float* src = (blockIdx.y == 0) ? W0 : (blockIdx.y == 1) ? W1 : (blockIdx.y == 2) ? W2 : W3;
    float4 f = ((const float4*)src)[i];
    __half2 a, b;
    a.x = __float2half(f.x); a.y = __float2half(f.y);
    b.x = __float2half(f.z); b.y = __float2half(f.w);
    ((uint2*)(dst + (size_t)blockIdx.y * HIDD * HIDD))[i] = make_uint2(*(uint32_t*)&a, *(uint32_t*)&b);
}

// ============ fp16 GEMM: C = (Ah[+Al])[M,K] * B16[N,K]^T, fused RoPE epilogue ============
// CTA 128x256, warp 64x64, 4-stage cp.async
#define QSTAGE 4
#define ATILE  10240
#define BTILE  20480
#define QBUF   (2 * ATILE + BTILE)      // 40960
#define QSMEM  (QSTAGE * QBUF)          // 163840

__global__ void __launch_bounds__(256, 1)
gemm_f16(const __half* __restrict__ Ah, const __half* __restrict__ Al,
         const __half* __restrict__ Bw,
         float* __restrict__ C0, float* __restrict__ C1, float* __restrict__ C2,
         const float* __restrict__ cosT, const float* __restrict__ sinT,
         int dorope, int losel) {
    extern __shared__ char dsm[];
    const uint32_t sbase = smem_u32(dsm);

    const int tid  = threadIdx.x;
    const int lane = tid & 31;
    const int wid  = tid >> 5;
    const int wm   = wid >> 2;      // 0..1
    const int wn   = wid & 3;       // 0..3
    const int m0   = blockIdx.y * 128;
    const int n0   = blockIdx.x * 256;

    const int sel = n0 >> 10;
    float* C = (sel == 0) ? C0 : (sel == 1) ? C1 : C2;
    const int nc0 = n0 & 1023;
    const bool need_lo = (sel < losel);

    const int rowoff = ((lane >> 3) & 1) * 8 + (lane & 7);
    const int koff   = (lane >> 4) * 8;

    const int arow = tid >> 2, acc4 = tid & 3;
    const uint32_t adst = (uint32_t)arow * 80 + acc4 * 16;

    float acc[4][8][4];
#pragma unroll
    for (int i = 0; i < 4; i++)
#pragma unroll
        for (int j = 0; j < 8; j++)
#pragma unroll
            for (int r = 0; r < 4; r++) acc[i][j][r] = 0.f;

    auto issue_stage = [&](int kc) {
        uint32_t base = sbase + (kc & (QSTAGE - 1)) * QBUF;
        int kcol = kc * 32 + acc4 * 8;
#pragma unroll
        for (int i = 0; i < 2; i++) {
            int r = arow + i * 64;
            CPASYNC16(base + adst + (uint32_t)i * 64 * 80,
                      Ah + (size_t)(m0 + r) * GK + kcol);
            if (need_lo)
                CPASYNC16(base + ATILE + adst + (uint32_t)i * 64 * 80,
                          Al + (size_t)(m0 + r) * GK + kcol);
        }
#pragma unroll
        for (int i = 0; i < 4; i++) {
            int r = arow + i * 64;
            CPASYNC16(base + 2 * ATILE + adst + (uint32_t)i * 64 * 80,
                      Bw + (size_t)(n0 + r) * GK + kcol);
        }
        CPCOMMIT();
    };

    issue_stage(0);
    issue_stage(1);
    issue_stage(2);

    for (int kc = 0; kc < GK / 32; kc++) {
        CPWAIT2();
        __syncthreads();
        if (kc + 3 < GK / 32) issue_stage(kc + 3);
        else CPCOMMIT();

        const uint32_t smA = sbase + (kc & (QSTAGE - 1)) * QBUF;
        const uint32_t smB = smA + 2 * ATILE;

#pragma unroll
        for (int ks = 0; ks < 2; ks++) {
            uint32_t af[4][4], bf[4][4];
#pragma unroll
            for (int nb = 0; nb < 4; nb++)
                LDSM_X4(bf[nb], smB + ((uint32_t)(wn * 64 + nb * 16 + rowoff) * 40 + ks * 16 + koff) * 2);
#pragma unroll
            for (int mf = 0; mf < 4; mf++)
                LDSM_X4(af[mf], smA + ((uint32_t)(wm * 64 + mf * 16 + rowoff) * 40 + ks * 16 + koff) * 2);
#pragma unroll
            for (int mf = 0; mf < 4; mf++)
#pragma unroll
                for (int nf = 0; nf < 8; nf++)
                    MMAH16816(acc[mf][nf], af[mf], bf[nf >> 1][nf & 1], bf[nf >> 1][(nf & 1) + 2]);
            if (need_lo) {
#pragma unroll
                for (int mf = 0; mf < 4; mf++)
                    LDSM_X4(af[mf], smA + ATILE + ((uint32_t)(wm * 64 + mf * 16 + rowoff) * 40 + ks * 16 + koff) * 2);
#pragma unroll
                for (int mf = 0; mf < 4; mf++)
#pragma unroll
                    for (int nf = 0; nf < 8; nf++)
                        MMAH16816(acc[mf][nf], af[mf], bf[nf >> 1][nf & 1], bf[nf >> 1][(nf & 1) + 2]);
            }
        }
    }

    // ---- fused RoPE (q,k only) ----
    if (dorope && sel < 2) {
        CPWAIT0();
        __syncthreads();
        float* csm = (float*)dsm;            // [128][64]
        float* ssm = csm + 8192;             // [128][64]
        const int s0 = m0 & (SS - 1);
        for (int i = tid; i < 2048; i += 256) {
            ((float4*)csm)[i] = ((const float4*)(cosT + (size_t)s0 * DD))[i];
            ((float4*)ssm)[i] = ((const float4*)(sinT + (size_t)s0 * DD))[i];
        }
        __syncthreads();
#pragma unroll
        for (int mf = 0; mf < 4; mf++) {
            int rl0 = wm * 64 + mf * 16 + (lane >> 2);
#pragma unroll
            for (int hf = 0; hf < 2; hf++) {
                int rl = rl0 + hf * 8;
#pragma unroll
                for (int nf = 0; nf < 4; nf++) {
#pragma unroll
                    for (int j = 0; j < 2; j++) {
                        int d0 = nf * 8 + (lane & 3) * 2 + j;
                        float c1 = csm[rl * 64 + d0],      s1 = ssm[rl * 64 + d0];
                        float c2 = csm[rl * 64 + d0 + 32], s2 = ssm[rl * 64 + d0 + 32];
                        float x1 = acc[mf][nf][hf * 2 + j];
                        float x2 = acc[mf][nf + 4][hf * 2 + j];
                        acc[mf][nf][hf * 2 + j]     = x1 * c1 - x2 * s1;
                        acc[mf][nf + 4][hf * 2 + j] = x2 * c2 + x1 * s2;
                    }
                }
            }
        }
    }

#pragma unroll
    for (int mf = 0; mf < 4; mf++) {
        int r0 = m0 + wm * 64 + mf * 16 + (lane >> 2);
#pragma unroll
        for (int nf = 0; nf < 8; nf++) {
            int c0 = nc0 + wn * 64 + nf * 8 + (lane & 3) * 2;
            *(float2*)(C + (size_t)r0 * HIDD + c0)       = make_float2(acc[mf][nf][0], acc[mf][nf][1]);
            *(float2*)(C + (size_t)(r0 + 8) * HIDD + c0) = make_float2(acc[mf][nf][2], acc[mf][nf][3]);
        }
    }
}

// ================= per-chunk RFA summaries ((b,s,h,d)) =================
__global__ void __launch_bounds__(128) rfa_kernel(const float* __restrict__ k,
                                                  const float* __restrict__ v,
                                                  const float* __restrict__ mu,
                                                  const float* __restrict__ phi,
                                                  float* __restrict__ rk,
                                                  float* __restrict__ rv) {
    int bh = blockIdx.x / NCC;
    int c  = blockIdx.x % NCC;
    int b  = bh / NHH, h = bh % NHH;
    int j  = threadIdx.x;
    __shared__ float sb[CHUNKK], sg[CHUNKK];
    const float* kbase = k + (((size_t)b * SS + c * CHUNKK) * NHH + h) * DD;
    const float* vbase = v + (((size_t)b * SS + c * CHUNKK) * NHH + h) * DD;
    const float* kr = kbase + (size_t)j * HIDD;
    float dm = 0.f, dp = 0.f, nn = 0.f;
#pragma unroll
    for (int d = 0; d < DD; d++) {
        float kv = kr[d];
        dm += kv * mu[h * DD + d];
        dp += kv * phi[h * DD + d];
        nn += kv * kv;
    }
    float halfn = 0.5f * SCALEF * nn;
    sb[j] = SCALEF * dm - halfn;
    sg[j] = SCALEF * dp - halfn;
    __syncthreads();
    float mb = -1e30f, mg = -1e30f;
    for (int t = 0; t < CHUNKK; t++) { mb = fmaxf(mb, sb[t]); mg = fmaxf(mg, sg[t]); }
    float eb = expf(sb[j] - mb), eg = expf(sg[j] - mg);
    __syncthreads();
    sb[j] = eb; sg[j] = eg;
    __syncthreads();
    float zb = 0.f, zg = 0.f;
    for (int t = 0; t < CHUNKK; t++) { zb += sb[t]; zg += sg[t]; }
    float invb = 1.f / zb, invg = 1.f / zg;
    if (j < DD) {
        int d = j;
        float acc = 0.f;
        for (int t = 0; t < CHUNKK; t++) acc += sb[t] * kbase[(size_t)t * HIDD + d];
        rk[((size_t)bh * NCC + c) * DD + d] = acc * invb;
    } else {
        int d = j - DD;
        float acc = 0.f;
        for (int t = 0; t < CHUNKK; t++) acc += sg[t] * vbase[(size_t)t * HIDD + d];
        rv[((size_t)bh * NCC + c) * DD + d] = acc * invg;
    }
}

// ================= MMA flash attention (bf16 3-pass core, fp16 epilogue) =================
#define AQ_H 0
#define AQ_L 18432
#define AK_H 36864
#define AK_L 46080
#define AV_H 55296
#define AV_L 64512
#define AT_SMEM 73728

__device__ __forceinline__ void fill_split(const float* __restrict__ src, int rstride,
                                           int rows, int rlimit,
                                           uint32_t dhi, uint32_t dlo, int tid, float scale) {
    const int col4 = tid & 15;
    const int r0   = tid >> 4;
    for (int r = r0; r < rows; r += 8) {
        float4 f;
        if (r < rlimit) {
            f = *(const float4*)(src + (size_t)r * rstride + col4 * 4);
            f.x *= scale; f.y *= scale; f.z *= scale; f.w *= scale;
        } else {
            f = make_float4(0.f, 0.f, 0.f, 0.f);
        }
        uint32_t off = (uint32_t)r * 144 + col4 * 8;
        cvtsts(f, dhi + off, dlo + off);
    }
}

__global__ void __launch_bounds__(128, 2)
attn_mma(const float* __restrict__ q, const float* __restrict__ k,
         const float* __restrict__ v, const float* __restrict__ rk,
         const float* __restrict__ rv, __half* __restrict__ oh) {
    extern __shared__ char dsm[];
    const uint32_t sb = smem_u32(dsm);

    const int qt  = blockIdx.x;
    const int w   = blockIdx.y;
    const int bh  = blockIdx.z;
    const int b   = bh >> 4, h = bh & 15;
    const int tid = threadIdx.x, lane = tid & 31, wq = tid >> 5;

    const int rowoff = ((lane >> 3) & 1) * 8 + (lane & 7);
    const int koff   = (lane >> 4) * 8;
    const int vrow   = lane & 15;
    const int vnadd  = (lane >> 4) * 8;

    const float* qg = q + (((size_t)b * SS + w * WINN + qt * 128) * NHH + h) * DD;
    fill_split(qg, HIDD, 128, 128, sb + AQ_H, sb + AQ_L, tid, SCALEF);

    float OA[2][8][4];
#pragma unroll
    for (int mf = 0; mf < 2; mf++)
#pragma unroll
        for (int nf = 0; nf < 8; nf++)
#pragma unroll
            for (int r = 0; r < 4; r++) OA[mf][nf][r] = 0.f;
    float mrow[2][2] = {{-1e30f, -1e30f}, {-1e30f, -1e30f}};
    float lrow[2][2] = {{0.f, 0.f}, {0.f, 0.f}};

    const float* kwin = k + (((size_t)b * SS + w * WINN) * NHH + h) * DD;
    const float* vwin = v + (((size_t)b * SS + w * WINN) * NHH + h) * DD;
    const float* rkb  = rk + (size_t)bh * NCC * DD;
    const float* rvb  = rv + (size_t)bh * NCC * DD;

    const int nwt    = 2 * qt + 2;
    const int nch    = 4 * w;
    const int ntile  = nwt + (nch > 0 ? 1 : 0);

    for (int t = 0; t < ntile; t++) {
        const bool ischunk = (t == nwt);
        const int kt0 = t * 64;
        __syncthreads();
        if (!ischunk) {
            fill_split(kwin + (size_t)kt0 * HIDD, HIDD, 64, 64, sb + AK_H, sb + AK_L, tid, 1.f);
            fill_split(vwin + (size_t)kt0 * HIDD, HIDD, 64, 64, sb + AV_H, sb + AV_L, tid, 1.f);
        } else {
            fill_split(rkb, DD, 64, nch, sb + AK_H, sb + AK_L, tid, 1.f);
            fill_split(rvb, DD, 64, nch, sb + AV_H, sb + AV_L, tid, 1.f);
        }
        __syncthreads();

        float SA[2][8][4];
#pragma unroll
        for (int mf = 0; mf < 2; mf++)
#pragma unroll
            for (int nf = 0; nf < 8; nf++)
#pragma unroll
                for (int r = 0; r < 4; r++) SA[mf][nf][r] = 0.f;

#pragma unroll
        for (int pass = 0; pass < 3; pass++) {
            const uint32_t Ab = sb + ((pass == 2) ? AQ_L : AQ_H);
            const uint32_t Bb = sb + ((pass == 1) ? AK_L : AK_H);
#pragma unroll
            for (int ks = 0; ks < 4; ks++) {
                uint32_t af[2][4], bf[4][4];
#pragma unroll
                for (int mf = 0; mf < 2; mf++)
                    LDSM_X4(af[mf], Ab + ((uint32_t)(wq * 32 + mf * 16 + rowoff) * 72 + ks * 16 + koff) * 2);
#pragma unroll
                for (int nb = 0; nb < 4; nb++)
                    LDSM_X4(bf[nb], Bb + ((uint32_t)(nb * 16 + rowoff) * 72 + ks * 16 + koff) * 2);
#pragma unroll
                for (int mf = 0; mf < 2; mf++)
#pragma unroll
                    for (int nf = 0; nf < 8; nf++)
                        MMA16816(SA[mf][nf], af[mf], bf[nf >> 1][nf & 1], bf[nf >> 1][(nf & 1) + 2]);
            }
        }

        if (ischunk) {
#pragma unroll
            for (int mf = 0; mf < 2; mf++)
#pragma unroll
                for (int nf = 0; nf < 8; nf++) {
                    int colb = nf * 8 + (lane & 3) * 2;
                    if (colb     >= nch) { SA[mf][nf][0] = -1e30f; SA[mf][nf][2] = -1e30f; }
                    if (colb + 1 >= nch) { SA[mf][nf][1] = -1e30f; SA[mf][nf][3] = -1e30f; }
                }
        } else if (t >= 2 * qt) {
#pragma unroll
            for (int mf = 0; mf < 2; mf++)
#pragma unroll
                for (int nf = 0; nf < 8; nf++) {
                    int colb = kt0 + nf * 8 + (lane & 3) * 2;
#pragma unroll
                    for (int hf = 0; hf < 2; hf++) {
                        int rowq = qt * 128 + wq * 32 + mf * 16 + (lane >> 2) + hf * 8;
                        if (colb     > rowq) SA[mf][nf][hf * 2]     = -1e30f;
                        if (colb + 1 > rowq) SA[mf][nf][hf * 2 + 1] = -1e30f;
                    }
                }
        }

#pragma unroll
        for (int mf = 0; mf < 2; mf++)
#pragma unroll
            for (int hf = 0; hf < 2; hf++) {
                float tm = -1e30f;
#pragma unroll
                for (int nf = 0; nf < 8; nf++) {
                    tm = fmaxf(tm, SA[mf][nf][hf * 2]);
                    tm = fmaxf(tm, SA[mf][nf][hf * 2 + 1]);
                }
                tm = fmaxf(tm, __shfl_xor_sync(0xFFFFFFFF, tm, 1));
                tm = fmaxf(tm, __shfl_xor_sync(0xFFFFFFFF, tm, 2));
                float mold = mrow[mf][hf];
                float mnew = fmaxf(mold, tm);
                float f = __expf(mold - mnew);
                float rs = 0.f;
#pragma unroll
                for (int nf = 0; nf < 8; nf++) {
                    float p0 = __expf(SA[mf][nf][hf * 2]     - mnew);
                    float p1 = __expf(SA[mf][nf][hf * 2 + 1] - mnew);
                    SA[mf][nf][hf * 2]     = p0;
                    SA[mf][nf][hf * 2 + 1] = p1;
                    rs += p0 + p1;
                }
                rs += __shfl_xor_sync(0xFFFFFFFF, rs, 1);
                rs += __shfl_xor_sync(0xFFFFFFFF, rs, 2);
                lrow[mf][hf] = lrow[mf][hf] * f + rs;
                mrow[mf][hf] = mnew;
#pragma unroll
                for (int nf = 0; nf < 8; nf++) {
                    OA[mf][nf][hf * 2]     *= f;
                    OA[mf][nf][hf * 2 + 1] *= f;
                }
            }

#pragma unroll
        for (int kc = 0; kc < 4; kc++) {
            uint32_t ah[2][4], al[2][4];
#pragma unroll
            for (int mf = 0; mf < 2; mf++) {
                packsplit(SA[mf][2 * kc][0],     SA[mf][2 * kc][1],     ah[mf][0], al[mf][0]);
                packsplit(SA[mf][2 * kc][2],     SA[mf][2 * kc][3],     ah[mf][1], al[mf][1]);
                packsplit(SA[mf][2 * kc + 1][0], SA[mf][2 * kc + 1][1], ah[mf][2], al[mf][2]);
                packsplit(SA[mf][2 * kc + 1][2], SA[mf][2 * kc + 1][3], ah[mf][3], al[mf][3]);
            }
#pragma unroll
            for (int nq = 0; nq < 4; nq++) {
                uint32_t off = ((uint32_t)(kc * 16 + vrow) * 72 + nq * 16 + vnadd) * 2;
                uint32_t bv[4];
                LDSM_X4T(bv, sb + AV_H + off);
#pragma unroll
                for (int mf = 0; mf < 2; mf++) {
                    MMA16816R(OA[mf][2 * nq],     ah[mf][0], ah[mf][1], ah[mf][2], ah[mf][3], bv[0], bv[1]);
                    MMA16816R(OA[mf][2 * nq + 1], ah[mf][0], ah[mf][1], ah[mf][2], ah[mf][3], bv[2], bv[3]);
                    MMA16816R(OA[mf][2 * nq],     al[mf][0], al[mf][1], al[mf][2], al[mf][3], bv[0], bv[1]);
                    MMA16816R(OA[mf][2 * nq + 1], al[mf][0], al[mf][1], al[mf][2], al[mf][3], bv[2], bv[3]);
                }
                LDSM_X4T(bv, sb + AV_L + off);
#pragma unroll
                for (int mf = 0; mf < 2; mf++) {
                    MMA16816R(OA[mf][2 * nq],     ah[mf][0], ah[mf][1], ah[mf][2], ah[mf][3], bv[0], bv[1]);
                    MMA16816R(OA[mf][2 * nq + 1], ah[mf][0], ah[mf][1], ah[mf][2], ah[mf][3], bv[2], bv[3]);
                }
            }
        }
    }

    // ---- epilogue: single fp16 for O-projection ----
#pragma unroll
    for (int mf = 0; mf < 2; mf++)
#pragma unroll
        for (int hf = 0; hf < 2; hf++) {
            float inv = 1.f / lrow[mf][hf];
            int row = w * WINN + qt * 128 + wq * 32 + mf * 16 + (lane >> 2) + hf * 8;
            size_t base = ((size_t)b * SS + row) * HIDD + h * DD;
#pragma unroll
            for (int nf = 0; nf < 8; nf++) {
                int d = nf * 8 + (lane & 3) * 2;
                __half2 hv;
                hv.x = __float2half(OA[mf][nf][hf * 2] * inv);
                hv.y = __float2half(OA[mf][nf][hf * 2 + 1] * inv);
                *(uint32_t*)(oh + base + d) = *(uint32_t*)&hv;
            }
        }
}

// ---------------- launch ----------------
extern "C" void kernel_launch(void* const* d_in, const int* in_sizes, int n_in,
                              void* d_out, int out_size) {
    const float* hidden = (const float*)d_in[0];
    const float* Wq     = (const float*)d_in[1];
    const float* Wk     = (const float*)d_in[2];
    const float* Wv     = (const float*)d_in[3];
    const float* Wo     = (const float*)d_in[4];
    const float* mu     = (const float*)d_in[5];
    const float* phi    = (const float*)d_in[6];
    const float* cosT   = (const float*)d_in[7];
    const float* sinT   = (const float*)d_in[8];

    float *qb, *kb, *vb, *rkb, *rvb;
    __half *hidh, *hidl, *aoh, *w16;
    cudaGetSymbolAddress((void**)&qb,   g_q);
    cudaGetSymbolAddress((void**)&kb,   g_k);
    cudaGetSymbolAddress((void**)&vb,   g_v);
    cudaGetSymbolAddress((void**)&rkb,  g_rfak);
    cudaGetSymbolAddress((void**)&rvb,  g_rfav);
    cudaGetSymbolAddress((void**)&hidh, g_hid_h);
    cudaGetSymbolAddress((void**)&hidl, g_hid_l);
    cudaGetSymbolAddress((void**)&aoh,  g_ao_h);
    cudaGetSymbolAddress((void**)&w16,  g_w16);

    static bool attr_set = false;
    if (!attr_set) {
        cudaFuncSetAttribute((const void*)gemm_f16,
                             cudaFuncAttributeMaxDynamicSharedMemorySize, QSMEM);
        cudaFuncSetAttribute((const void*)attn_mma,
                             cudaFuncAttributeMaxDynamicSharedMemorySize, AT_SMEM);
        attr_set = true;
    }

    const int WSZ = HIDD * HIDD;
    const int HN4 = MTOK * HIDD / 4;
    const int WN4 = WSZ / 4;

    // launch 0: all weight converts; 1-2: hidden split halves; 3: big GEMM (ncu lands here)
    cvt16_all<<<dim3((WN4 + 255) / 256, 4), 256>>>(Wq, Wk, Wv, Wo, w16, WN4);
    split_h_kernel<<<(HN4 / 2 + 255) / 256, 256>>>(hidden, hidh, hidl, HN4 / 2);
    split_h_kernel<<<(HN4 / 2 + 255) / 256, 256>>>(hidden + MTOK * HIDD / 2,
                                                   hidh + MTOK * HIDD / 2,
                                                   hidl + MTOK * HIDD / 2, HN4 / 2);

    // fused QKV GEMM with RoPE epilogue (q,k 2-pass; v 1-pass)
    gemm_f16<<<dim3(3072 / 256, MTOK / 128), 256, QSMEM>>>(hidh, hidl, w16, qb, kb, vb,
                                                           cosT, sinT, 1, 2);

    rfa_kernel<<<BB * NHH * NCC, 128>>>(kb, vb, mu, phi, rkb, rvb);

    attn_mma<<<dim3(4, NWW, BB * NHH), 128, AT_SMEM>>>(qb, kb, vb, rkb, rvb, aoh);

    // O projection (1-pass fp16)
    gemm_f16<<<dim3(1024 / 256, MTOK / 128), 256, QSMEM>>>(aoh, aoh, w16 + 3 * WSZ,
                                                           (float*)d_out, (float*)d_out, (float*)d_out,
                                                           cosT, sinT, 0, 0);
}

// round 12
// speedup vs baseline: 1.6309x; 1.0327x over previous
#include <cuda_runtime.h>
#include <cuda_bf16.h>
#include <cuda_fp16.h>
#include <cstdint>
#include <math.h>

// ---------------- problem constants ----------------
#define BB     4
#define SS     4096
#define HIDD   1024
#define NHH    16
#define DD     64
#define WINN   512
#define CHUNKK 128
#define NWW    8
#define NCC    32
#define SCALEF 0.125f
#define MTOK   (BB*SS)   // 16384
#define GK     1024

// ---------------- scratch (device globals) ----------------
__device__ float g_q[MTOK*HIDD];
__device__ float g_k[MTOK*HIDD];
__device__ float g_v[MTOK*HIDD];
__device__ float g_rfak[BB*NHH*NCC*DD];
__device__ float g_rfav[BB*NHH*NCC*DD];
__device__ __half g_hid_h[MTOK*HIDD];
__device__ __half g_hid_l[MTOK*HIDD];
__device__ __half g_ao_h[MTOK*HIDD];
__device__ __half g_w16[4*HIDD*HIDD];

// ================= helpers =================
__device__ __forceinline__ uint32_t smem_u32(const void* p) {
    uint32_t a;
    asm("{ .reg .u64 t; cvta.to.shared.u64 t, %1; cvt.u32.u64 %0, t; }" : "=r"(a) : "l"(p));
    return a;
}

#define LDSM_X4(r, a)                                                          \
    asm volatile("ldmatrix.sync.aligned.m8n8.x4.shared.b16 {%0,%1,%2,%3}, [%4];" \
        : "=r"((r)[0]), "=r"((r)[1]), "=r"((r)[2]), "=r"((r)[3]) : "r"(a))

#define LDSM_X4T(r, a)                                                         \
    asm volatile("ldmatrix.sync.aligned.m8n8.x4.trans.shared.b16 {%0,%1,%2,%3}, [%4];" \
        : "=r"((r)[0]), "=r"((r)[1]), "=r"((r)[2]), "=r"((r)[3]) : "r"(a))

#define MMA16816(c, a, b0, b1)                                                 \
    asm volatile("mma.sync.aligned.m16n8k16.row.col.f32.bf16.bf16.f32 "        \
        "{%0,%1,%2,%3}, {%4,%5,%6,%7}, {%8,%9}, {%0,%1,%2,%3};"                \
        : "+f"((c)[0]), "+f"((c)[1]), "+f"((c)[2]), "+f"((c)[3])               \
        : "r"((a)[0]), "r"((a)[1]), "r"((a)[2]), "r"((a)[3]), "r"(b0), "r"(b1))

#define MMA16816R(c, a0, a1, a2, a3, b0, b1)                                   \
    asm volatile("mma.sync.aligned.m16n8k16.row.col.f32.bf16.bf16.f32 "        \
        "{%0,%1,%2,%3}, {%4,%5,%6,%7}, {%8,%9}, {%0,%1,%2,%3};"                \
        : "+f"((c)[0]), "+f"((c)[1]), "+f"((c)[2]), "+f"((c)[3])               \
        : "r"(a0), "r"(a1), "r"(a2), "r"(a3), "r"(b0), "r"(b1))

#define MMAH16816(c, a, b0, b1)                                                \
    asm volatile("mma.sync.aligned.m16n8k16.row.col.f32.f16.f16.f32 "          \
        "{%0,%1,%2,%3}, {%4,%5,%6,%7}, {%8,%9}, {%0,%1,%2,%3};"                \
        : "+f"((c)[0]), "+f"((c)[1]), "+f"((c)[2]), "+f"((c)[3])               \
        : "r"((a)[0]), "r"((a)[1]), "r"((a)[2]), "r"((a)[3]), "r"(b0), "r"(b1))

#define CPASYNC16(dst, src) \
    asm volatile("cp.async.cg.shared.global [%0], [%1], 16;" :: "r"(dst), "l"(src) : "memory")
#define CPCOMMIT() asm volatile("cp.async.commit_group;" ::: "memory")
#define CPWAIT2()  asm volatile("cp.async.wait_group 2;" ::: "memory")
#define CPWAIT0()  asm volatile("cp.async.wait_group 0;" ::: "memory")

__device__ __forceinline__ void cvtsts(float4 f, uint32_t dhi, uint32_t dlo) {
    __nv_bfloat162 h0, h1, l0, l1;
    h0.x = __float2bfloat16(f.x); h0.y = __float2bfloat16(f.y);
    h1.x = __float2bfloat16(f.z); h1.y = __float2bfloat16(f.w);
    l0.x = __float2bfloat16(f.x - __bfloat162float(h0.x));
    l0.y = __float2bfloat16(f.y - __bfloat162float(h0.y));
    l1.x = __float2bfloat16(f.z - __bfloat162float(h1.x));
    l1.y = __float2bfloat16(f.w - __bfloat162float(h1.y));
    asm volatile("st.shared.v2.b32 [%0], {%1, %2};"
                 :: "r"(dhi), "r"(*(uint32_t*)&h0), "r"(*(uint32_t*)&h1) : "memory");
    asm volatile("st.shared.v2.b32 [%0], {%1, %2};"
                 :: "r"(dlo), "r"(*(uint32_t*)&l0), "r"(*(uint32_t*)&l1) : "memory");
}

__device__ __forceinline__ void packsplit(float x, float y, uint32_t& hi, uint32_t& lo) {
    __nv_bfloat162 h, l;
    h.x = __float2bfloat16(x); h.y = __float2bfloat16(y);
    l.x = __float2bfloat16(x - __bfloat162float(h.x));
    l.y = __float2bfloat16(y - __bfloat162float(h.y));
    hi = *(uint32_t*)&h; lo = *(uint32_t*)&l;
}

// ================= convert kernels =================
__global__ void split_h_kernel(const float* __restrict__ src, __half* __restrict__ hi,
                               __half* __restrict__ lo, int n4) {
    int i = blockIdx.x * blockDim.x + threadIdx.x;
    if (i >= n4) return;
    float4 f = ((const float4*)src)[i];
    __half2 h0, h1, l0, l1;
    h0.x = __float2half(f.x); h0.y = __float2half(f.y);
    h1.x = __float2half(f.z); h1.y = __float2half(f.w);
    l0.x = __float2half(f.x - __half2float(h0.x));
    l0.y = __float2half(f.y - __half2float(h0.y));
    l1.x = __float2half(f.z - __half2float(h1.x));
    l1.y = __float2half(f.w - __half2float(h1.y));
    ((uint2*)hi)[i] = make_uint2(*(uint32_t*)&h0, *(uint32_t*)&h1);
    ((uint2*)lo)[i] = make_uint2(*(uint32_t*)&l0, *(uint32_t*)&l1);
}

__global__ void cvt16_all(const float* __restrict__ W0, const float* __restrict__ W1,
                          const float* __restrict__ W2, const float* __restrict__ W3,
                          __half* __restrict__ dst, int n4) {
    int i = blockIdx.x * blockDim.x + threadIdx.x;
    if (i >= n4) return;
    const float* src = (blockIdx.y == 0) ? W0 : (blockIdx.y == 1) ? W1 : (blockIdx.y == 2) ? W2 : W3;
    float4 f = ((const float4*)src)[i];
    __half2 a, b;
    a.x = __float2half(f.x); a.y = __float2half(f.y);
    b.x = __float2half(f.z); b.y = __float2half(f.w);
    ((uint2*)(dst + (size_t)blockIdx.y * HIDD * HIDD))[i] = make_uint2(*(uint32_t*)&a, *(uint32_t*)&b);
}

// ============ fp16 GEMM: C = (Ah[+Al])[M,K] * B16[N,K]^T, fused RoPE epilogue ============
// CTA 128x256, 512 threads, warp tile 32x64, 4-stage cp.async
#define QSTAGE 4
#define ATILE  10240
#define BTILE  20480
#define QBUF   (2 * ATILE + BTILE)      // 40960
#define QSMEM  (QSTAGE * QBUF)          // 163840

__global__ void __launch_bounds__(512, 1)
gemm_f16(const __half* __restrict__ Ah, const __half* __restrict__ Al,
         const __half* __restrict__ Bw,
         float* __restrict__ C0, float* __restrict__ C1, float* __restrict__ C2,
         const float* __restrict__ cosT, const float* __restrict__ sinT,
         int dorope, int losel) {
    extern __shared__ char dsm[];
    const uint32_t sbase = smem_u32(dsm);

    const int tid  = threadIdx.x;
    const int lane = tid & 31;
    const int wid  = tid >> 5;       // 0..15
    const int wm   = wid & 3;        // 0..3 (32-row stripes)
    const int wn   = wid >> 2;       // 0..3 (64-col stripes)
    const int m0   = blockIdx.y * 128;
    const int n0   = blockIdx.x * 256;

    const int sel = n0 >> 10;
    float* C = (sel == 0) ? C0 : (sel == 1) ? C1 : C2;
    const int nc0 = n0 & 1023;
    const bool need_lo = (sel < losel);

    const int rowoff = ((lane >> 3) & 1) * 8 + (lane & 7);
    const int koff   = (lane >> 4) * 8;

    // hoisted LDSM base offsets (bytes, stage-base added in loop)
    uint32_t aoffb[2], boffb[4];
#pragma unroll
    for (int mf = 0; mf < 2; mf++)
        aoffb[mf] = ((uint32_t)(wm * 32 + mf * 16 + rowoff) * 40 + koff) * 2;
#pragma unroll
    for (int nb = 0; nb < 4; nb++)
        boffb[nb] = 2 * ATILE + ((uint32_t)(wn * 64 + nb * 16 + rowoff) * 40 + koff) * 2;

    // cp.async mapping: 512 threads, per stage: 1 Ah + (1 Al) + 2 B chunks each
    const int arow = tid >> 2, acc4 = tid & 3;
    const uint32_t adst = (uint32_t)arow * 80 + acc4 * 16;

    float acc[2][8][4];
#pragma unroll
    for (int i = 0; i < 2; i++)
#pragma unroll
        for (int j = 0; j < 8; j++)
#pragma unroll
            for (int r = 0; r < 4; r++) acc[i][j][r] = 0.f;

    auto issue_stage = [&](int kc) {
        uint32_t base = sbase + (kc & (QSTAGE - 1)) * QBUF;
        int kcol = kc * 32 + acc4 * 8;
        CPASYNC16(base + adst, Ah + (size_t)(m0 + arow) * GK + kcol);
        if (need_lo)
            CPASYNC16(base + ATILE + adst, Al + (size_t)(m0 + arow) * GK + kcol);
        CPASYNC16(base + 2 * ATILE + adst, Bw + (size_t)(n0 + arow) * GK + kcol);
        CPASYNC16(base + 2 * ATILE + adst + 128 * 80,
                  Bw + (size_t)(n0 + arow + 128) * GK + kcol);
        CPCOMMIT();
    };

    issue_stage(0);
    issue_stage(1);
    issue_stage(2);

    for (int kc = 0; kc < GK / 32; kc++) {
        CPWAIT2();
        __syncthreads();
        if (kc + 3 < GK / 32) issue_stage(kc + 3);
        else CPCOMMIT();

        const uint32_t stb = sbase + (kc & (QSTAGE - 1)) * QBUF;

#pragma unroll
        for (int ks = 0; ks < 2; ks++) {
            const uint32_t ksb = stb + ks * 32;
            uint32_t af[2][4], bf[4][4];
#pragma unroll
            for (int nb = 0; nb < 4; nb++)
                LDSM_X4(bf[nb], ksb + boffb[nb]);
#pragma unroll
            for (int mf = 0; mf < 2; mf++)
                LDSM_X4(af[mf], ksb + aoffb[mf]);
#pragma unroll
            for (int mf = 0; mf < 2; mf++)
#pragma unroll
                for (int nf = 0; nf < 8; nf++)
                    MMAH16816(acc[mf][nf], af[mf], bf[nf >> 1][nf & 1], bf[nf >> 1][(nf & 1) + 2]);
            if (need_lo) {
#pragma unroll
                for (int mf = 0; mf < 2; mf++)
                    LDSM_X4(af[mf], ksb + ATILE + aoffb[mf]);
#pragma unroll
                for (int mf = 0; mf < 2; mf++)
#pragma unroll
                    for (int nf = 0; nf < 8; nf++)
                        MMAH16816(acc[mf][nf], af[mf], bf[nf >> 1][nf & 1], bf[nf >> 1][(nf & 1) + 2]);
            }
        }
    }

    // ---- fused RoPE (q,k only) ----
    if (dorope && sel < 2) {
        CPWAIT0();
        __syncthreads();
        float* csm = (float*)dsm;            // [128][64]
        float* ssm = csm + 8192;             // [128][64]
        const int s0 = m0 & (SS - 1);
        for (int i = tid; i < 2048; i += 512) {
            ((float4*)csm)[i] = ((const float4*)(cosT + (size_t)s0 * DD))[i];
            ((float4*)ssm)[i] = ((const float4*)(sinT + (size_t)s0 * DD))[i];
        }
        __syncthreads();
#pragma unroll
        for (int mf = 0; mf < 2; mf++) {
            int rl0 = wm * 32 + mf * 16 + (lane >> 2);
#pragma unroll
            for (int hf = 0; hf < 2; hf++) {
                int rl = rl0 + hf * 8;
#pragma unroll
                for (int nf = 0; nf < 4; nf++) {
#pragma unroll
                    for (int j = 0; j < 2; j++) {
                        int d0 = nf * 8 + (lane & 3) * 2 + j;
                        float c1 = csm[rl * 64 + d0],      s1 = ssm[rl * 64 + d0];
                        float c2 = csm[rl * 64 + d0 + 32], s2 = ssm[rl * 64 + d0 + 32];
                        float x1 = acc[mf][nf][hf * 2 + j];
                        float x2 = acc[mf][nf + 4][hf * 2 + j];
                        acc[mf][nf][hf * 2 + j]     = x1 * c1 - x2 * s1;
                        acc[mf][nf + 4][hf * 2 + j] = x2 * c2 + x1 * s2;
                    }
                }
            }
        }
    }

#pragma unroll
    for (int mf = 0; mf < 2; mf++) {
        int r0 = m0 + wm * 32 + mf * 16 + (lane >> 2);
#pragma unroll
        for (int nf = 0; nf < 8; nf++) {
            int c0 = nc0 + wn * 64 + nf * 8 + (lane & 3) * 2;
            *(float2*)(C + (size_t)r0 * HIDD + c0)       = make_float2(acc[mf][nf][0], acc[mf][nf][1]);
            *(float2*)(C + (size_t)(r0 + 8) * HIDD + c0) = make_float2(acc[mf][nf][2], acc[mf][nf][3]);
        }
    }
}

// ================= per-chunk RFA summaries ((b,s,h,d)) =================
__global__ void __launch_bounds__(128) rfa_kernel(const float* __restrict__ k,
                                                  const float* __restrict__ v,
                                                  const float* __restrict__ mu,
                                                  const float* __restrict__ phi,
                                                  float* __restrict__ rk,
                                                  float* __restrict__ rv) {
    int bh = blockIdx.x / NCC;
    int c  = blockIdx.x % NCC;
    int b  = bh / NHH, h = bh % NHH;
    int j  = threadIdx.x;
    __shared__ float sb[CHUNKK], sg[CHUNKK];
    const float* kbase = k + (((size_t)b * SS + c * CHUNKK) * NHH + h) * DD;
    const float* vbase = v + (((size_t)b * SS + c * CHUNKK) * NHH + h) * DD;
    const float* kr = kbase + (size_t)j * HIDD;
    float dm = 0.f, dp = 0.f, nn = 0.f;
#pragma unroll
    for (int d = 0; d < DD; d++) {
        float kv = kr[d];
        dm += kv * mu[h * DD + d];
        dp += kv * phi[h * DD + d];
        nn += kv * kv;
    }
    float halfn = 0.5f * SCALEF * nn;
    sb[j] = SCALEF * dm - halfn;
    sg[j] = SCALEF * dp - halfn;
    __syncthreads();
    float mb = -1e30f, mg = -1e30f;
    for (int t = 0; t < CHUNKK; t++) { mb = fmaxf(mb, sb[t]); mg = fmaxf(mg, sg[t]); }
    float eb = expf(sb[j] - mb), eg = expf(sg[j] - mg);
    __syncthreads();
    sb[j] = eb; sg[j] = eg;
    __syncthreads();
    float zb = 0.f, zg = 0.f;
    for (int t = 0; t < CHUNKK; t++) { zb += sb[t]; zg += sg[t]; }
    float invb = 1.f / zb, invg = 1.f / zg;
    if (j < DD) {
        int d = j;
        float acc = 0.f;
        for (int t = 0; t < CHUNKK; t++) acc += sb[t] * kbase[(size_t)t * HIDD + d];
        rk[((size_t)bh * NCC + c) * DD + d] = acc * invb;
    } else {
        int d = j - DD;
        float acc = 0.f;
        for (int t = 0; t < CHUNKK; t++) acc += sg[t] * vbase[(size_t)t * HIDD + d];
        rv[((size_t)bh * NCC + c) * DD + d] = acc * invg;
    }
}

// ================= MMA flash attention (bf16 3-pass core, fp16 epilogue) =================
#define AQ_H 0
#define AQ_L 18432
#define AK_H 36864
#define AK_L 46080
#define AV_H 55296
#define AV_L 64512
#define AT_SMEM 73728

__device__ __forceinline__ void fill_split(const float* __restrict__ src, int rstride,
                                           int rows, int rlimit,
                                           uint32_t dhi, uint32_t dlo, int tid, float scale) {
    const int col4 = tid & 15;
    const int r0   = tid >> 4;
    for (int r = r0; r < rows; r += 8) {
        float4 f;
        if (r < rlimit) {
            f = *(const float4*)(src + (size_t)r * rstride + col4 * 4);
            f.x *= scale; f.y *= scale; f.z *= scale; f.w *= scale;
        } else {
            f = make_float4(0.f, 0.f, 0.f, 0.f);
        }
        uint32_t off = (uint32_t)r * 144 + col4 * 8;
        cvtsts(f, dhi + off, dlo + off);
    }
}

__global__ void __launch_bounds__(128, 2)
attn_mma(const float* __restrict__ q, const float* __restrict__ k,
         const float* __restrict__ v, const float* __restrict__ rk,
         const float* __restrict__ rv, __half* __restrict__ oh) {
    extern __shared__ char dsm[];
    const uint32_t sb = smem_u32(dsm);

    const int qt  = blockIdx.x;
    const int w   = blockIdx.y;
    const int bh  = blockIdx.z;
    const int b   = bh >> 4, h = bh & 15;
    const int tid = threadIdx.x, lane = tid & 31, wq = tid >> 5;

    const int rowoff = ((lane >> 3) & 1) * 8 + (lane & 7);
    const int koff   = (lane >> 4) * 8;
    const int vrow   = lane & 15;
    const int vnadd  = (lane >> 4) * 8;

    const float* qg = q + (((size_t)b * SS + w * WINN + qt * 128) * NHH + h) * DD;
    fill_split(qg, HIDD, 128, 128, sb + AQ_H, sb + AQ_L, tid, SCALEF);

    float OA[2][8][4];
#pragma unroll
    for (int mf = 0; mf < 2; mf++)
#pragma unroll
        for (int nf = 0; nf < 8; nf++)
#pragma unroll
            for (int r = 0; r < 4; r++) OA[mf][nf][r] = 0.f;
    float mrow[2][2] = {{-1e30f, -1e30f}, {-1e30f, -1e30f}};
    float lrow[2][2] = {{0.f, 0.f}, {0.f, 0.f}};

    const float* kwin = k + (((size_t)b * SS + w * WINN) * NHH + h) * DD;
    const float* vwin = v + (((size_t)b * SS + w * WINN) * NHH + h) * DD;
    const float* rkb  = rk + (size_t)bh * NCC * DD;
    const float* rvb  = rv + (size_t)bh * NCC * DD;

    const int nwt    = 2 * qt + 2;
    const int nch    = 4 * w;
    const int ntile  = nwt + (nch > 0 ? 1 : 0);

    for (int t = 0; t < ntile; t++) {
        const bool ischunk = (t == nwt);
        const int kt0 = t * 64;
        __syncthreads();
        if (!ischunk) {
            fill_split(kwin + (size_t)kt0 * HIDD, HIDD, 64, 64, sb + AK_H, sb + AK_L, tid, 1.f);
            fill_split(vwin + (size_t)kt0 * HIDD, HIDD, 64, 64, sb + AV_H, sb + AV_L, tid, 1.f);
        } else {
            fill_split(rkb, DD, 64, nch, sb + AK_H, sb + AK_L, tid, 1.f);
            fill_split(rvb, DD, 64, nch, sb + AV_H, sb + AV_L, tid, 1.f);
        }
        __syncthreads();

        float SA[2][8][4];
#pragma unroll
        for (int mf = 0; mf < 2; mf++)
#pragma unroll
            for (int nf = 0; nf < 8; nf++)
#pragma unroll
                for (int r = 0; r < 4; r++) SA[mf][nf][r] = 0.f;

#pragma unroll
        for (int pass = 0; pass < 3; pass++) {
            const uint32_t Ab = sb + ((pass == 2) ? AQ_L : AQ_H);
            const uint32_t Bb = sb + ((pass == 1) ? AK_L : AK_H);
#pragma unroll
            for (int ks = 0; ks < 4; ks++) {
                uint32_t af[2][4], bf[4][4];
#pragma unroll
                for (int mf = 0; mf < 2; mf++)
                    LDSM_X4(af[mf], Ab + ((uint32_t)(wq * 32 + mf * 16 + rowoff) * 72 + ks * 16 + koff) * 2);
#pragma unroll
                for (int nb = 0; nb < 4; nb++)
                    LDSM_X4(bf[nb], Bb + ((uint32_t)(nb * 16 + rowoff) * 72 + ks * 16 + koff) * 2);
#pragma unroll
                for (int mf = 0; mf < 2; mf++)
#pragma unroll
                    for (int nf = 0; nf < 8; nf++)
                        MMA16816(SA[mf][nf], af[mf], bf[nf >> 1][nf & 1], bf[nf >> 1][(nf & 1) + 2]);
            }
        }

        if (ischunk) {
#pragma unroll
            for (int mf = 0; mf < 2; mf++)
#pragma unroll
                for (int nf = 0; nf < 8; nf++) {
                    int colb = nf * 8 + (lane & 3) * 2;
                    if (colb     >= nch) { SA[mf][nf][0] = -1e30f; SA[mf][nf][2] = -1e30f; }
                    if (colb + 1 >= nch) { SA[mf][nf][1] = -1e30f; SA[mf][nf][3] = -1e30f; }
                }
        } else if (t >= 2 * qt) {
#pragma unroll
            for (int mf = 0; mf < 2; mf++)
#pragma unroll
                for (int nf = 0; nf < 8; nf++) {
                    int colb = kt0 + nf * 8 + (lane & 3) * 2;
#pragma unroll
                    for (int hf = 0; hf < 2; hf++) {
                        int rowq = qt * 128 + wq * 32 + mf * 16 + (lane >> 2) + hf * 8;
                        if (colb     > rowq) SA[mf][nf][hf * 2]     = -1e30f;
                        if (colb + 1 > rowq) SA[mf][nf][hf * 2 + 1] = -1e30f;
                    }
                }
        }

#pragma unroll
        for (int mf = 0; mf < 2; mf++)
#pragma unroll
            for (int hf = 0; hf < 2; hf++) {
                float tm = -1e30f;
#pragma unroll
                for (int nf = 0; nf < 8; nf++) {
                    tm = fmaxf(tm, SA[mf][nf][hf * 2]);
                    tm = fmaxf(tm, SA[mf][nf][hf * 2 + 1]);
                }
                tm = fmaxf(tm, __shfl_xor_sync(0xFFFFFFFF, tm, 1));
                tm = fmaxf(tm, __shfl_xor_sync(0xFFFFFFFF, tm, 2));
                float mold = mrow[mf][hf];
                float mnew = fmaxf(mold, tm);
                float f = __expf(mold - mnew);
                float rs = 0.f;
#pragma unroll
                for (int nf = 0; nf < 8; nf++) {
                    float p0 = __expf(SA[mf][nf][hf * 2]     - mnew);
                    float p1 = __expf(SA[mf][nf][hf * 2 + 1] - mnew);
                    SA[mf][nf][hf * 2]     = p0;
                    SA[mf][nf][hf * 2 + 1] = p1;
                    rs += p0 + p1;
                }
                rs += __shfl_xor_sync(0xFFFFFFFF, rs, 1);
                rs += __shfl_xor_sync(0xFFFFFFFF, rs, 2);
                lrow[mf][hf] = lrow[mf][hf] * f + rs;
                mrow[mf][hf] = mnew;
#pragma unroll
                for (int nf = 0; nf < 8; nf++) {
                    OA[mf][nf][hf * 2]     *= f;
                    OA[mf][nf][hf * 2 + 1] *= f;
                }
            }

#pragma unroll
        for (int kc = 0; kc < 4; kc++) {
            uint32_t ah[2][4], al[2][4];
#pragma unroll
            for (int mf = 0; mf < 2; mf++) {
                packsplit(SA[mf][2 * kc][0],     SA[mf][2 * kc][1],     ah[mf][0], al[mf][0]);
                packsplit(SA[mf][2 * kc][2],     SA[mf][2 * kc][3],     ah[mf][1], al[mf][1]);
                packsplit(SA[mf][2 * kc + 1][0], SA[mf][2 * kc + 1][1], ah[mf][2], al[mf][2]);
                packsplit(SA[mf][2 * kc + 1][2], SA[mf][2 * kc + 1][3], ah[mf][3], al[mf][3]);
            }
#pragma unroll
            for (int nq = 0; nq < 4; nq++) {
                uint32_t off = ((uint32_t)(kc * 16 + vrow) * 72 + nq * 16 + vnadd) * 2;
                uint32_t bv[4];
                LDSM_X4T(bv, sb + AV_H + off);
#pragma unroll
                for (int mf = 0; mf < 2; mf++) {
                    MMA16816R(OA[mf][2 * nq],     ah[mf][0], ah[mf][1], ah[mf][2], ah[mf][3], bv[0], bv[1]);
                    MMA16816R(OA[mf][2 * nq + 1], ah[mf][0], ah[mf][1], ah[mf][2], ah[mf][3], bv[2], bv[3]);
                    MMA16816R(OA[mf][2 * nq],     al[mf][0], al[mf][1], al[mf][2], al[mf][3], bv[0], bv[1]);
                    MMA16816R(OA[mf][2 * nq + 1], al[mf][0], al[mf][1], al[mf][2], al[mf][3], bv[2], bv[3]);
                }
                LDSM_X4T(bv, sb + AV_L + off);
#pragma unroll
                for (int mf = 0; mf < 2; mf++) {
                    MMA16816R(OA[mf][2 * nq],     ah[mf][0], ah[mf][1], ah[mf][2], ah[mf][3], bv[0], bv[1]);
                    MMA16816R(OA[mf][2 * nq + 1], ah[mf][0], ah[mf][1], ah[mf][2], ah[mf][3], bv[2], bv[3]);
                }
            }
        }
    }

    // ---- epilogue: single fp16 for O-projection ----
#pragma unroll
    for (int mf = 0; mf < 2; mf++)
#pragma unroll
        for (int hf = 0; hf < 2; hf++) {
            float inv = 1.f / lrow[mf][hf];
            int row = w * WINN + qt * 128 + wq * 32 + mf * 16 + (lane >> 2) + hf * 8;
            size_t base = ((size_t)b * SS + row) * HIDD + h * DD;
#pragma unroll
            for (int nf = 0; nf < 8; nf++) {
                int d = nf * 8 + (lane & 3) * 2;
                __half2 hv;
                hv.x = __float2half(OA[mf][nf][hf * 2] * inv);
                hv.y = __float2half(OA[mf][nf][hf * 2 + 1] * inv);
                *(uint32_t*)(oh + base + d) = *(uint32_t*)&hv;
            }
        }
}

// ---------------- launch ----------------
extern "C" void kernel_launch(void* const* d_in, const int* in_sizes, int n_in,
                              void* d_out, int out_size) {
    const float* hidden = (const float*)d_in[0];
    const float* Wq     = (const float*)d_in[1];
    const float* Wk     = (const float*)d_in[2];
    const float* Wv     = (const float*)d_in[3];
    const float* Wo     = (const float*)d_in[4];
    const float* mu     = (const float*)d_in[5];
    const float* phi    = (const float*)d_in[6];
    const float* cosT   = (const float*)d_in[7];
    const float* sinT   = (const float*)d_in[8];

    float *qb, *kb, *vb, *rkb, *rvb;
    __half *hidh, *hidl, *aoh, *w16;
    cudaGetSymbolAddress((void**)&qb,   g_q);
    cudaGetSymbolAddress((void**)&kb,   g_k);
    cudaGetSymbolAddress((void**)&vb,   g_v);
    cudaGetSymbolAddress((void**)&rkb,  g_rfak);
    cudaGetSymbolAddress((void**)&rvb,  g_rfav);
    cudaGetSymbolAddress((void**)&hidh, g_hid_h);
    cudaGetSymbolAddress((void**)&hidl, g_hid_l);
    cudaGetSymbolAddress((void**)&aoh,  g_ao_h);
    cudaGetSymbolAddress((void**)&w16,  g_w16);

    static bool attr_set = false;
    if (!attr_set) {
        cudaFuncSetAttribute((const void*)gemm_f16,
                             cudaFuncAttributeMaxDynamicSharedMemorySize, QSMEM);
        cudaFuncSetAttribute((const void*)attn_mma,
                             cudaFuncAttributeMaxDynamicSharedMemorySize, AT_SMEM);
        attr_set = true;
    }

    const int WSZ = HIDD * HIDD;
    const int HN4 = MTOK * HIDD / 4;
    const int WN4 = WSZ / 4;

    // launch 0: weight converts; 1-2: hidden split halves; 3: big GEMM (ncu lands here)
    cvt16_all<<<dim3((WN4 + 255) / 256, 4), 256>>>(Wq, Wk, Wv, Wo, w16, WN4);
    split_h_kernel<<<(HN4 / 2 + 255) / 256, 256>>>(hidden, hidh, hidl, HN4 / 2);
    split_h_kernel<<<(HN4 / 2 + 255) / 256, 256>>>(hidden + MTOK * HIDD / 2,
                                                   hidh + MTOK * HIDD / 2,
                                                   hidl + MTOK * HIDD / 2, HN4 / 2);

    // fused QKV GEMM with RoPE epilogue (q,k 2-pass; v 1-pass)
    gemm_f16<<<dim3(3072 / 256, MTOK / 128), 512, QSMEM>>>(hidh, hidl, w16, qb, kb, vb,
                                                           cosT, sinT, 1, 2);

    rfa_kernel<<<BB * NHH * NCC, 128>>>(kb, vb, mu, phi, rkb, rvb);

    attn_mma<<<dim3(4, NWW, BB * NHH), 128, AT_SMEM>>>(qb, kb, vb, rkb, rvb, aoh);

    // O projection (1-pass fp16)
    gemm_f16<<<dim3(1024 / 256, MTOK / 128), 512, QSMEM>>>(aoh, aoh, w16 + 3 * WSZ,
                                                           (float*)d_out, (float*)d_out, (float*)d_out,
                                                           cosT, sinT, 0, 0);
}

// round 13
// speedup vs baseline: 1.9429x; 1.1913x over previous
#include <cuda_runtime.h>
#include <cuda_bf16.h>
#include <cuda_fp16.h>
#include <cstdint>
#include <math.h>

// ---------------- problem constants ----------------
#define BB     4
#define SS     4096
#define HIDD   1024
#define NHH    16
#define DD     64
#define WINN   512
#define CHUNKK 128
#define NWW    8
#define NCC    32
#define SCALEF 0.125f
#define MTOK   (BB*SS)   // 16384
#define GK     1024

// ---------------- scratch (device globals) ----------------
__device__ float g_q[MTOK*HIDD];
__device__ float g_k[MTOK*HIDD];
__device__ float g_v[MTOK*HIDD];
__device__ float g_rfak[BB*NHH*NCC*DD];
__device__ float g_rfav[BB*NHH*NCC*DD];
__device__ __half g_hid_h[MTOK*HIDD];
__device__ __half g_hid_l[MTOK*HIDD];
__device__ __half g_ao_h[MTOK*HIDD];
__device__ __half g_w16[4*HIDD*HIDD];

// ================= helpers =================
__device__ __forceinline__ uint32_t smem_u32(const void* p) {
    uint32_t a;
    asm("{ .reg .u64 t; cvta.to.shared.u64 t, %1; cvt.u32.u64 %0, t; }" : "=r"(a) : "l"(p));
    return a;
}

#define LDSM_X4(r, a)                                                          \
    asm volatile("ldmatrix.sync.aligned.m8n8.x4.shared.b16 {%0,%1,%2,%3}, [%4];" \
        : "=r"((r)[0]), "=r"((r)[1]), "=r"((r)[2]), "=r"((r)[3]) : "r"(a))

#define LDSM_X4T(r, a)                                                         \
    asm volatile("ldmatrix.sync.aligned.m8n8.x4.trans.shared.b16 {%0,%1,%2,%3}, [%4];" \
        : "=r"((r)[0]), "=r"((r)[1]), "=r"((r)[2]), "=r"((r)[3]) : "r"(a))

// fp16 mma
#define MMAH16816(c, a, b0, b1)                                                \
    asm volatile("mma.sync.aligned.m16n8k16.row.col.f32.f16.f16.f32 "          \
        "{%0,%1,%2,%3}, {%4,%5,%6,%7}, {%8,%9}, {%0,%1,%2,%3};"                \
        : "+f"((c)[0]), "+f"((c)[1]), "+f"((c)[2]), "+f"((c)[3])               \
        : "r"((a)[0]), "r"((a)[1]), "r"((a)[2]), "r"((a)[3]), "r"(b0), "r"(b1))

#define MMAH16816R(c, a0, a1, a2, a3, b0, b1)                                  \
    asm volatile("mma.sync.aligned.m16n8k16.row.col.f32.f16.f16.f32 "          \
        "{%0,%1,%2,%3}, {%4,%5,%6,%7}, {%8,%9}, {%0,%1,%2,%3};"                \
        : "+f"((c)[0]), "+f"((c)[1]), "+f"((c)[2]), "+f"((c)[3])               \
        : "r"(a0), "r"(a1), "r"(a2), "r"(a3), "r"(b0), "r"(b1))

#define CPASYNC16(dst, src) \
    asm volatile("cp.async.cg.shared.global [%0], [%1], 16;" :: "r"(dst), "l"(src) : "memory")
#define CPCOMMIT() asm volatile("cp.async.commit_group;" ::: "memory")
#define CPWAIT2()  asm volatile("cp.async.wait_group 2;" ::: "memory")
#define CPWAIT0()  asm volatile("cp.async.wait_group 0;" ::: "memory")

// fp16 hi/lo split store (pair)
__device__ __forceinline__ void cvtsts_h(float4 f, uint32_t dhi, uint32_t dlo) {
    __half2 h0, h1, l0, l1;
    h0.x = __float2half(f.x); h0.y = __float2half(f.y);
    h1.x = __float2half(f.z); h1.y = __float2half(f.w);
    l0.x = __float2half(f.x - __half2float(h0.x));
    l0.y = __float2half(f.y - __half2float(h0.y));
    l1.x = __float2half(f.z - __half2float(h1.x));
    l1.y = __float2half(f.w - __half2float(h1.y));
    asm volatile("st.shared.v2.b32 [%0], {%1, %2};"
                 :: "r"(dhi), "r"(*(uint32_t*)&h0), "r"(*(uint32_t*)&h1) : "memory");
    asm volatile("st.shared.v2.b32 [%0], {%1, %2};"
                 :: "r"(dlo), "r"(*(uint32_t*)&l0), "r"(*(uint32_t*)&l1) : "memory");
}
// fp16 single store
__device__ __forceinline__ void cvtsts_h1(float4 f, uint32_t dst) {
    __half2 h0, h1;
    h0.x = __float2half(f.x); h0.y = __float2half(f.y);
    h1.x = __float2half(f.z); h1.y = __float2half(f.w);
    asm volatile("st.shared.v2.b32 [%0], {%1, %2};"
                 :: "r"(dst), "r"(*(uint32_t*)&h0), "r"(*(uint32_t*)&h1) : "memory");
}

__device__ __forceinline__ void packsplit_h(float x, float y, uint32_t& hi, uint32_t& lo) {
    __half2 h, l;
    h.x = __float2half(x); h.y = __float2half(y);
    l.x = __float2half(x - __half2float(h.x));
    l.y = __float2half(y - __half2float(h.y));
    hi = *(uint32_t*)&h; lo = *(uint32_t*)&l;
}

// ================= convert kernels =================
__global__ void split_h_kernel(const float* __restrict__ src, __half* __restrict__ hi,
                               __half* __restrict__ lo, int n4) {
    int i = blockIdx.x * blockDim.x + threadIdx.x;
    if (i >= n4) return;
    float4 f = ((const float4*)src)[i];
    __half2 h0, h1, l0, l1;
    h0.x = __float2half(f.x); h0.y = __float2half(f.y);
    h1.x = __float2half(f.z); h1.y = __float2half(f.w);
    l0.x = __float2half(f.x - __half2float(h0.x));
    l0.y = __float2half(f.y - __half2float(h0.y));
    l1.x = __float2half(f.z - __half2float(h1.x));
    l1.y = __float2half(f.w - __half2float(h1.y));
    ((uint2*)hi)[i] = make_uint2(*(uint32_t*)&h0, *(uint32_t*)&h1);
    ((uint2*)lo)[i] = make_uint2(*(uint32_t*)&l0, *(uint32_t*)&l1);
}

__global__ void cvt16_all(const float* __restrict__ W0, const float* __restrict__ W1,
                          const float* __restrict__ W2, const float* __restrict__ W3,
                          __half* __restrict__ dst, int n4) {
    int i = blockIdx.x * blockDim.x + threadIdx.x;
    if (i >= n4) return;
    const float* src = (blockIdx.y == 0) ? W0 : (blockIdx.y == 1) ? W1 : (blockIdx.y == 2) ? W2 : W3;
    float4 f = ((const float4*)src)[i];
    __half2 a, b;
    a.x = __float2half(f.x); a.y = __float2half(f.y);
    b.x = __float2half(f.z); b.y = __float2half(f.w);
    ((uint2*)(dst + (size_t)blockIdx.y * HIDD * HIDD))[i] = make_uint2(*(uint32_t*)&a, *(uint32_t*)&b);
}

// ============ fp16 GEMM: C = (Ah[+Al])[M,K] * B16[N,K]^T, fused RoPE epilogue ============
// CTA 128x256, 512 threads, warp tile 32x64, 4-stage cp.async
#define QSTAGE 4
#define ATILE  10240
#define BTILE  20480
#define QBUF   (2 * ATILE + BTILE)      // 40960
#define QSMEM  (QSTAGE * QBUF)          // 163840

__global__ void __launch_bounds__(512, 1)
gemm_f16(const __half* __restrict__ Ah, const __half* __restrict__ Al,
         const __half* __restrict__ Bw,
         float* __restrict__ C0, float* __restrict__ C1, float* __restrict__ C2,
         const float* __restrict__ cosT, const float* __restrict__ sinT,
         int dorope, int lomask) {
    extern __shared__ char dsm[];
    const uint32_t sbase = smem_u32(dsm);

    const int tid  = threadIdx.x;
    const int lane = tid & 31;
    const int wid  = tid >> 5;       // 0..15
    const int wm   = wid & 3;        // 0..3 (32-row stripes)
    const int wn   = wid >> 2;       // 0..3 (64-col stripes)
    const int m0   = blockIdx.y * 128;
    const int n0   = blockIdx.x * 256;

    const int sel = n0 >> 10;
    float* C = (sel == 0) ? C0 : (sel == 1) ? C1 : C2;
    const int nc0 = n0 & 1023;
    const bool need_lo = ((lomask >> sel) & 1) != 0;

    const int rowoff = ((lane >> 3) & 1) * 8 + (lane & 7);
    const int koff   = (lane >> 4) * 8;

    uint32_t aoffb[2], boffb[4];
#pragma unroll
    for (int mf = 0; mf < 2; mf++)
        aoffb[mf] = ((uint32_t)(wm * 32 + mf * 16 + rowoff) * 40 + koff) * 2;
#pragma unroll
    for (int nb = 0; nb < 4; nb++)
        boffb[nb] = 2 * ATILE + ((uint32_t)(wn * 64 + nb * 16 + rowoff) * 40 + koff) * 2;

    const int arow = tid >> 2, acc4 = tid & 3;
    const uint32_t adst = (uint32_t)arow * 80 + acc4 * 16;

    float acc[2][8][4];
#pragma unroll
    for (int i = 0; i < 2; i++)
#pragma unroll
        for (int j = 0; j < 8; j++)
#pragma unroll
            for (int r = 0; r < 4; r++) acc[i][j][r] = 0.f;

    auto issue_stage = [&](int kc) {
        uint32_t base = sbase + (kc & (QSTAGE - 1)) * QBUF;
        int kcol = kc * 32 + acc4 * 8;
        CPASYNC16(base + adst, Ah + (size_t)(m0 + arow) * GK + kcol);
        if (need_lo)
            CPASYNC16(base + ATILE + adst, Al + (size_t)(m0 + arow) * GK + kcol);
        CPASYNC16(base + 2 * ATILE + adst, Bw + (size_t)(n0 + arow) * GK + kcol);
        CPASYNC16(base + 2 * ATILE + adst + 128 * 80,
                  Bw + (size_t)(n0 + arow + 128) * GK + kcol);
        CPCOMMIT();
    };

    issue_stage(0);
    issue_stage(1);
    issue_stage(2);

    for (int kc = 0; kc < GK / 32; kc++) {
        CPWAIT2();
        __syncthreads();
        if (kc + 3 < GK / 32) issue_stage(kc + 3);
        else CPCOMMIT();

        const uint32_t stb = sbase + (kc & (QSTAGE - 1)) * QBUF;

#pragma unroll
        for (int ks = 0; ks < 2; ks++) {
            const uint32_t ksb = stb + ks * 32;
            uint32_t af[2][4], bf[4][4];
#pragma unroll
            for (int nb = 0; nb < 4; nb++)
                LDSM_X4(bf[nb], ksb + boffb[nb]);
#pragma unroll
            for (int mf = 0; mf < 2; mf++)
                LDSM_X4(af[mf], ksb + aoffb[mf]);
#pragma unroll
            for (int mf = 0; mf < 2; mf++)
#pragma unroll
                for (int nf = 0; nf < 8; nf++)
                    MMAH16816(acc[mf][nf], af[mf], bf[nf >> 1][nf & 1], bf[nf >> 1][(nf & 1) + 2]);
            if (need_lo) {
#pragma unroll
                for (int mf = 0; mf < 2; mf++)
                    LDSM_X4(af[mf], ksb + ATILE + aoffb[mf]);
#pragma unroll
                for (int mf = 0; mf < 2; mf++)
#pragma unroll
                    for (int nf = 0; nf < 8; nf++)
                        MMAH16816(acc[mf][nf], af[mf], bf[nf >> 1][nf & 1], bf[nf >> 1][(nf & 1) + 2]);
            }
        }
    }

    // ---- fused RoPE (q,k only) ----
    if (dorope && sel < 2) {
        CPWAIT0();
        __syncthreads();
        float* csm = (float*)dsm;            // [128][64]
        float* ssm = csm + 8192;             // [128][64]
        const int s0 = m0 & (SS - 1);
        for (int i = tid; i < 2048; i += 512) {
            ((float4*)csm)[i] = ((const float4*)(cosT + (size_t)s0 * DD))[i];
            ((float4*)ssm)[i] = ((const float4*)(sinT + (size_t)s0 * DD))[i];
        }
        __syncthreads();
#pragma unroll
        for (int mf = 0; mf < 2; mf++) {
            int rl0 = wm * 32 + mf * 16 + (lane >> 2);
#pragma unroll
            for (int hf = 0; hf < 2; hf++) {
                int rl = rl0 + hf * 8;
#pragma unroll
                for (int nf = 0; nf < 4; nf++) {
#pragma unroll
                    for (int j = 0; j < 2; j++) {
                        int d0 = nf * 8 + (lane & 3) * 2 + j;
                        float c1 = csm[rl * 64 + d0],      s1 = ssm[rl * 64 + d0];
                        float c2 = csm[rl * 64 + d0 + 32], s2 = ssm[rl * 64 + d0 + 32];
                        float x1 = acc[mf][nf][hf * 2 + j];
                        float x2 = acc[mf][nf + 4][hf * 2 + j];
                        acc[mf][nf][hf * 2 + j]     = x1 * c1 - x2 * s1;
                        acc[mf][nf + 4][hf * 2 + j] = x2 * c2 + x1 * s2;
                    }
                }
            }
        }
    }

#pragma unroll
    for (int mf = 0; mf < 2; mf++) {
        int r0 = m0 + wm * 32 + mf * 16 + (lane >> 2);
#pragma unroll
        for (int nf = 0; nf < 8; nf++) {
            int c0 = nc0 + wn * 64 + nf * 8 + (lane & 3) * 2;
            *(float2*)(C + (size_t)r0 * HIDD + c0)       = make_float2(acc[mf][nf][0], acc[mf][nf][1]);
            *(float2*)(C + (size_t)(r0 + 8) * HIDD + c0) = make_float2(acc[mf][nf][2], acc[mf][nf][3]);
        }
    }
}

// ================= per-chunk RFA summaries ((b,s,h,d)) =================
__global__ void __launch_bounds__(128) rfa_kernel(const float* __restrict__ k,
                                                  const float* __restrict__ v,
                                                  const float* __restrict__ mu,
                                                  const float* __restrict__ phi,
                                                  float* __restrict__ rk,
                                                  float* __restrict__ rv) {
    int bh = blockIdx.x / NCC;
    int c  = blockIdx.x % NCC;
    int b  = bh / NHH, h = bh % NHH;
    int j  = threadIdx.x;
    __shared__ float sb[CHUNKK], sg[CHUNKK];
    const float* kbase = k + (((size_t)b * SS + c * CHUNKK) * NHH + h) * DD;
    const float* vbase = v + (((size_t)b * SS + c * CHUNKK) * NHH + h) * DD;
    const float* kr = kbase + (size_t)j * HIDD;
    float dm = 0.f, dp = 0.f, nn = 0.f;
#pragma unroll
    for (int d = 0; d < DD; d++) {
        float kv = kr[d];
        dm += kv * mu[h * DD + d];
        dp += kv * phi[h * DD + d];
        nn += kv * kv;
    }
    float halfn = 0.5f * SCALEF * nn;
    sb[j] = SCALEF * dm - halfn;
    sg[j] = SCALEF * dp - halfn;
    __syncthreads();
    float mb = -1e30f, mg = -1e30f;
    for (int t = 0; t < CHUNKK; t++) { mb = fmaxf(mb, sb[t]); mg = fmaxf(mg, sg[t]); }
    float eb = expf(sb[j] - mb), eg = expf(sg[j] - mg);
    __syncthreads();
    sb[j] = eb; sg[j] = eg;
    __syncthreads();
    float zb = 0.f, zg = 0.f;
    for (int t = 0; t < CHUNKK; t++) { zb += sb[t]; zg += sg[t]; }
    float invb = 1.f / zb, invg = 1.f / zg;
    if (j < DD) {
        int d = j;
        float acc = 0.f;
        for (int t = 0; t < CHUNKK; t++) acc += sb[t] * kbase[(size_t)t * HIDD + d];
        rk[((size_t)bh * NCC + c) * DD + d] = acc * invb;
    } else {
        int d = j - DD;
        float acc = 0.f;
        for (int t = 0; t < CHUNKK; t++) acc += sg[t] * vbase[(size_t)t * HIDD + d];
        rv[((size_t)bh * NCC + c) * DD + d] = acc * invg;
    }
}

// ================= MMA flash attention (fp16 2-pass QK, 2-pass PV) =================
// smem: Qh[128][72], Ql[128][72], K[64][72], V[64][72] (fp16)
#define AQ_H 0
#define AQ_L 18432
#define AK_S 36864
#define AV_S 46080
#define AT_SMEM 55296

// fp16 hi/lo split fill
__device__ __forceinline__ void fill_split_h(const float* __restrict__ src, int rstride,
                                             int rows, int rlimit,
                                             uint32_t dhi, uint32_t dlo, int tid, float scale) {
    const int col4 = tid & 15;
    const int r0   = tid >> 4;
    for (int r = r0; r < rows; r += 8) {
        float4 f;
        if (r < rlimit) {
            f = *(const float4*)(src + (size_t)r * rstride + col4 * 4);
            f.x *= scale; f.y *= scale; f.z *= scale; f.w *= scale;
        } else {
            f = make_float4(0.f, 0.f, 0.f, 0.f);
        }
        uint32_t off = (uint32_t)r * 144 + col4 * 8;
        cvtsts_h(f, dhi + off, dlo + off);
    }
}
// fp16 single fill
__device__ __forceinline__ void fill_h(const float* __restrict__ src, int rstride,
                                       int rows, int rlimit, uint32_t dst, int tid) {
    const int col4 = tid & 15;
    const int r0   = tid >> 4;
    for (int r = r0; r < rows; r += 8) {
        float4 f;
        if (r < rlimit) {
            f = *(const float4*)(src + (size_t)r * rstride + col4 * 4);
        } else {
            f = make_float4(0.f, 0.f, 0.f, 0.f);
        }
        cvtsts_h1(f, dst + (uint32_t)r * 144 + col4 * 8);
    }
}

__global__ void __launch_bounds__(128, 2)
attn_mma(const float* __restrict__ q, const float* __restrict__ k,
         const float* __restrict__ v, const float* __restrict__ rk,
         const float* __restrict__ rv, __half* __restrict__ oh) {
    extern __shared__ char dsm[];
    const uint32_t sb = smem_u32(dsm);

    const int qt  = blockIdx.x;
    const int w   = blockIdx.y;
    const int bh  = blockIdx.z;
    const int b   = bh >> 4, h = bh & 15;
    const int tid = threadIdx.x, lane = tid & 31, wq = tid >> 5;

    const int rowoff = ((lane >> 3) & 1) * 8 + (lane & 7);
    const int koff   = (lane >> 4) * 8;
    const int vrow   = lane & 15;
    const int vnadd  = (lane >> 4) * 8;

    const float* qg = q + (((size_t)b * SS + w * WINN + qt * 128) * NHH + h) * DD;
    fill_split_h(qg, HIDD, 128, 128, sb + AQ_H, sb + AQ_L, tid, SCALEF);

    float OA[2][8][4];
#pragma unroll
    for (int mf = 0; mf < 2; mf++)
#pragma unroll
        for (int nf = 0; nf < 8; nf++)
#pragma unroll
            for (int r = 0; r < 4; r++) OA[mf][nf][r] = 0.f;
    float mrow[2][2] = {{-1e30f, -1e30f}, {-1e30f, -1e30f}};
    float lrow[2][2] = {{0.f, 0.f}, {0.f, 0.f}};

    const float* kwin = k + (((size_t)b * SS + w * WINN) * NHH + h) * DD;
    const float* vwin = v + (((size_t)b * SS + w * WINN) * NHH + h) * DD;
    const float* rkb  = rk + (size_t)bh * NCC * DD;
    const float* rvb  = rv + (size_t)bh * NCC * DD;

    const int nwt    = 2 * qt + 2;
    const int nch    = 4 * w;
    const int ntile  = nwt + (nch > 0 ? 1 : 0);

    for (int t = 0; t < ntile; t++) {
        const bool ischunk = (t == nwt);
        const int kt0 = t * 64;
        __syncthreads();
        if (!ischunk) {
            fill_h(kwin + (size_t)kt0 * HIDD, HIDD, 64, 64, sb + AK_S, tid);
            fill_h(vwin + (size_t)kt0 * HIDD, HIDD, 64, 64, sb + AV_S, tid);
        } else {
            fill_h(rkb, DD, 64, nch, sb + AK_S, tid);
            fill_h(rvb, DD, 64, nch, sb + AV_S, tid);
        }
        __syncthreads();

        float SA[2][8][4];
#pragma unroll
        for (int mf = 0; mf < 2; mf++)
#pragma unroll
            for (int nf = 0; nf < 8; nf++)
#pragma unroll
                for (int r = 0; r < 4; r++) SA[mf][nf][r] = 0.f;

        // ---- S = (Qh + Ql) * K^T : 2 fp16 passes ----
#pragma unroll
        for (int pass = 0; pass < 2; pass++) {
            const uint32_t Ab = sb + ((pass == 1) ? AQ_L : AQ_H);
#pragma unroll
            for (int ks = 0; ks < 4; ks++) {
                uint32_t af[2][4], bf[4][4];
#pragma unroll
                for (int mf = 0; mf < 2; mf++)
                    LDSM_X4(af[mf], Ab + ((uint32_t)(wq * 32 + mf * 16 + rowoff) * 72 + ks * 16 + koff) * 2);
#pragma unroll
                for (int nb = 0; nb < 4; nb++)
                    LDSM_X4(bf[nb], sb + AK_S + ((uint32_t)(nb * 16 + rowoff) * 72 + ks * 16 + koff) * 2);
#pragma unroll
                for (int mf = 0; mf < 2; mf++)
#pragma unroll
                    for (int nf = 0; nf < 8; nf++)
                        MMAH16816(SA[mf][nf], af[mf], bf[nf >> 1][nf & 1], bf[nf >> 1][(nf & 1) + 2]);
            }
        }

        if (ischunk) {
#pragma unroll
            for (int mf = 0; mf < 2; mf++)
#pragma unroll
                for (int nf = 0; nf < 8; nf++) {
                    int colb = nf * 8 + (lane & 3) * 2;
                    if (colb     >= nch) { SA[mf][nf][0] = -1e30f; SA[mf][nf][2] = -1e30f; }
                    if (colb + 1 >= nch) { SA[mf][nf][1] = -1e30f; SA[mf][nf][3] = -1e30f; }
                }
        } else if (t >= 2 * qt) {
#pragma unroll
            for (int mf = 0; mf < 2; mf++)
#pragma unroll
                for (int nf = 0; nf < 8; nf++) {
                    int colb = kt0 + nf * 8 + (lane & 3) * 2;
#pragma unroll
                    for (int hf = 0; hf < 2; hf++) {
                        int rowq = qt * 128 + wq * 32 + mf * 16 + (lane >> 2) + hf * 8;
                        if (colb     > rowq) SA[mf][nf][hf * 2]     = -1e30f;
                        if (colb + 1 > rowq) SA[mf][nf][hf * 2 + 1] = -1e30f;
                    }
                }
        }

#pragma unroll
        for (int mf = 0; mf < 2; mf++)
#pragma unroll
            for (int hf = 0; hf < 2; hf++) {
                float tm = -1e30f;
#pragma unroll
                for (int nf = 0; nf < 8; nf++) {
                    tm = fmaxf(tm, SA[mf][nf][hf * 2]);
                    tm = fmaxf(tm, SA[mf][nf][hf * 2 + 1]);
                }
                tm = fmaxf(tm, __shfl_xor_sync(0xFFFFFFFF, tm, 1));
                tm = fmaxf(tm, __shfl_xor_sync(0xFFFFFFFF, tm, 2));
                float mold = mrow[mf][hf];
                float mnew = fmaxf(mold, tm);
                float f = __expf(mold - mnew);
                float rs = 0.f;
#pragma unroll
                for (int nf = 0; nf < 8; nf++) {
                    float p0 = __expf(SA[mf][nf][hf * 2]     - mnew);
                    float p1 = __expf(SA[mf][nf][hf * 2 + 1] - mnew);
                    SA[mf][nf][hf * 2]     = p0;
                    SA[mf][nf][hf * 2 + 1] = p1;
                    rs += p0 + p1;
                }
                rs += __shfl_xor_sync(0xFFFFFFFF, rs, 1);
                rs += __shfl_xor_sync(0xFFFFFFFF, rs, 2);
                lrow[mf][hf] = lrow[mf][hf] * f + rs;
                mrow[mf][hf] = mnew;
#pragma unroll
                for (int nf = 0; nf < 8; nf++) {
                    OA[mf][nf][hf * 2]     *= f;
                    OA[mf][nf][hf * 2 + 1] *= f;
                }
            }

        // ---- O += (Ph + Pl) * V : 2 fp16 passes, single V ----
#pragma unroll
        for (int kc = 0; kc < 4; kc++) {
            uint32_t ah[2][4], al[2][4];
#pragma unroll
            for (int mf = 0; mf < 2; mf++) {
                packsplit_h(SA[mf][2 * kc][0],     SA[mf][2 * kc][1],     ah[mf][0], al[mf][0]);
                packsplit_h(SA[mf][2 * kc][2],     SA[mf][2 * kc][3],     ah[mf][1], al[mf][1]);
                packsplit_h(SA[mf][2 * kc + 1][0], SA[mf][2 * kc + 1][1], ah[mf][2], al[mf][2]);
                packsplit_h(SA[mf][2 * kc + 1][2], SA[mf][2 * kc + 1][3], ah[mf][3], al[mf][3]);
            }
#pragma unroll
            for (int nq = 0; nq < 4; nq++) {
                uint32_t off = ((uint32_t)(kc * 16 + vrow) * 72 + nq * 16 + vnadd) * 2;
                uint32_t bv[4];
                LDSM_X4T(bv, sb + AV_S + off);
#pragma unroll
                for (int mf = 0; mf < 2; mf++) {
                    MMAH16816R(OA[mf][2 * nq],     ah[mf][0], ah[mf][1], ah[mf][2], ah[mf][3], bv[0], bv[1]);
                    MMAH16816R(OA[mf][2 * nq + 1], ah[mf][0], ah[mf][1], ah[mf][2], ah[mf][3], bv[2], bv[3]);
                    MMAH16816R(OA[mf][2 * nq],     al[mf][0], al[mf][1], al[mf][2], al[mf][3], bv[0], bv[1]);
                    MMAH16816R(OA[mf][2 * nq + 1], al[mf][0], al[mf][1], al[mf][2], al[mf][3], bv[2], bv[3]);
                }
            }
        }
    }

    // ---- epilogue: single fp16 for O-projection ----
#pragma unroll
    for (int mf = 0; mf < 2; mf++)
#pragma unroll
        for (int hf = 0; hf < 2; hf++) {
            float inv = 1.f / lrow[mf][hf];
            int row = w * WINN + qt * 128 + wq * 32 + mf * 16 + (lane >> 2) + hf * 8;
            size_t base = ((size_t)b * SS + row) * HIDD + h * DD;
#pragma unroll
            for (int nf = 0; nf < 8; nf++) {
                int d = nf * 8 + (lane & 3) * 2;
                __half2 hv;
                hv.x = __float2half(OA[mf][nf][hf * 2] * inv);
                hv.y = __float2half(OA[mf][nf][hf * 2 + 1] * inv);
                *(uint32_t*)(oh + base + d) = *(uint32_t*)&hv;
            }
        }
}

// ---------------- launch ----------------
extern "C" void kernel_launch(void* const* d_in, const int* in_sizes, int n_in,
                              void* d_out, int out_size) {
    const float* hidden = (const float*)d_in[0];
    const float* Wq     = (const float*)d_in[1];
    const float* Wk     = (const float*)d_in[2];
    const float* Wv     = (const float*)d_in[3];
    const float* Wo     = (const float*)d_in[4];
    const float* mu     = (const float*)d_in[5];
    const float* phi    = (const float*)d_in[6];
    const float* cosT   = (const float*)d_in[7];
    const float* sinT   = (const float*)d_in[8];

    float *qb, *kb, *vb, *rkb, *rvb;
    __half *hidh, *hidl, *aoh, *w16;
    cudaGetSymbolAddress((void**)&qb,   g_q);
    cudaGetSymbolAddress((void**)&kb,   g_k);
    cudaGetSymbolAddress((void**)&vb,   g_v);
    cudaGetSymbolAddress((void**)&rkb,  g_rfak);
    cudaGetSymbolAddress((void**)&rvb,  g_rfav);
    cudaGetSymbolAddress((void**)&hidh, g_hid_h);
    cudaGetSymbolAddress((void**)&hidl, g_hid_l);
    cudaGetSymbolAddress((void**)&aoh,  g_ao_h);
    cudaGetSymbolAddress((void**)&w16,  g_w16);

    static bool attr_set = false;
    if (!attr_set) {
        cudaFuncSetAttribute((const void*)gemm_f16,
                             cudaFuncAttributeMaxDynamicSharedMemorySize, QSMEM);
        cudaFuncSetAttribute((const void*)attn_mma,
                             cudaFuncAttributeMaxDynamicSharedMemorySize, AT_SMEM);
        attr_set = true;
    }

    const int WSZ = HIDD * HIDD;
    const int HN4 = MTOK * HIDD / 4;
    const int WN4 = WSZ / 4;

    // launch 0: weight converts; 1-2: hidden split halves; 3: big GEMM (ncu lands here)
    cvt16_all<<<dim3((WN4 + 255) / 256, 4), 256>>>(Wq, Wk, Wv, Wo, w16, WN4);
    split_h_kernel<<<(HN4 / 2 + 255) / 256, 256>>>(hidden, hidh, hidl, HN4 / 2);
    split_h_kernel<<<(HN4 / 2 + 255) / 256, 256>>>(hidden + MTOK * HIDD / 2,
                                                   hidh + MTOK * HIDD / 2,
                                                   hidl + MTOK * HIDD / 2, HN4 / 2);

    // fused QKV GEMM with RoPE epilogue (k 2-pass; q,v 1-pass)
    gemm_f16<<<dim3(3072 / 256, MTOK / 128), 512, QSMEM>>>(hidh, hidl, w16, qb, kb, vb,
                                                           cosT, sinT, 1, 0b010);

    rfa_kernel<<<BB * NHH * NCC, 128>>>(kb, vb, mu, phi, rkb, rvb);

    attn_mma<<<dim3(4, NWW, BB * NHH), 128, AT_SMEM>>>(qb, kb, vb, rkb, rvb, aoh);

    // O projection (1-pass fp16)
    gemm_f16<<<dim3(1024 / 256, MTOK / 128), 512, QSMEM>>>(aoh, aoh, w16 + 3 * WSZ,
                                                           (float*)d_out, (float*)d_out, (float*)d_out,
                                                           cosT, sinT, 0, 0);
}

// round 14
// speedup vs baseline: 2.2694x; 1.1681x over previous
#include <cuda_runtime.h>
#include <cuda_bf16.h>
#include <cuda_fp16.h>
#include <cstdint>
#include <math.h>

// ---------------- problem constants ----------------
#define BB     4
#define SS     4096
#define HIDD   1024
#define NHH    16
#define DD     64
#define WINN   512
#define CHUNKK 128
#define NWW    8
#define NCC    32
#define SCALEF 0.125f
#define MTOK   (BB*SS)   // 16384
#define GK     1024

// ---------------- scratch (device globals) ----------------
__device__ float g_q[MTOK*HIDD];
__device__ float g_k[MTOK*HIDD];
__device__ float g_v[MTOK*HIDD];
__device__ float g_rfak[BB*NHH*NCC*DD];
__device__ float g_rfav[BB*NHH*NCC*DD];
__device__ __half g_hid_h[MTOK*HIDD];
__device__ __half g_ao_h[MTOK*HIDD];
__device__ __half g_w16[4*HIDD*HIDD];

// ================= helpers =================
__device__ __forceinline__ uint32_t smem_u32(const void* p) {
    uint32_t a;
    asm("{ .reg .u64 t; cvta.to.shared.u64 t, %1; cvt.u32.u64 %0, t; }" : "=r"(a) : "l"(p));
    return a;
}

#define LDSM_X4(r, a)                                                          \
    asm volatile("ldmatrix.sync.aligned.m8n8.x4.shared.b16 {%0,%1,%2,%3}, [%4];" \
        : "=r"((r)[0]), "=r"((r)[1]), "=r"((r)[2]), "=r"((r)[3]) : "r"(a))

#define LDSM_X4T(r, a)                                                         \
    asm volatile("ldmatrix.sync.aligned.m8n8.x4.trans.shared.b16 {%0,%1,%2,%3}, [%4];" \
        : "=r"((r)[0]), "=r"((r)[1]), "=r"((r)[2]), "=r"((r)[3]) : "r"(a))

#define MMAH16816(c, a, b0, b1)                                                \
    asm volatile("mma.sync.aligned.m16n8k16.row.col.f32.f16.f16.f32 "          \
        "{%0,%1,%2,%3}, {%4,%5,%6,%7}, {%8,%9}, {%0,%1,%2,%3};"                \
        : "+f"((c)[0]), "+f"((c)[1]), "+f"((c)[2]), "+f"((c)[3])               \
        : "r"((a)[0]), "r"((a)[1]), "r"((a)[2]), "r"((a)[3]), "r"(b0), "r"(b1))

#define MMAH16816R(c, a0, a1, a2, a3, b0, b1)                                  \
    asm volatile("mma.sync.aligned.m16n8k16.row.col.f32.f16.f16.f32 "          \
        "{%0,%1,%2,%3}, {%4,%5,%6,%7}, {%8,%9}, {%0,%1,%2,%3};"                \
        : "+f"((c)[0]), "+f"((c)[1]), "+f"((c)[2]), "+f"((c)[3])               \
        : "r"(a0), "r"(a1), "r"(a2), "r"(a3), "r"(b0), "r"(b1))

#define CPASYNC16(dst, src) \
    asm volatile("cp.async.cg.shared.global [%0], [%1], 16;" :: "r"(dst), "l"(src) : "memory")
#define CPCOMMIT() asm volatile("cp.async.commit_group;" ::: "memory")
#define CPWAIT2()  asm volatile("cp.async.wait_group 2;" ::: "memory")
#define CPWAIT0()  asm volatile("cp.async.wait_group 0;" ::: "memory")

// fp16 hi/lo split store (pair)
__device__ __forceinline__ void cvtsts_h(float4 f, uint32_t dhi, uint32_t dlo) {
    __half2 h0, h1, l0, l1;
    h0.x = __float2half(f.x); h0.y = __float2half(f.y);
    h1.x = __float2half(f.z); h1.y = __float2half(f.w);
    l0.x = __float2half(f.x - __half2float(h0.x));
    l0.y = __float2half(f.y - __half2float(h0.y));
    l1.x = __float2half(f.z - __half2float(h1.x));
    l1.y = __float2half(f.w - __half2float(h1.y));
    asm volatile("st.shared.v2.b32 [%0], {%1, %2};"
                 :: "r"(dhi), "r"(*(uint32_t*)&h0), "r"(*(uint32_t*)&h1) : "memory");
    asm volatile("st.shared.v2.b32 [%0], {%1, %2};"
                 :: "r"(dlo), "r"(*(uint32_t*)&l0), "r"(*(uint32_t*)&l1) : "memory");
}
// fp16 single store
__device__ __forceinline__ void cvtsts_h1(float4 f, uint32_t dst) {
    __half2 h0, h1;
    h0.x = __float2half(f.x); h0.y = __float2half(f.y);
    h1.x = __float2half(f.z); h1.y = __float2half(f.w);
    asm volatile("st.shared.v2.b32 [%0], {%1, %2};"
                 :: "r"(dst), "r"(*(uint32_t*)&h0), "r"(*(uint32_t*)&h1) : "memory");
}

__device__ __forceinline__ uint32_t packh2(float x, float y) {
    __half2 h;
    h.x = __float2half(x); h.y = __float2half(y);
    return *(uint32_t*)&h;
}

// ================= convert kernels =================
__global__ void cvt16_one(const float* __restrict__ src, __half* __restrict__ dst, int n4) {
    int i = blockIdx.x * blockDim.x + threadIdx.x;
    if (i >= n4) return;
    float4 f = ((const float4*)src)[i];
    __half2 a, b;
    a.x = __float2half(f.x); a.y = __float2half(f.y);
    b.x = __float2half(f.z); b.y = __float2half(f.w);
    ((uint2*)dst)[i] = make_uint2(*(uint32_t*)&a, *(uint32_t*)&b);
}

__global__ void cvt16_all(const float* __restrict__ W0, const float* __restrict__ W1,
                          const float* __restrict__ W2, const float* __restrict__ W3,
                          __half* __restrict__ dst, int n4) {
    int i = blockIdx.x * blockDim.x + threadIdx.x;
    if (i >= n4) return;
    const float* src = (blockIdx.y == 0) ? W0 : (blockIdx.y == 1) ? W1 : (blockIdx.y == 2) ? W2 : W3;
    float4 f = ((const float4*)src)[i];
    __half2 a, b;
    a.x = __float2half(f.x); a.y = __float2half(f.y);
    b.x = __float2half(f.z); b.y = __float2half(f.w);
    ((uint2*)(dst + (size_t)blockIdx.y * HIDD * HIDD))[i] = make_uint2(*(uint32_t*)&a, *(uint32_t*)&b);
}

// ============ fp16 GEMM: C = A[M,K] * B16[N,K]^T, fused RoPE epilogue ============
// CTA 128x256, 512 threads, warp tile 32x64, 4-stage cp.async
// stage: A[128][40] | B[256][40]  (fp16, 80B padded rows)
#define QSTAGE 4
#define ATILE  10240
#define BTILE  20480
#define QBUF   (ATILE + BTILE)          // 30720
#define QSMEM  (QSTAGE * QBUF)          // 122880

__global__ void __launch_bounds__(512, 1)
gemm_f16(const __half* __restrict__ Ah,
         const __half* __restrict__ Bw,
         float* __restrict__ C0, float* __restrict__ C1, float* __restrict__ C2,
         const float* __restrict__ cosT, const float* __restrict__ sinT,
         int dorope) {
    extern __shared__ char dsm[];
    const uint32_t sbase = smem_u32(dsm);

    const int tid  = threadIdx.x;
    const int lane = tid & 31;
    const int wid  = tid >> 5;       // 0..15
    const int wm   = wid & 3;        // 0..3 (32-row stripes)
    const int wn   = wid >> 2;       // 0..3 (64-col stripes)
    const int m0   = blockIdx.y * 128;
    const int n0   = blockIdx.x * 256;

    const int sel = n0 >> 10;
    float* C = (sel == 0) ? C0 : (sel == 1) ? C1 : C2;
    const int nc0 = n0 & 1023;

    const int rowoff = ((lane >> 3) & 1) * 8 + (lane & 7);
    const int koff   = (lane >> 4) * 8;

    uint32_t aoffb[2], boffb[4];
#pragma unroll
    for (int mf = 0; mf < 2; mf++)
        aoffb[mf] = ((uint32_t)(wm * 32 + mf * 16 + rowoff) * 40 + koff) * 2;
#pragma unroll
    for (int nb = 0; nb < 4; nb++)
        boffb[nb] = ATILE + ((uint32_t)(wn * 64 + nb * 16 + rowoff) * 40 + koff) * 2;

    const int arow = tid >> 2, acc4 = tid & 3;
    const uint32_t adst = (uint32_t)arow * 80 + acc4 * 16;

    float acc[2][8][4];
#pragma unroll
    for (int i = 0; i < 2; i++)
#pragma unroll
        for (int j = 0; j < 8; j++)
#pragma unroll
            for (int r = 0; r < 4; r++) acc[i][j][r] = 0.f;

    auto issue_stage = [&](int kc) {
        uint32_t base = sbase + (kc & (QSTAGE - 1)) * QBUF;
        int kcol = kc * 32 + acc4 * 8;
        CPASYNC16(base + adst, Ah + (size_t)(m0 + arow) * GK + kcol);
        CPASYNC16(base + ATILE + adst, Bw + (size_t)(n0 + arow) * GK + kcol);
        CPASYNC16(base + ATILE + adst + 128 * 80,
                  Bw + (size_t)(n0 + arow + 128) * GK + kcol);
        CPCOMMIT();
    };

    issue_stage(0);
    issue_stage(1);
    issue_stage(2);

    for (int kc = 0; kc < GK / 32; kc++) {
        CPWAIT2();
        __syncthreads();
        if (kc + 3 < GK / 32) issue_stage(kc + 3);
        else CPCOMMIT();

        const uint32_t stb = sbase + (kc & (QSTAGE - 1)) * QBUF;

#pragma unroll
        for (int ks = 0; ks < 2; ks++) {
            const uint32_t ksb = stb + ks * 32;
            uint32_t af[2][4], bf[4][4];
#pragma unroll
            for (int nb = 0; nb < 4; nb++)
                LDSM_X4(bf[nb], ksb + boffb[nb]);
#pragma unroll
            for (int mf = 0; mf < 2; mf++)
                LDSM_X4(af[mf], ksb + aoffb[mf]);
#pragma unroll
            for (int mf = 0; mf < 2; mf++)
#pragma unroll
                for (int nf = 0; nf < 8; nf++)
                    MMAH16816(acc[mf][nf], af[mf], bf[nf >> 1][nf & 1], bf[nf >> 1][(nf & 1) + 2]);
        }
    }

    // ---- fused RoPE (q,k only) ----
    if (dorope && sel < 2) {
        CPWAIT0();
        __syncthreads();
        float* csm = (float*)dsm;            // [128][64]
        float* ssm = csm + 8192;             // [128][64]
        const int s0 = m0 & (SS - 1);
        for (int i = tid; i < 2048; i += 512) {
            ((float4*)csm)[i] = ((const float4*)(cosT + (size_t)s0 * DD))[i];
            ((float4*)ssm)[i] = ((const float4*)(sinT + (size_t)s0 * DD))[i];
        }
        __syncthreads();
#pragma unroll
        for (int mf = 0; mf < 2; mf++) {
            int rl0 = wm * 32 + mf * 16 + (lane >> 2);
#pragma unroll
            for (int hf = 0; hf < 2; hf++) {
                int rl = rl0 + hf * 8;
#pragma unroll
                for (int nf = 0; nf < 4; nf++) {
#pragma unroll
                    for (int j = 0; j < 2; j++) {
                        int d0 = nf * 8 + (lane & 3) * 2 + j;
                        float c1 = csm[rl * 64 + d0],      s1 = ssm[rl * 64 + d0];
                        float c2 = csm[rl * 64 + d0 + 32], s2 = ssm[rl * 64 + d0 + 32];
                        float x1 = acc[mf][nf][hf * 2 + j];
                        float x2 = acc[mf][nf + 4][hf * 2 + j];
                        acc[mf][nf][hf * 2 + j]     = x1 * c1 - x2 * s1;
                        acc[mf][nf + 4][hf * 2 + j] = x2 * c2 + x1 * s2;
                    }
                }
            }
        }
    }

#pragma unroll
    for (int mf = 0; mf < 2; mf++) {
        int r0 = m0 + wm * 32 + mf * 16 + (lane >> 2);
#pragma unroll
        for (int nf = 0; nf < 8; nf++) {
            int c0 = nc0 + wn * 64 + nf * 8 + (lane & 3) * 2;
            *(float2*)(C + (size_t)r0 * HIDD + c0)       = make_float2(acc[mf][nf][0], acc[mf][nf][1]);
            *(float2*)(C + (size_t)(r0 + 8) * HIDD + c0) = make_float2(acc[mf][nf][2], acc[mf][nf][3]);
        }
    }
}

// ================= per-chunk RFA summaries ((b,s,h,d)) =================
__global__ void __launch_bounds__(128) rfa_kernel(const float* __restrict__ k,
                                                  const float* __restrict__ v,
                                                  const float* __restrict__ mu,
                                                  const float* __restrict__ phi,
                                                  float* __restrict__ rk,
                                                  float* __restrict__ rv) {
    int bh = blockIdx.x / NCC;
    int c  = blockIdx.x % NCC;
    int b  = bh / NHH, h = bh % NHH;
    int j  = threadIdx.x;
    __shared__ float sb[CHUNKK], sg[CHUNKK];
    const float* kbase = k + (((size_t)b * SS + c * CHUNKK) * NHH + h) * DD;
    const float* vbase = v + (((size_t)b * SS + c * CHUNKK) * NHH + h) * DD;
    const float* kr = kbase + (size_t)j * HIDD;
    float dm = 0.f, dp = 0.f, nn = 0.f;
#pragma unroll
    for (int d = 0; d < DD; d++) {
        float kv = kr[d];
        dm += kv * mu[h * DD + d];
        dp += kv * phi[h * DD + d];
        nn += kv * kv;
    }
    float halfn = 0.5f * SCALEF * nn;
    sb[j] = SCALEF * dm - halfn;
    sg[j] = SCALEF * dp - halfn;
    __syncthreads();
    float mb = -1e30f, mg = -1e30f;
    for (int t = 0; t < CHUNKK; t++) { mb = fmaxf(mb, sb[t]); mg = fmaxf(mg, sg[t]); }
    float eb = expf(sb[j] - mb), eg = expf(sg[j] - mg);
    __syncthreads();
    sb[j] = eb; sg[j] = eg;
    __syncthreads();
    float zb = 0.f, zg = 0.f;
    for (int t = 0; t < CHUNKK; t++) { zb += sb[t]; zg += sg[t]; }
    float invb = 1.f / zb, invg = 1.f / zg;
    if (j < DD) {
        int d = j;
        float acc = 0.f;
        for (int t = 0; t < CHUNKK; t++) acc += sb[t] * kbase[(size_t)t * HIDD + d];
        rk[((size_t)bh * NCC + c) * DD + d] = acc * invb;
    } else {
        int d = j - DD;
        float acc = 0.f;
        for (int t = 0; t < CHUNKK; t++) acc += sg[t] * vbase[(size_t)t * HIDD + d];
        rv[((size_t)bh * NCC + c) * DD + d] = acc * invg;
    }
}

// ================= MMA flash attention (fp16: 2-pass QK, 1-pass PV) =================
// smem: Qh[128][72], Ql[128][72], K[64][72], V[64][72] (fp16)
#define AQ_H 0
#define AQ_L 18432
#define AK_S 36864
#define AV_S 46080
#define AT_SMEM 55296

__device__ __forceinline__ void fill_split_h(const float* __restrict__ src, int rstride,
                                             int rows, int rlimit,
                                             uint32_t dhi, uint32_t dlo, int tid, float scale) {
    const int col4 = tid & 15;
    const int r0   = tid >> 4;
    for (int r = r0; r < rows; r += 8) {
        float4 f;
        if (r < rlimit) {
            f = *(const float4*)(src + (size_t)r * rstride + col4 * 4);
            f.x *= scale; f.y *= scale; f.z *= scale; f.w *= scale;
        } else {
            f = make_float4(0.f, 0.f, 0.f, 0.f);
        }
        uint32_t off = (uint32_t)r * 144 + col4 * 8;
        cvtsts_h(f, dhi + off, dlo + off);
    }
}
__device__ __forceinline__ void fill_h(const float* __restrict__ src, int rstride,
                                       int rows, int rlimit, uint32_t dst, int tid) {
    const int col4 = tid & 15;
    const int r0   = tid >> 4;
    for (int r = r0; r < rows; r += 8) {
        float4 f;
        if (r < rlimit) {
            f = *(const float4*)(src + (size_t)r * rstride + col4 * 4);
        } else {
            f = make_float4(0.f, 0.f, 0.f, 0.f);
        }
        cvtsts_h1(f, dst + (uint32_t)r * 144 + col4 * 8);
    }
}

__global__ void __launch_bounds__(128, 2)
attn_mma(const float* __restrict__ q, const float* __restrict__ k,
         const float* __restrict__ v, const float* __restrict__ rk,
         const float* __restrict__ rv, __half* __restrict__ oh) {
    extern __shared__ char dsm[];
    const uint32_t sb = smem_u32(dsm);

    const int qt  = blockIdx.x;
    const int w   = blockIdx.y;
    const int bh  = blockIdx.z;
    const int b   = bh >> 4, h = bh & 15;
    const int tid = threadIdx.x, lane = tid & 31, wq = tid >> 5;

    const int rowoff = ((lane >> 3) & 1) * 8 + (lane & 7);
    const int koff   = (lane >> 4) * 8;
    const int vrow   = lane & 15;
    const int vnadd  = (lane >> 4) * 8;

    const float* qg = q + (((size_t)b * SS + w * WINN + qt * 128) * NHH + h) * DD;
    fill_split_h(qg, HIDD, 128, 128, sb + AQ_H, sb + AQ_L, tid, SCALEF);

    float OA[2][8][4];
#pragma unroll
    for (int mf = 0; mf < 2; mf++)
#pragma unroll
        for (int nf = 0; nf < 8; nf++)
#pragma unroll
            for (int r = 0; r < 4; r++) OA[mf][nf][r] = 0.f;
    float mrow[2][2] = {{-1e30f, -1e30f}, {-1e30f, -1e30f}};
    float lrow[2][2] = {{0.f, 0.f}, {0.f, 0.f}};

    const float* kwin = k + (((size_t)b * SS + w * WINN) * NHH + h) * DD;
    const float* vwin = v + (((size_t)b * SS + w * WINN) * NHH + h) * DD;
    const float* rkb  = rk + (size_t)bh * NCC * DD;
    const float* rvb  = rv + (size_t)bh * NCC * DD;

    const int nwt    = 2 * qt + 2;
    const int nch    = 4 * w;
    const int ntile  = nwt + (nch > 0 ? 1 : 0);

    for (int t = 0; t < ntile; t++) {
        const bool ischunk = (t == nwt);
        const int kt0 = t * 64;
        __syncthreads();
        if (!ischunk) {
            fill_h(kwin + (size_t)kt0 * HIDD, HIDD, 64, 64, sb + AK_S, tid);
            fill_h(vwin + (size_t)kt0 * HIDD, HIDD, 64, 64, sb + AV_S, tid);
        } else {
            fill_h(rkb, DD, 64, nch, sb + AK_S, tid);
            fill_h(rvb, DD, 64, nch, sb + AV_S, tid);
        }
        __syncthreads();

        float SA[2][8][4];
#pragma unroll
        for (int mf = 0; mf < 2; mf++)
#pragma unroll
            for (int nf = 0; nf < 8; nf++)
#pragma unroll
                for (int r = 0; r < 4; r++) SA[mf][nf][r] = 0.f;

        // ---- S = (Qh + Ql) * K^T : 2 fp16 passes ----
#pragma unroll
        for (int pass = 0; pass < 2; pass++) {
            const uint32_t Ab = sb + ((pass == 1) ? AQ_L : AQ_H);
#pragma unroll
            for (int ks = 0; ks < 4; ks++) {
                uint32_t af[2][4], bf[4][4];
#pragma unroll
                for (int mf = 0; mf < 2; mf++)
                    LDSM_X4(af[mf], Ab + ((uint32_t)(wq * 32 + mf * 16 + rowoff) * 72 + ks * 16 + koff) * 2);
#pragma unroll
                for (int nb = 0; nb < 4; nb++)
                    LDSM_X4(bf[nb], sb + AK_S + ((uint32_t)(nb * 16 + rowoff) * 72 + ks * 16 + koff) * 2);
#pragma unroll
                for (int mf = 0; mf < 2; mf++)
#pragma unroll
                    for (int nf = 0; nf < 8; nf++)
                        MMAH16816(SA[mf][nf], af[mf], bf[nf >> 1][nf & 1], bf[nf >> 1][(nf & 1) + 2]);
            }
        }

        if (ischunk) {
#pragma unroll
            for (int mf = 0; mf < 2; mf++)
#pragma unroll
                for (int nf = 0; nf < 8; nf++) {
                    int colb = nf * 8 + (lane & 3) * 2;
                    if (colb     >= nch) { SA[mf][nf][0] = -1e30f; SA[mf][nf][2] = -1e30f; }
                    if (colb + 1 >= nch) { SA[mf][nf][1] = -1e30f; SA[mf][nf][3] = -1e30f; }
                }
        } else if (t >= 2 * qt) {
#pragma unroll
            for (int mf = 0; mf < 2; mf++)
#pragma unroll
                for (int nf = 0; nf < 8; nf++) {
                    int colb = kt0 + nf * 8 + (lane & 3) * 2;
#pragma unroll
                    for (int hf = 0; hf < 2; hf++) {
                        int rowq = qt * 128 + wq * 32 + mf * 16 + (lane >> 2) + hf * 8;
                        if (colb     > rowq) SA[mf][nf][hf * 2]     = -1e30f;
                        if (colb + 1 > rowq) SA[mf][nf][hf * 2 + 1] = -1e30f;
                    }
                }
        }

#pragma unroll
        for (int mf = 0; mf < 2; mf++)
#pragma unroll
            for (int hf = 0; hf < 2; hf++) {
                float tm = -1e30f;
#pragma unroll
                for (int nf = 0; nf < 8; nf++) {
                    tm = fmaxf(tm, SA[mf][nf][hf * 2]);
                    tm = fmaxf(tm, SA[mf][nf][hf * 2 + 1]);
                }
                tm = fmaxf(tm, __shfl_xor_sync(0xFFFFFFFF, tm, 1));
                tm = fmaxf(tm, __shfl_xor_sync(0xFFFFFFFF, tm, 2));
                float mold = mrow[mf][hf];
                float mnew = fmaxf(mold, tm);
                float f = __expf(mold - mnew);
                float rs = 0.f;
#pragma unroll
                for (int nf = 0; nf < 8; nf++) {
                    float p0 = __expf(SA[mf][nf][hf * 2]     - mnew);
                    float p1 = __expf(SA[mf][nf][hf * 2 + 1] - mnew);
                    SA[mf][nf][hf * 2]     = p0;
                    SA[mf][nf][hf * 2 + 1] = p1;
                    rs += p0 + p1;
                }
                rs += __shfl_xor_sync(0xFFFFFFFF, rs, 1);
                rs += __shfl_xor_sync(0xFFFFFFFF, rs, 2);
                lrow[mf][hf] = lrow[mf][hf] * f + rs;
                mrow[mf][hf] = mnew;
#pragma unroll
                for (int nf = 0; nf < 8; nf++) {
                    OA[mf][nf][hf * 2]     *= f;
                    OA[mf][nf][hf * 2 + 1] *= f;
                }
            }

        // ---- O += P * V : 1 fp16 pass ----
#pragma unroll
        for (int kc = 0; kc < 4; kc++) {
            uint32_t ah[2][4];
#pragma unroll
            for (int mf = 0; mf < 2; mf++) {
                ah[mf][0] = packh2(SA[mf][2 * kc][0],     SA[mf][2 * kc][1]);
                ah[mf][1] = packh2(SA[mf][2 * kc][2],     SA[mf][2 * kc][3]);
                ah[mf][2] = packh2(SA[mf][2 * kc + 1][0], SA[mf][2 * kc + 1][1]);
                ah[mf][3] = packh2(SA[mf][2 * kc + 1][2], SA[mf][2 * kc + 1][3]);
            }
#pragma unroll
            for (int nq = 0; nq < 4; nq++) {
                uint32_t off = ((uint32_t)(kc * 16 + vrow) * 72 + nq * 16 + vnadd) * 2;
                uint32_t bv[4];
                LDSM_X4T(bv, sb + AV_S + off);
#pragma unroll
                for (int mf = 0; mf < 2; mf++) {
                    MMAH16816R(OA[mf][2 * nq],     ah[mf][0], ah[mf][1], ah[mf][2], ah[mf][3], bv[0], bv[1]);
                    MMAH16816R(OA[mf][2 * nq + 1], ah[mf][0], ah[mf][1], ah[mf][2], ah[mf][3], bv[2], bv[3]);
                }
            }
        }
    }

    // ---- epilogue: single fp16 for O-projection ----
#pragma unroll
    for (int mf = 0; mf < 2; mf++)
#pragma unroll
        for (int hf = 0; hf < 2; hf++) {
            float inv = 1.f / lrow[mf][hf];
            int row = w * WINN + qt * 128 + wq * 32 + mf * 16 + (lane >> 2) + hf * 8;
            size_t base = ((size_t)b * SS + row) * HIDD + h * DD;
#pragma unroll
            for (int nf = 0; nf < 8; nf++) {
                int d = nf * 8 + (lane & 3) * 2;
                uint32_t hv = packh2(OA[mf][nf][hf * 2] * inv, OA[mf][nf][hf * 2 + 1] * inv);
                *(uint32_t*)(oh + base + d) = hv;
            }
        }
}

// ---------------- launch ----------------
extern "C" void kernel_launch(void* const* d_in, const int* in_sizes, int n_in,
                              void* d_out, int out_size) {
    const float* hidden = (const float*)d_in[0];
    const float* Wq     = (const float*)d_in[1];
    const float* Wk     = (const float*)d_in[2];
    const float* Wv     = (const float*)d_in[3];
    const float* Wo     = (const float*)d_in[4];
    const float* mu     = (const float*)d_in[5];
    const float* phi    = (const float*)d_in[6];
    const float* cosT   = (const float*)d_in[7];
    const float* sinT   = (const float*)d_in[8];

    float *qb, *kb, *vb, *rkb, *rvb;
    __half *hidh, *aoh, *w16;
    cudaGetSymbolAddress((void**)&qb,   g_q);
    cudaGetSymbolAddress((void**)&kb,   g_k);
    cudaGetSymbolAddress((void**)&vb,   g_v);
    cudaGetSymbolAddress((void**)&rkb,  g_rfak);
    cudaGetSymbolAddress((void**)&rvb,  g_rfav);
    cudaGetSymbolAddress((void**)&hidh, g_hid_h);
    cudaGetSymbolAddress((void**)&aoh,  g_ao_h);
    cudaGetSymbolAddress((void**)&w16,  g_w16);

    static bool attr_set = false;
    if (!attr_set) {
        cudaFuncSetAttribute((const void*)gemm_f16,
                             cudaFuncAttributeMaxDynamicSharedMemorySize, QSMEM);
        cudaFuncSetAttribute((const void*)attn_mma,
                             cudaFuncAttributeMaxDynamicSharedMemorySize, AT_SMEM);
        attr_set = true;
    }

    const int WSZ = HIDD * HIDD;
    const int HN4 = MTOK * HIDD / 4;
    const int WN4 = WSZ / 4;

    // launches 0-2: converts; launch 3: big QKV GEMM (ncu capture slot)
    cvt16_all<<<dim3((WN4 + 255) / 256, 4), 256>>>(Wq, Wk, Wv, Wo, w16, WN4);
    cvt16_one<<<(HN4 / 2 + 255) / 256, 256>>>(hidden, hidh, HN4 / 2);
    cvt16_one<<<(HN4 / 2 + 255) / 256, 256>>>(hidden + MTOK * HIDD / 2,
                                              hidh + MTOK * HIDD / 2, HN4 / 2);

    // fused QKV GEMM with RoPE epilogue (all 1-pass fp16)
    gemm_f16<<<dim3(3072 / 256, MTOK / 128), 512, QSMEM>>>(hidh, w16, qb, kb, vb,
                                                           cosT, sinT, 1);

    rfa_kernel<<<BB * NHH * NCC, 128>>>(kb, vb, mu, phi, rkb, rvb);

    attn_mma<<<dim3(4, NWW, BB * NHH), 128, AT_SMEM>>>(qb, kb, vb, rkb, rvb, aoh);

    // O projection (1-pass fp16)
    gemm_f16<<<dim3(1024 / 256, MTOK / 128), 512, QSMEM>>>(aoh, w16 + 3 * WSZ,
                                                           (float*)d_out, (float*)d_out, (float*)d_out,
                                                           cosT, sinT, 0);
}

// round 15
// speedup vs baseline: 2.4646x; 1.0860x over previous
#include <cuda_runtime.h>
#include <cuda_bf16.h>
#include <cuda_fp16.h>
#include <cstdint>
#include <math.h>

// ---------------- problem constants ----------------
#define BB     4
#define SS     4096
#define HIDD   1024
#define NHH    16
#define DD     64
#define WINN   512
#define CHUNKK 128
#define NWW    8
#define NCC    32
#define SCALEF 0.125f
#define MTOK   (BB*SS)   // 16384
#define GK     1024

// ---------------- scratch (device globals) ----------------
__device__ float g_q[MTOK*HIDD];
__device__ float g_k[MTOK*HIDD];
__device__ float g_v[MTOK*HIDD];
__device__ float g_rfak[BB*NHH*NCC*DD];
__device__ float g_rfav[BB*NHH*NCC*DD];
__device__ __half g_hid_h[MTOK*HIDD];
__device__ __half g_ao_h[MTOK*HIDD];
__device__ __half g_w16[4*HIDD*HIDD];

// ================= helpers =================
__device__ __forceinline__ uint32_t smem_u32(const void* p) {
    uint32_t a;
    asm("{ .reg .u64 t; cvta.to.shared.u64 t, %1; cvt.u32.u64 %0, t; }" : "=r"(a) : "l"(p));
    return a;
}

#define LDSM_X4(r, a)                                                          \
    asm volatile("ldmatrix.sync.aligned.m8n8.x4.shared.b16 {%0,%1,%2,%3}, [%4];" \
        : "=r"((r)[0]), "=r"((r)[1]), "=r"((r)[2]), "=r"((r)[3]) : "r"(a))

#define LDSM_X4T(r, a)                                                         \
    asm volatile("ldmatrix.sync.aligned.m8n8.x4.trans.shared.b16 {%0,%1,%2,%3}, [%4];" \
        : "=r"((r)[0]), "=r"((r)[1]), "=r"((r)[2]), "=r"((r)[3]) : "r"(a))

#define MMAH16816(c, a, b0, b1)                                                \
    asm volatile("mma.sync.aligned.m16n8k16.row.col.f32.f16.f16.f32 "          \
        "{%0,%1,%2,%3}, {%4,%5,%6,%7}, {%8,%9}, {%0,%1,%2,%3};"                \
        : "+f"((c)[0]), "+f"((c)[1]), "+f"((c)[2]), "+f"((c)[3])               \
        : "r"((a)[0]), "r"((a)[1]), "r"((a)[2]), "r"((a)[3]), "r"(b0), "r"(b1))

#define MMAH16816R(c, a0, a1, a2, a3, b0, b1)                                  \
    asm volatile("mma.sync.aligned.m16n8k16.row.col.f32.f16.f16.f32 "          \
        "{%0,%1,%2,%3}, {%4,%5,%6,%7}, {%8,%9}, {%0,%1,%2,%3};"                \
        : "+f"((c)[0]), "+f"((c)[1]), "+f"((c)[2]), "+f"((c)[3])               \
        : "r"(a0), "r"(a1), "r"(a2), "r"(a3), "r"(b0), "r"(b1))

#define CPASYNC16(dst, src) \
    asm volatile("cp.async.cg.shared.global [%0], [%1], 16;" :: "r"(dst), "l"(src) : "memory")
#define CPCOMMIT() asm volatile("cp.async.commit_group;" ::: "memory")
#define CPWAIT1()  asm volatile("cp.async.wait_group 1;" ::: "memory")
#define CPWAIT0()  asm volatile("cp.async.wait_group 0;" ::: "memory")

// fp16 single store
__device__ __forceinline__ void cvtsts_h1(float4 f, uint32_t dst) {
    __half2 h0, h1;
    h0.x = __float2half(f.x); h0.y = __float2half(f.y);
    h1.x = __float2half(f.z); h1.y = __float2half(f.w);
    asm volatile("st.shared.v2.b32 [%0], {%1, %2};"
                 :: "r"(dst), "r"(*(uint32_t*)&h0), "r"(*(uint32_t*)&h1) : "memory");
}

__device__ __forceinline__ uint32_t packh2(float x, float y) {
    __half2 h;
    h.x = __float2half(x); h.y = __float2half(y);
    return *(uint32_t*)&h;
}

// ================= convert kernels =================
__global__ void cvt16_one(const float* __restrict__ src, __half* __restrict__ dst, int n4) {
    int i = blockIdx.x * blockDim.x + threadIdx.x;
    if (i >= n4) return;
    float4 f = ((const float4*)src)[i];
    __half2 a, b;
    a.x = __float2half(f.x); a.y = __float2half(f.y);
    b.x = __float2half(f.z); b.y = __float2half(f.w);
    ((uint2*)dst)[i] = make_uint2(*(uint32_t*)&a, *(uint32_t*)&b);
}

__global__ void cvt16_all(const float* __restrict__ W0, const float* __restrict__ W1,
                          const float* __restrict__ W2, const float* __restrict__ W3,
                          __half* __restrict__ dst, int n4) {
    int i = blockIdx.x * blockDim.x + threadIdx.x;
    if (i >= n4) return;
    const float* src = (blockIdx.y == 0) ? W0 : (blockIdx.y == 1) ? W1 : (blockIdx.y == 2) ? W2 : W3;
    float4 f = ((const float4*)src)[i];
    __half2 a, b;
    a.x = __float2half(f.x); a.y = __float2half(f.y);
    b.x = __float2half(f.z); b.y = __float2half(f.w);
    ((uint2*)(dst + (size_t)blockIdx.y * HIDD * HIDD))[i] = make_uint2(*(uint32_t*)&a, *(uint32_t*)&b);
}

// ============ fp16 GEMM: C = A[M,K] * B16[N,K]^T, fused RoPE epilogue ============
// CTA 128x256, 512 threads, warp tile 32x64, K-chunk 64, 3-stage cp.async
// stage: A[128 rows][144B] | B[256 rows][144B]   (row = 64 fp16 = 128B data + 16B pad)
#define QSTAGE 3
#define ATILE  18432
#define BTILE  36864
#define QBUF   (ATILE + BTILE)          // 55296
#define QSMEM  (QSTAGE * QBUF)          // 165888

__global__ void __launch_bounds__(512, 1)
gemm_f16(const __half* __restrict__ Ah,
         const __half* __restrict__ Bw,
         float* __restrict__ C0, float* __restrict__ C1, float* __restrict__ C2,
         const float* __restrict__ cosT, const float* __restrict__ sinT,
         int dorope) {
    extern __shared__ char dsm[];
    const uint32_t sbase = smem_u32(dsm);

    const int tid  = threadIdx.x;
    const int lane = tid & 31;
    const int wid  = tid >> 5;       // 0..15
    const int wm   = wid & 3;        // 0..3 (32-row stripes)
    const int wn   = wid >> 2;       // 0..3 (64-col stripes)
    const int m0   = blockIdx.y * 128;
    const int n0   = blockIdx.x * 256;

    const int sel = n0 >> 10;
    float* C = (sel == 0) ? C0 : (sel == 1) ? C1 : C2;
    const int nc0 = n0 & 1023;

    const int rowoff = ((lane >> 3) & 1) * 8 + (lane & 7);
    const int koff   = (lane >> 4) * 8;

    uint32_t aoffb[2], boffb[4];
#pragma unroll
    for (int mf = 0; mf < 2; mf++)
        aoffb[mf] = (uint32_t)(wm * 32 + mf * 16 + rowoff) * 144 + koff * 2;
#pragma unroll
    for (int nb = 0; nb < 4; nb++)
        boffb[nb] = ATILE + (uint32_t)(wn * 64 + nb * 16 + rowoff) * 144 + koff * 2;

    // cp.async mapping: per stage A=1024 chunks16, B=2048 chunks16; 512 threads
    const int arow0 = tid >> 3, ac8 = tid & 7;   // A chunk t: row=t>>3, col8=t&7
    float acc[2][8][4];
#pragma unroll
    for (int i = 0; i < 2; i++)
#pragma unroll
        for (int j = 0; j < 8; j++)
#pragma unroll
            for (int r = 0; r < 4; r++) acc[i][j][r] = 0.f;

    auto issue_stage = [&](int kc) {
        uint32_t base = sbase + (kc % QSTAGE) * QBUF;
        int kcol = kc * 64 + ac8 * 8;
        // A: rows arow0, arow0+64
#pragma unroll
        for (int i = 0; i < 2; i++) {
            int r = arow0 + i * 64;
            CPASYNC16(base + (uint32_t)r * 144 + ac8 * 16,
                      Ah + (size_t)(m0 + r) * GK + kcol);
        }
        // B: rows arow0, +64, +128, +192
#pragma unroll
        for (int i = 0; i < 4; i++) {
            int r = arow0 + i * 64;
            CPASYNC16(base + ATILE + (uint32_t)r * 144 + ac8 * 16,
                      Bw + (size_t)(n0 + r) * GK + kcol);
        }
        CPCOMMIT();
    };

    issue_stage(0);
    issue_stage(1);

    for (int kc = 0; kc < GK / 64; kc++) {
        CPWAIT1();
        __syncthreads();
        if (kc + 2 < GK / 64) issue_stage(kc + 2);
        else CPCOMMIT();

        const uint32_t stb = sbase + (kc % QSTAGE) * QBUF;

#pragma unroll
        for (int ks = 0; ks < 4; ks++) {
            const uint32_t ksb = stb + ks * 32;
            uint32_t af[2][4], bf[4][4];
#pragma unroll
            for (int nb = 0; nb < 4; nb++)
                LDSM_X4(bf[nb], ksb + boffb[nb]);
#pragma unroll
            for (int mf = 0; mf < 2; mf++)
                LDSM_X4(af[mf], ksb + aoffb[mf]);
#pragma unroll
            for (int mf = 0; mf < 2; mf++)
#pragma unroll
                for (int nf = 0; nf < 8; nf++)
                    MMAH16816(acc[mf][nf], af[mf], bf[nf >> 1][nf & 1], bf[nf >> 1][(nf & 1) + 2]);
        }
    }

    // ---- fused RoPE (q,k only) ----
    if (dorope && sel < 2) {
        CPWAIT0();
        __syncthreads();
        float* csm = (float*)dsm;            // [128][64]
        float* ssm = csm + 8192;             // [128][64]
        const int s0 = m0 & (SS - 1);
        for (int i = tid; i < 2048; i += 512) {
            ((float4*)csm)[i] = ((const float4*)(cosT + (size_t)s0 * DD))[i];
            ((float4*)ssm)[i] = ((const float4*)(sinT + (size_t)s0 * DD))[i];
        }
        __syncthreads();
#pragma unroll
        for (int mf = 0; mf < 2; mf++) {
            int rl0 = wm * 32 + mf * 16 + (lane >> 2);
#pragma unroll
            for (int hf = 0; hf < 2; hf++) {
                int rl = rl0 + hf * 8;
#pragma unroll
                for (int nf = 0; nf < 4; nf++) {
#pragma unroll
                    for (int j = 0; j < 2; j++) {
                        int d0 = nf * 8 + (lane & 3) * 2 + j;
                        float c1 = csm[rl * 64 + d0],      s1 = ssm[rl * 64 + d0];
                        float c2 = csm[rl * 64 + d0 + 32], s2 = ssm[rl * 64 + d0 + 32];
                        float x1 = acc[mf][nf][hf * 2 + j];
                        float x2 = acc[mf][nf + 4][hf * 2 + j];
                        acc[mf][nf][hf * 2 + j]     = x1 * c1 - x2 * s1;
                        acc[mf][nf + 4][hf * 2 + j] = x2 * c2 + x1 * s2;
                    }
                }
            }
        }
    }

#pragma unroll
    for (int mf = 0; mf < 2; mf++) {
        int r0 = m0 + wm * 32 + mf * 16 + (lane >> 2);
#pragma unroll
        for (int nf = 0; nf < 8; nf++) {
            int c0 = nc0 + wn * 64 + nf * 8 + (lane & 3) * 2;
            *(float2*)(C + (size_t)r0 * HIDD + c0)       = make_float2(acc[mf][nf][0], acc[mf][nf][1]);
            *(float2*)(C + (size_t)(r0 + 8) * HIDD + c0) = make_float2(acc[mf][nf][2], acc[mf][nf][3]);
        }
    }
}

// ================= per-chunk RFA summaries ((b,s,h,d)) =================
__global__ void __launch_bounds__(128) rfa_kernel(const float* __restrict__ k,
                                                  const float* __restrict__ v,
                                                  const float* __restrict__ mu,
                                                  const float* __restrict__ phi,
                                                  float* __restrict__ rk,
                                                  float* __restrict__ rv) {
    int bh = blockIdx.x / NCC;
    int c  = blockIdx.x % NCC;
    int b  = bh / NHH, h = bh % NHH;
    int j  = threadIdx.x;
    __shared__ float sb[CHUNKK], sg[CHUNKK];
    const float* kbase = k + (((size_t)b * SS + c * CHUNKK) * NHH + h) * DD;
    const float* vbase = v + (((size_t)b * SS + c * CHUNKK) * NHH + h) * DD;
    const float* kr = kbase + (size_t)j * HIDD;
    float dm = 0.f, dp = 0.f, nn = 0.f;
#pragma unroll
    for (int d = 0; d < DD; d++) {
        float kv = kr[d];
        dm += kv * mu[h * DD + d];
        dp += kv * phi[h * DD + d];
        nn += kv * kv;
    }
    float halfn = 0.5f * SCALEF * nn;
    sb[j] = SCALEF * dm - halfn;
    sg[j] = SCALEF * dp - halfn;
    __syncthreads();
    float mb = -1e30f, mg = -1e30f;
    for (int t = 0; t < CHUNKK; t++) { mb = fmaxf(mb, sb[t]); mg = fmaxf(mg, sg[t]); }
    float eb = expf(sb[j] - mb), eg = expf(sg[j] - mg);
    __syncthreads();
    sb[j] = eb; sg[j] = eg;
    __syncthreads();
    float zb = 0.f, zg = 0.f;
    for (int t = 0; t < CHUNKK; t++) { zb += sb[t]; zg += sg[t]; }
    float invb = 1.f / zb, invg = 1.f / zg;
    if (j < DD) {
        int d = j;
        float acc = 0.f;
        for (int t = 0; t < CHUNKK; t++) acc += sb[t] * kbase[(size_t)t * HIDD + d];
        rk[((size_t)bh * NCC + c) * DD + d] = acc * invb;
    } else {
        int d = j - DD;
        float acc = 0.f;
        for (int t = 0; t < CHUNKK; t++) acc += sg[t] * vbase[(size_t)t * HIDD + d];
        rv[((size_t)bh * NCC + c) * DD + d] = acc * invg;
    }
}

// ================= MMA flash attention (fp16: 1-pass QK, 1-pass PV) =================
// smem: Q[128][72], K[64][72], V[64][72] (fp16)
#define AQ_S 0
#define AK_S 18432
#define AV_S 27648
#define AT_SMEM 36864

__device__ __forceinline__ void fill_h(const float* __restrict__ src, int rstride,
                                       int rows, int rlimit, uint32_t dst, int tid, float scale) {
    const int col4 = tid & 15;
    const int r0   = tid >> 4;
    for (int r = r0; r < rows; r += 8) {
        float4 f;
        if (r < rlimit) {
            f = *(const float4*)(src + (size_t)r * rstride + col4 * 4);
            f.x *= scale; f.y *= scale; f.z *= scale; f.w *= scale;
        } else {
            f = make_float4(0.f, 0.f, 0.f, 0.f);
        }
        cvtsts_h1(f, dst + (uint32_t)r * 144 + col4 * 8);
    }
}

__global__ void __launch_bounds__(128, 2)
attn_mma(const float* __restrict__ q, const float* __restrict__ k,
         const float* __restrict__ v, const float* __restrict__ rk,
         const float* __restrict__ rv, __half* __restrict__ oh) {
    extern __shared__ char dsm[];
    const uint32_t sb = smem_u32(dsm);

    const int qt  = blockIdx.x;
    const int w   = blockIdx.y;
    const int bh  = blockIdx.z;
    const int b   = bh >> 4, h = bh & 15;
    const int tid = threadIdx.x, lane = tid & 31, wq = tid >> 5;

    const int rowoff = ((lane >> 3) & 1) * 8 + (lane & 7);
    const int koff   = (lane >> 4) * 8;
    const int vrow   = lane & 15;
    const int vnadd  = (lane >> 4) * 8;

    const float* qg = q + (((size_t)b * SS + w * WINN + qt * 128) * NHH + h) * DD;
    fill_h(qg, HIDD, 128, 128, sb + AQ_S, tid, SCALEF);

    float OA[2][8][4];
#pragma unroll
    for (int mf = 0; mf < 2; mf++)
#pragma unroll
        for (int nf = 0; nf < 8; nf++)
#pragma unroll
            for (int r = 0; r < 4; r++) OA[mf][nf][r] = 0.f;
    float mrow[2][2] = {{-1e30f, -1e30f}, {-1e30f, -1e30f}};
    float lrow[2][2] = {{0.f, 0.f}, {0.f, 0.f}};

    const float* kwin = k + (((size_t)b * SS + w * WINN) * NHH + h) * DD;
    const float* vwin = v + (((size_t)b * SS + w * WINN) * NHH + h) * DD;
    const float* rkb  = rk + (size_t)bh * NCC * DD;
    const float* rvb  = rv + (size_t)bh * NCC * DD;

    const int nwt    = 2 * qt + 2;
    const int nch    = 4 * w;
    const int ntile  = nwt + (nch > 0 ? 1 : 0);

    // pre-load Q fragments once (Q tile is reused for every K-tile)
    __syncthreads();
    uint32_t qf[4][2][4];   // [ks][mf][frag]
#pragma unroll
    for (int ks = 0; ks < 4; ks++)
#pragma unroll
        for (int mf = 0; mf < 2; mf++)
            LDSM_X4(qf[ks][mf], sb + AQ_S + (uint32_t)(wq * 32 + mf * 16 + rowoff) * 144 + (ks * 16 + koff) * 2);

    for (int t = 0; t < ntile; t++) {
        const bool ischunk = (t == nwt);
        const int kt0 = t * 64;
        __syncthreads();
        if (!ischunk) {
            fill_h(kwin + (size_t)kt0 * HIDD, HIDD, 64, 64, sb + AK_S, tid, 1.f);
            fill_h(vwin + (size_t)kt0 * HIDD, HIDD, 64, 64, sb + AV_S, tid, 1.f);
        } else {
            fill_h(rkb, DD, 64, nch, sb + AK_S, tid, 1.f);
            fill_h(rvb, DD, 64, nch, sb + AV_S, tid, 1.f);
        }
        __syncthreads();

        float SA[2][8][4];
#pragma unroll
        for (int mf = 0; mf < 2; mf++)
#pragma unroll
            for (int nf = 0; nf < 8; nf++)
#pragma unroll
                for (int r = 0; r < 4; r++) SA[mf][nf][r] = 0.f;

        // ---- S = Q * K^T : 1 fp16 pass ----
#pragma unroll
        for (int ks = 0; ks < 4; ks++) {
            uint32_t bf[4][4];
#pragma unroll
            for (int nb = 0; nb < 4; nb++)
                LDSM_X4(bf[nb], sb + AK_S + (uint32_t)(nb * 16 + rowoff) * 144 + (ks * 16 + koff) * 2);
#pragma unroll
            for (int mf = 0; mf < 2; mf++)
#pragma unroll
                for (int nf = 0; nf < 8; nf++)
                    MMAH16816(SA[mf][nf], qf[ks][mf], bf[nf >> 1][nf & 1], bf[nf >> 1][(nf & 1) + 2]);
        }

        if (ischunk) {
#pragma unroll
            for (int mf = 0; mf < 2; mf++)
#pragma unroll
                for (int nf = 0; nf < 8; nf++) {
                    int colb = nf * 8 + (lane & 3) * 2;
                    if (colb     >= nch) { SA[mf][nf][0] = -1e30f; SA[mf][nf][2] = -1e30f; }
                    if (colb + 1 >= nch) { SA[mf][nf][1] = -1e30f; SA[mf][nf][3] = -1e30f; }
                }
        } else if (t >= 2 * qt) {
#pragma unroll
            for (int mf = 0; mf < 2; mf++)
#pragma unroll
                for (int nf = 0; nf < 8; nf++) {
                    int colb = kt0 + nf * 8 + (lane & 3) * 2;
#pragma unroll
                    for (int hf = 0; hf < 2; hf++) {
                        int rowq = qt * 128 + wq * 32 + mf * 16 + (lane >> 2) + hf * 8;
                        if (colb     > rowq) SA[mf][nf][hf * 2]     = -1e30f;
                        if (colb + 1 > rowq) SA[mf][nf][hf * 2 + 1] = -1e30f;
                    }
                }
        }

#pragma unroll
        for (int mf = 0; mf < 2; mf++)
#pragma unroll
            for (int hf = 0; hf < 2; hf++) {
                float tm = -1e30f;
#pragma unroll
                for (int nf = 0; nf < 8; nf++) {
                    tm = fmaxf(tm, SA[mf][nf][hf * 2]);
                    tm = fmaxf(tm, SA[mf][nf][hf * 2 + 1]);
                }
                tm = fmaxf(tm, __shfl_xor_sync(0xFFFFFFFF, tm, 1));
                tm = fmaxf(tm, __shfl_xor_sync(0xFFFFFFFF, tm, 2));
                float mold = mrow[mf][hf];
                float mnew = fmaxf(mold, tm);
                float f = __expf(mold - mnew);
                float rs = 0.f;
#pragma unroll
                for (int nf = 0; nf < 8; nf++) {
                    float p0 = __expf(SA[mf][nf][hf * 2]     - mnew);
                    float p1 = __expf(SA[mf][nf][hf * 2 + 1] - mnew);
                    SA[mf][nf][hf * 2]     = p0;
                    SA[mf][nf][hf * 2 + 1] = p1;
                    rs += p0 + p1;
                }
                rs += __shfl_xor_sync(0xFFFFFFFF, rs, 1);
                rs += __shfl_xor_sync(0xFFFFFFFF, rs, 2);
                lrow[mf][hf] = lrow[mf][hf] * f + rs;
                mrow[mf][hf] = mnew;
#pragma unroll
                for (int nf = 0; nf < 8; nf++) {
                    OA[mf][nf][hf * 2]     *= f;
                    OA[mf][nf][hf * 2 + 1] *= f;
                }
            }

        // ---- O += P * V : 1 fp16 pass ----
#pragma unroll
        for (int kc = 0; kc < 4; kc++) {
            uint32_t ah[2][4];
#pragma unroll
            for (int mf = 0; mf < 2; mf++) {
                ah[mf][0] = packh2(SA[mf][2 * kc][0],     SA[mf][2 * kc][1]);
                ah[mf][1] = packh2(SA[mf][2 * kc][2],     SA[mf][2 * kc][3]);
                ah[mf][2] = packh2(SA[mf][2 * kc + 1][0], SA[mf][2 * kc + 1][1]);
                ah[mf][3] = packh2(SA[mf][2 * kc + 1][2], SA[mf][2 * kc + 1][3]);
            }
#pragma unroll
            for (int nq = 0; nq < 4; nq++) {
                uint32_t off = (uint32_t)(kc * 16 + vrow) * 144 + (nq * 16 + vnadd) * 2;
                uint32_t bv[4];
                LDSM_X4T(bv, sb + AV_S + off);
#pragma unroll
                for (int mf = 0; mf < 2; mf++) {
                    MMAH16816R(OA[mf][2 * nq],     ah[mf][0], ah[mf][1], ah[mf][2], ah[mf][3], bv[0], bv[1]);
                    MMAH16816R(OA[mf][2 * nq + 1], ah[mf][0], ah[mf][1], ah[mf][2], ah[mf][3], bv[2], bv[3]);
                }
            }
        }
    }

    // ---- epilogue: single fp16 for O-projection ----
#pragma unroll
    for (int mf = 0; mf < 2; mf++)
#pragma unroll
        for (int hf = 0; hf < 2; hf++) {
            float inv = 1.f / lrow[mf][hf];
            int row = w * WINN + qt * 128 + wq * 32 + mf * 16 + (lane >> 2) + hf * 8;
            size_t base = ((size_t)b * SS + row) * HIDD + h * DD;
#pragma unroll
            for (int nf = 0; nf < 8; nf++) {
                int d = nf * 8 + (lane & 3) * 2;
                uint32_t hv = packh2(OA[mf][nf][hf * 2] * inv, OA[mf][nf][hf * 2 + 1] * inv);
                *(uint32_t*)(oh + base + d) = hv;
            }
        }
}

// ---------------- launch ----------------
extern "C" void kernel_launch(void* const* d_in, const int* in_sizes, int n_in,
                              void* d_out, int out_size) {
    const float* hidden = (const float*)d_in[0];
    const float* Wq     = (const float*)d_in[1];
    const float* Wk     = (const float*)d_in[2];
    const float* Wv     = (const float*)d_in[3];
    const float* Wo     = (const float*)d_in[4];
    const float* mu     = (const float*)d_in[5];
    const float* phi    = (const float*)d_in[6];
    const float* cosT   = (const float*)d_in[7];
    const float* sinT   = (const float*)d_in[8];

    float *qb, *kb, *vb, *rkb, *rvb;
    __half *hidh, *aoh, *w16;
    cudaGetSymbolAddress((void**)&qb,   g_q);
    cudaGetSymbolAddress((void**)&kb,   g_k);
    cudaGetSymbolAddress((void**)&vb,   g_v);
    cudaGetSymbolAddress((void**)&rkb,  g_rfak);
    cudaGetSymbolAddress((void**)&rvb,  g_rfav);
    cudaGetSymbolAddress((void**)&hidh, g_hid_h);
    cudaGetSymbolAddress((void**)&aoh,  g_ao_h);
    cudaGetSymbolAddress((void**)&w16,  g_w16);

    static bool attr_set = false;
    if (!attr_set) {
        cudaFuncSetAttribute((const void*)gemm_f16,
                             cudaFuncAttributeMaxDynamicSharedMemorySize, QSMEM);
        cudaFuncSetAttribute((const void*)attn_mma,
                             cudaFuncAttributeMaxDynamicSharedMemorySize, AT_SMEM);
        attr_set = true;
    }

    const int WSZ = HIDD * HIDD;
    const int HN4 = MTOK * HIDD / 4;
    const int WN4 = WSZ / 4;

    // launches 0-2: converts; launch 3: big QKV GEMM (ncu capture slot)
    cvt16_all<<<dim3((WN4 + 255) / 256, 4), 256>>>(Wq, Wk, Wv, Wo, w16, WN4);
    cvt16_one<<<(HN4 / 2 + 255) / 256, 256>>>(hidden, hidh, HN4 / 2);
    cvt16_one<<<(HN4 / 2 + 255) / 256, 256>>>(hidden + MTOK * HIDD / 2,
                                              hidh + MTOK * HIDD / 2, HN4 / 2);

    // fused QKV GEMM with RoPE epilogue (1-pass fp16, K-chunk 64)
    gemm_f16<<<dim3(3072 / 256, MTOK / 128), 512, QSMEM>>>(hidh, w16, qb, kb, vb,
                                                           cosT, sinT, 1);

    rfa_kernel<<<BB * NHH * NCC, 128>>>(kb, vb, mu, phi, rkb, rvb);

    attn_mma<<<dim3(4, NWW, BB * NHH), 128, AT_SMEM>>>(qb, kb, vb, rkb, rvb, aoh);

    // O projection (1-pass fp16)
    gemm_f16<<<dim3(1024 / 256, MTOK / 128), 512, QSMEM>>>(aoh, w16 + 3 * WSZ,
                                                           (float*)d_out, (float*)d_out, (float*)d_out,
                                                           cosT, sinT, 0);
}

// round 16
// speedup vs baseline: 2.6982x; 1.0948x over previous
#include <cuda_runtime.h>
#include <cuda_bf16.h>
#include <cuda_fp16.h>
#include <cstdint>
#include <math.h>

// ---------------- problem constants ----------------
#define BB     4
#define SS     4096
#define HIDD   1024
#define NHH    16
#define DD     64
#define WINN   512
#define CHUNKK 128
#define NWW    8
#define NCC    32
#define SCALEF 0.125f
#define MTOK   (BB*SS)   // 16384
#define GK     1024

// ---------------- scratch (device globals) ----------------
__device__ __half g_q16[MTOK*HIDD];
__device__ __half g_k16[MTOK*HIDD];
__device__ __half g_v16[MTOK*HIDD];
__device__ __half g_rfak16[BB*NHH*NCC*DD];
__device__ __half g_rfav16[BB*NHH*NCC*DD];
__device__ __half g_hid_h[MTOK*HIDD];
__device__ __half g_ao_h[MTOK*HIDD];
__device__ __half g_w16[4*HIDD*HIDD];

// ================= helpers =================
__device__ __forceinline__ uint32_t smem_u32(const void* p) {
    uint32_t a;
    asm("{ .reg .u64 t; cvta.to.shared.u64 t, %1; cvt.u32.u64 %0, t; }" : "=r"(a) : "l"(p));
    return a;
}

#define LDSM_X4(r, a)                                                          \
    asm volatile("ldmatrix.sync.aligned.m8n8.x4.shared.b16 {%0,%1,%2,%3}, [%4];" \
        : "=r"((r)[0]), "=r"((r)[1]), "=r"((r)[2]), "=r"((r)[3]) : "r"(a))

#define LDSM_X4T(r, a)                                                         \
    asm volatile("ldmatrix.sync.aligned.m8n8.x4.trans.shared.b16 {%0,%1,%2,%3}, [%4];" \
        : "=r"((r)[0]), "=r"((r)[1]), "=r"((r)[2]), "=r"((r)[3]) : "r"(a))

#define MMAH16816(c, a, b0, b1)                                                \
    asm volatile("mma.sync.aligned.m16n8k16.row.col.f32.f16.f16.f32 "          \
        "{%0,%1,%2,%3}, {%4,%5,%6,%7}, {%8,%9}, {%0,%1,%2,%3};"                \
        : "+f"((c)[0]), "+f"((c)[1]), "+f"((c)[2]), "+f"((c)[3])               \
        : "r"((a)[0]), "r"((a)[1]), "r"((a)[2]), "r"((a)[3]), "r"(b0), "r"(b1))

#define MMAH16816R(c, a0, a1, a2, a3, b0, b1)                                  \
    asm volatile("mma.sync.aligned.m16n8k16.row.col.f32.f16.f16.f32 "          \
        "{%0,%1,%2,%3}, {%4,%5,%6,%7}, {%8,%9}, {%0,%1,%2,%3};"                \
        : "+f"((c)[0]), "+f"((c)[1]), "+f"((c)[2]), "+f"((c)[3])               \
        : "r"(a0), "r"(a1), "r"(a2), "r"(a3), "r"(b0), "r"(b1))

#define CPASYNC16(dst, src) \
    asm volatile("cp.async.cg.shared.global [%0], [%1], 16;" :: "r"(dst), "l"(src) : "memory")
#define CPASYNC16P(dst, src, sz) \
    asm volatile("cp.async.cg.shared.global [%0], [%1], 16, %2;" :: "r"(dst), "l"(src), "r"(sz) : "memory")
#define CPCOMMIT() asm volatile("cp.async.commit_group;" ::: "memory")
#define CPWAIT1()  asm volatile("cp.async.wait_group 1;" ::: "memory")
#define CPWAIT0()  asm volatile("cp.async.wait_group 0;" ::: "memory")

__device__ __forceinline__ uint32_t packh2(float x, float y) {
    __half2 h;
    h.x = __float2half(x); h.y = __float2half(y);
    return *(uint32_t*)&h;
}

// ================= convert kernels =================
__global__ void cvt16_one(const float* __restrict__ src, __half* __restrict__ dst, int n4) {
    int i = blockIdx.x * blockDim.x + threadIdx.x;
    if (i >= n4) return;
    float4 f = ((const float4*)src)[i];
    ((uint2*)dst)[i] = make_uint2(packh2(f.x, f.y), packh2(f.z, f.w));
}

__global__ void cvt16_all(const float* __restrict__ W0, const float* __restrict__ W1,
                          const float* __restrict__ W2, const float* __restrict__ W3,
                          __half* __restrict__ dst, int n4) {
    int i = blockIdx.x * blockDim.x + threadIdx.x;
    if (i >= n4) return;
    const float* src = (blockIdx.y == 0) ? W0 : (blockIdx.y == 1) ? W1 : (blockIdx.y == 2) ? W2 : W3;
    float4 f = ((const float4*)src)[i];
    ((uint2*)(dst + (size_t)blockIdx.y * HIDD * HIDD))[i] = make_uint2(packh2(f.x, f.y), packh2(f.z, f.w));
}

// ============ fp16 GEMM: C = A[M,K] * B16[N,K]^T, fused RoPE, fp16 or fp32 out ============
// CTA 128x256, 512 threads, warp tile 32x64, K-chunk 64, 3-stage cp.async
#define QSTAGE 3
#define ATILE  18432
#define BTILE  36864
#define QBUF   (ATILE + BTILE)          // 55296
#define QSMEM  (QSTAGE * QBUF)          // 165888

__global__ void __launch_bounds__(512, 1)
gemm_f16(const __half* __restrict__ Ah,
         const __half* __restrict__ Bw,
         __half* __restrict__ H0, __half* __restrict__ H1, __half* __restrict__ H2,
         float* __restrict__ Cf,
         const float* __restrict__ cosT, const float* __restrict__ sinT,
         int dorope, int out16) {
    extern __shared__ char dsm[];
    const uint32_t sbase = smem_u32(dsm);

    const int tid  = threadIdx.x;
    const int lane = tid & 31;
    const int wid  = tid >> 5;       // 0..15
    const int wm   = wid & 3;        // 0..3 (32-row stripes)
    const int wn   = wid >> 2;       // 0..3 (64-col stripes)
    const int m0   = blockIdx.y * 128;
    const int n0   = blockIdx.x * 256;

    const int sel = n0 >> 10;
    const int nc0 = n0 & 1023;

    const int rowoff = ((lane >> 3) & 1) * 8 + (lane & 7);
    const int koff   = (lane >> 4) * 8;

    uint32_t aoffb[2], boffb[4];
#pragma unroll
    for (int mf = 0; mf < 2; mf++)
        aoffb[mf] = (uint32_t)(wm * 32 + mf * 16 + rowoff) * 144 + koff * 2;
#pragma unroll
    for (int nb = 0; nb < 4; nb++)
        boffb[nb] = ATILE + (uint32_t)(wn * 64 + nb * 16 + rowoff) * 144 + koff * 2;

    const int arow0 = tid >> 3, ac8 = tid & 7;
    float acc[2][8][4];
#pragma unroll
    for (int i = 0; i < 2; i++)
#pragma unroll
        for (int j = 0; j < 8; j++)
#pragma unroll
            for (int r = 0; r < 4; r++) acc[i][j][r] = 0.f;

    auto issue_stage = [&](int kc) {
        uint32_t base = sbase + (kc % QSTAGE) * QBUF;
        int kcol = kc * 64 + ac8 * 8;
#pragma unroll
        for (int i = 0; i < 2; i++) {
            int r = arow0 + i * 64;
            CPASYNC16(base + (uint32_t)r * 144 + ac8 * 16,
                      Ah + (size_t)(m0 + r) * GK + kcol);
        }
#pragma unroll
        for (int i = 0; i < 4; i++) {
            int r = arow0 + i * 64;
            CPASYNC16(base + ATILE + (uint32_t)r * 144 + ac8 * 16,
                      Bw + (size_t)(n0 + r) * GK + kcol);
        }
        CPCOMMIT();
    };

    issue_stage(0);
    issue_stage(1);

    for (int kc = 0; kc < GK / 64; kc++) {
        CPWAIT1();
        __syncthreads();
        if (kc + 2 < GK / 64) issue_stage(kc + 2);
        else CPCOMMIT();

        const uint32_t stb = sbase + (kc % QSTAGE) * QBUF;

#pragma unroll
        for (int ks = 0; ks < 4; ks++) {
            const uint32_t ksb = stb + ks * 32;
            uint32_t af[2][4], bf[4][4];
#pragma unroll
            for (int nb = 0; nb < 4; nb++)
                LDSM_X4(bf[nb], ksb + boffb[nb]);
#pragma unroll
            for (int mf = 0; mf < 2; mf++)
                LDSM_X4(af[mf], ksb + aoffb[mf]);
#pragma unroll
            for (int mf = 0; mf < 2; mf++)
#pragma unroll
                for (int nf = 0; nf < 8; nf++)
                    MMAH16816(acc[mf][nf], af[mf], bf[nf >> 1][nf & 1], bf[nf >> 1][(nf & 1) + 2]);
        }
    }

    // ---- fused RoPE (q,k only) ----
    if (dorope && sel < 2) {
        CPWAIT0();
        __syncthreads();
        float* csm = (float*)dsm;            // [128][64]
        float* ssm = csm + 8192;             // [128][64]
        const int s0 = m0 & (SS - 1);
        for (int i = tid; i < 2048; i += 512) {
            ((float4*)csm)[i] = ((const float4*)(cosT + (size_t)s0 * DD))[i];
            ((float4*)ssm)[i] = ((const float4*)(sinT + (size_t)s0 * DD))[i];
        }
        __syncthreads();
#pragma unroll
        for (int mf = 0; mf < 2; mf++) {
            int rl0 = wm * 32 + mf * 16 + (lane >> 2);
#pragma unroll
            for (int hf = 0; hf < 2; hf++) {
                int rl = rl0 + hf * 8;
#pragma unroll
                for (int nf = 0; nf < 4; nf++) {
#pragma unroll
                    for (int j = 0; j < 2; j++) {
                        int d0 = nf * 8 + (lane & 3) * 2 + j;
                        float c1 = csm[rl * 64 + d0],      s1 = ssm[rl * 64 + d0];
                        float c2 = csm[rl * 64 + d0 + 32], s2 = ssm[rl * 64 + d0 + 32];
                        float x1 = acc[mf][nf][hf * 2 + j];
                        float x2 = acc[mf][nf + 4][hf * 2 + j];
                        acc[mf][nf][hf * 2 + j]     = x1 * c1 - x2 * s1;
                        acc[mf][nf + 4][hf * 2 + j] = x2 * c2 + x1 * s2;
                    }
                }
            }
        }
    }

    if (out16) {
        __half* Ch = (sel == 0) ? H0 : (sel == 1) ? H1 : H2;
        const float sc = (sel == 0) ? SCALEF : 1.f;   // pre-scale q by SCALEF
#pragma unroll
        for (int mf = 0; mf < 2; mf++) {
            int r0 = m0 + wm * 32 + mf * 16 + (lane >> 2);
#pragma unroll
            for (int nf = 0; nf < 8; nf++) {
                int c0 = nc0 + wn * 64 + nf * 8 + (lane & 3) * 2;
                *(uint32_t*)(Ch + (size_t)r0 * HIDD + c0)       = packh2(acc[mf][nf][0] * sc, acc[mf][nf][1] * sc);
                *(uint32_t*)(Ch + (size_t)(r0 + 8) * HIDD + c0) = packh2(acc[mf][nf][2] * sc, acc[mf][nf][3] * sc);
            }
        }
    } else {
#pragma unroll
        for (int mf = 0; mf < 2; mf++) {
            int r0 = m0 + wm * 32 + mf * 16 + (lane >> 2);
#pragma unroll
            for (int nf = 0; nf < 8; nf++) {
                int c0 = nc0 + wn * 64 + nf * 8 + (lane & 3) * 2;
                *(float2*)(Cf + (size_t)r0 * HIDD + c0)       = make_float2(acc[mf][nf][0], acc[mf][nf][1]);
                *(float2*)(Cf + (size_t)(r0 + 8) * HIDD + c0) = make_float2(acc[mf][nf][2], acc[mf][nf][3]);
            }
        }
    }
}

// ================= per-chunk RFA summaries (fp16 in/out, fp32 math) =================
__global__ void __launch_bounds__(128) rfa_kernel(const __half* __restrict__ k,
                                                  const __half* __restrict__ v,
                                                  const float* __restrict__ mu,
                                                  const float* __restrict__ phi,
                                                  __half* __restrict__ rk,
                                                  __half* __restrict__ rv) {
    int bh = blockIdx.x / NCC;
    int c  = blockIdx.x % NCC;
    int b  = bh / NHH, h = bh % NHH;
    int j  = threadIdx.x;
    __shared__ float sb[CHUNKK], sg[CHUNKK];
    const __half* kbase = k + (((size_t)b * SS + c * CHUNKK) * NHH + h) * DD;
    const __half* vbase = v + (((size_t)b * SS + c * CHUNKK) * NHH + h) * DD;
    const __half* kr = kbase + (size_t)j * HIDD;
    float dm = 0.f, dp = 0.f, nn = 0.f;
#pragma unroll
    for (int d = 0; d < DD; d++) {
        float kv = __half2float(kr[d]);
        dm += kv * mu[h * DD + d];
        dp += kv * phi[h * DD + d];
        nn += kv * kv;
    }
    float halfn = 0.5f * SCALEF * nn;
    sb[j] = SCALEF * dm - halfn;
    sg[j] = SCALEF * dp - halfn;
    __syncthreads();
    float mb = -1e30f, mg = -1e30f;
    for (int t = 0; t < CHUNKK; t++) { mb = fmaxf(mb, sb[t]); mg = fmaxf(mg, sg[t]); }
    float eb = expf(sb[j] - mb), eg = expf(sg[j] - mg);
    __syncthreads();
    sb[j] = eb; sg[j] = eg;
    __syncthreads();
    float zb = 0.f, zg = 0.f;
    for (int t = 0; t < CHUNKK; t++) { zb += sb[t]; zg += sg[t]; }
    float invb = 1.f / zb, invg = 1.f / zg;
    if (j < DD) {
        int d = j;
        float acc = 0.f;
        for (int t = 0; t < CHUNKK; t++) acc += sb[t] * __half2float(kbase[(size_t)t * HIDD + d]);
        rk[((size_t)bh * NCC + c) * DD + d] = __float2half(acc * invb);
    } else {
        int d = j - DD;
        float acc = 0.f;
        for (int t = 0; t < CHUNKK; t++) acc += sg[t] * __half2float(vbase[(size_t)t * HIDD + d]);
        rv[((size_t)bh * NCC + c) * DD + d] = __float2half(acc * invg);
    }
}

// ================= MMA flash attention (fp16 ops, cp.async double-buffered K/V) =================
// smem: Q[128][144B] | buf0{K[64][144],V[64][144]} | buf1{...}
#define AQ_S   0
#define ABUF(i) (18432 + (i) * 18432)
#define AVOFF  9216
#define AT_SMEM 55296

__global__ void __launch_bounds__(128, 2)
attn_mma(const __half* __restrict__ q, const __half* __restrict__ k,
         const __half* __restrict__ v, const __half* __restrict__ rk,
         const __half* __restrict__ rv, __half* __restrict__ oh) {
    extern __shared__ char dsm[];
    const uint32_t sb = smem_u32(dsm);

    const int qt  = blockIdx.x;
    const int w   = blockIdx.y;
    const int bh  = blockIdx.z;
    const int b   = bh >> 4, h = bh & 15;
    const int tid = threadIdx.x, lane = tid & 31, wq = tid >> 5;

    const int rowoff = ((lane >> 3) & 1) * 8 + (lane & 7);
    const int koff   = (lane >> 4) * 8;
    const int vrow   = lane & 15;
    const int vnadd  = (lane >> 4) * 8;

    const __half* qg   = q + (((size_t)b * SS + w * WINN + qt * 128) * NHH + h) * DD;
    const __half* kwin = k + (((size_t)b * SS + w * WINN) * NHH + h) * DD;
    const __half* vwin = v + (((size_t)b * SS + w * WINN) * NHH + h) * DD;
    const __half* rkb  = rk + (size_t)bh * NCC * DD;
    const __half* rvb  = rv + (size_t)bh * NCC * DD;

    const int nwt    = 2 * qt + 2;
    const int nch    = 4 * w;
    const int ntile  = nwt + (nch > 0 ? 1 : 0);

    // chunk mapping for fills: 1024 chunks (Q) / 512 (K or V tile)
    const int qrow = tid >> 3, qc8 = tid & 7;

    // ---- issue Q (group 0) ----
#pragma unroll
    for (int i = 0; i < 8; i++) {
        int r = qrow + i * 16;
        CPASYNC16(sb + AQ_S + (uint32_t)r * 144 + qc8 * 16,
                  qg + (size_t)r * HIDD + qc8 * 8);
    }
    CPCOMMIT();

    auto issue_tile = [&](int t) {
        const uint32_t kd = sb + ABUF(t & 1);
        const uint32_t vd = kd + AVOFF;
        if (t < nwt) {
            const __half* ks = kwin + (size_t)(t * 64) * HIDD;
            const __half* vs = vwin + (size_t)(t * 64) * HIDD;
#pragma unroll
            for (int i = 0; i < 4; i++) {
                int ch = tid + i * 128, r = ch >> 3, c8 = ch & 7;
                CPASYNC16(kd + (uint32_t)r * 144 + c8 * 16, ks + (size_t)r * HIDD + c8 * 8);
                CPASYNC16(vd + (uint32_t)r * 144 + c8 * 16, vs + (size_t)r * HIDD + c8 * 8);
            }
        } else {
#pragma unroll
            for (int i = 0; i < 4; i++) {
                int ch = tid + i * 128, r = ch >> 3, c8 = ch & 7;
                uint32_t sz = (r < nch) ? 16u : 0u;
                size_t off = (r < nch) ? ((size_t)r * DD + c8 * 8) : 0;
                CPASYNC16P(kd + (uint32_t)r * 144 + c8 * 16, rkb + off, sz);
                CPASYNC16P(vd + (uint32_t)r * 144 + c8 * 16, rvb + off, sz);
            }
        }
        CPCOMMIT();
    };

    issue_tile(0);
    CPWAIT1();          // Q complete (tile 0 may be in flight)
    __syncthreads();

    // pre-load Q fragments once
    uint32_t qf[4][2][4];
#pragma unroll
    for (int ks = 0; ks < 4; ks++)
#pragma unroll
        for (int mf = 0; mf < 2; mf++)
            LDSM_X4(qf[ks][mf], sb + AQ_S + (uint32_t)(wq * 32 + mf * 16 + rowoff) * 144 + (ks * 16 + koff) * 2);

    float OA[2][8][4];
#pragma unroll
    for (int mf = 0; mf < 2; mf++)
#pragma unroll
        for (int nf = 0; nf < 8; nf++)
#pragma unroll
            for (int r = 0; r < 4; r++) OA[mf][nf][r] = 0.f;
    float mrow[2][2] = {{-1e30f, -1e30f}, {-1e30f, -1e30f}};
    float lrow[2][2] = {{0.f, 0.f}, {0.f, 0.f}};

    for (int t = 0; t < ntile; t++) {
        const bool ischunk = (t == nwt);
        const int kt0 = t * 64;
        const bool more = (t + 1 < ntile);
        if (more) issue_tile(t + 1);
        if (more) { CPWAIT1(); } else { CPWAIT0(); }
        __syncthreads();

        const uint32_t kbs = sb + ABUF(t & 1);
        const uint32_t vbs = kbs + AVOFF;

        float SA[2][8][4];
#pragma unroll
        for (int mf = 0; mf < 2; mf++)
#pragma unroll
            for (int nf = 0; nf < 8; nf++)
#pragma unroll
                for (int r = 0; r < 4; r++) SA[mf][nf][r] = 0.f;

        // ---- S = Q * K^T ----
#pragma unroll
        for (int ks = 0; ks < 4; ks++) {
            uint32_t bf[4][4];
#pragma unroll
            for (int nb = 0; nb < 4; nb++)
                LDSM_X4(bf[nb], kbs + (uint32_t)(nb * 16 + rowoff) * 144 + (ks * 16 + koff) * 2);
#pragma unroll
            for (int mf = 0; mf < 2; mf++)
#pragma unroll
                for (int nf = 0; nf < 8; nf++)
                    MMAH16816(SA[mf][nf], qf[ks][mf], bf[nf >> 1][nf & 1], bf[nf >> 1][(nf & 1) + 2]);
        }

        if (ischunk) {
#pragma unroll
            for (int mf = 0; mf < 2; mf++)
#pragma unroll
                for (int nf = 0; nf < 8; nf++) {
                    int colb = nf * 8 + (lane & 3) * 2;
                    if (colb     >= nch) { SA[mf][nf][0] = -1e30f; SA[mf][nf][2] = -1e30f; }
                    if (colb + 1 >= nch) { SA[mf][nf][1] = -1e30f; SA[mf][nf][3] = -1e30f; }
                }
        } else if (t >= 2 * qt) {
#pragma unroll
            for (int mf = 0; mf < 2; mf++)
#pragma unroll
                for (int nf = 0; nf < 8; nf++) {
                    int colb = kt0 + nf * 8 + (lane & 3) * 2;
#pragma unroll
                    for (int hf = 0; hf < 2; hf++) {
                        int rowq = qt * 128 + wq * 32 + mf * 16 + (lane >> 2) + hf * 8;
                        if (colb     > rowq) SA[mf][nf][hf * 2]     = -1e30f;
                        if (colb + 1 > rowq) SA[mf][nf][hf * 2 + 1] = -1e30f;
                    }
                }
        }

#pragma unroll
        for (int mf = 0; mf < 2; mf++)
#pragma unroll
            for (int hf = 0; hf < 2; hf++) {
                float tm = -1e30f;
#pragma unroll
                for (int nf = 0; nf < 8; nf++) {
                    tm = fmaxf(tm, SA[mf][nf][hf * 2]);
                    tm = fmaxf(tm, SA[mf][nf][hf * 2 + 1]);
                }
                tm = fmaxf(tm, __shfl_xor_sync(0xFFFFFFFF, tm, 1));
                tm = fmaxf(tm, __shfl_xor_sync(0xFFFFFFFF, tm, 2));
                float mold = mrow[mf][hf];
                float mnew = fmaxf(mold, tm);
                float f = __expf(mold - mnew);
                float rs = 0.f;
#pragma unroll
                for (int nf = 0; nf < 8; nf++) {
                    float p0 = __expf(SA[mf][nf][hf * 2]     - mnew);
                    float p1 = __expf(SA[mf][nf][hf * 2 + 1] - mnew);
                    SA[mf][nf][hf * 2]     = p0;
                    SA[mf][nf][hf * 2 + 1] = p1;
                    rs += p0 + p1;
                }
                rs += __shfl_xor_sync(0xFFFFFFFF, rs, 1);
                rs += __shfl_xor_sync(0xFFFFFFFF, rs, 2);
                lrow[mf][hf] = lrow[mf][hf] * f + rs;
                mrow[mf][hf] = mnew;
#pragma unroll
                for (int nf = 0; nf < 8; nf++) {
                    OA[mf][nf][hf * 2]     *= f;
                    OA[mf][nf][hf * 2 + 1] *= f;
                }
            }

        // ---- O += P * V ----
#pragma unroll
        for (int kc = 0; kc < 4; kc++) {
            uint32_t ah[2][4];
#pragma unroll
            for (int mf = 0; mf < 2; mf++) {
                ah[mf][0] = packh2(SA[mf][2 * kc][0],     SA[mf][2 * kc][1]);
                ah[mf][1] = packh2(SA[mf][2 * kc][2],     SA[mf][2 * kc][3]);
                ah[mf][2] = packh2(SA[mf][2 * kc + 1][0], SA[mf][2 * kc + 1][1]);
                ah[mf][3] = packh2(SA[mf][2 * kc + 1][2], SA[mf][2 * kc + 1][3]);
            }
#pragma unroll
            for (int nq = 0; nq < 4; nq++) {
                uint32_t off = (uint32_t)(kc * 16 + vrow) * 144 + (nq * 16 + vnadd) * 2;
                uint32_t bv[4];
                LDSM_X4T(bv, vbs + off);
#pragma unroll
                for (int mf = 0; mf < 2; mf++) {
                    MMAH16816R(OA[mf][2 * nq],     ah[mf][0], ah[mf][1], ah[mf][2], ah[mf][3], bv[0], bv[1]);
                    MMAH16816R(OA[mf][2 * nq + 1], ah[mf][0], ah[mf][1], ah[mf][2], ah[mf][3], bv[2], bv[3]);
                }
            }
        }
        __syncthreads();
    }

    // ---- epilogue: single fp16 for O-projection ----
#pragma unroll
    for (int mf = 0; mf < 2; mf++)
#pragma unroll
        for (int hf = 0; hf < 2; hf++) {
            float inv = 1.f / lrow[mf][hf];
            int row = w * WINN + qt * 128 + wq * 32 + mf * 16 + (lane >> 2) + hf * 8;
            size_t base = ((size_t)b * SS + row) * HIDD + h * DD;
#pragma unroll
            for (int nf = 0; nf < 8; nf++) {
                int d = nf * 8 + (lane & 3) * 2;
                *(uint32_t*)(oh + base + d) = packh2(OA[mf][nf][hf * 2] * inv, OA[mf][nf][hf * 2 + 1] * inv);
            }
        }
}

// ---------------- launch ----------------
extern "C" void kernel_launch(void* const* d_in, const int* in_sizes, int n_in,
                              void* d_out, int out_size) {
    const float* hidden = (const float*)d_in[0];
    const float* Wq     = (const float*)d_in[1];
    const float* Wk     = (const float*)d_in[2];
    const float* Wv     = (const float*)d_in[3];
    const float* Wo     = (const float*)d_in[4];
    const float* mu     = (const float*)d_in[5];
    const float* phi    = (const float*)d_in[6];
    const float* cosT   = (const float*)d_in[7];
    const float* sinT   = (const float*)d_in[8];

    __half *qb, *kb, *vb, *rkb, *rvb, *hidh, *aoh, *w16;
    cudaGetSymbolAddress((void**)&qb,   g_q16);
    cudaGetSymbolAddress((void**)&kb,   g_k16);
    cudaGetSymbolAddress((void**)&vb,   g_v16);
    cudaGetSymbolAddress((void**)&rkb,  g_rfak16);
    cudaGetSymbolAddress((void**)&rvb,  g_rfav16);
    cudaGetSymbolAddress((void**)&hidh, g_hid_h);
    cudaGetSymbolAddress((void**)&aoh,  g_ao_h);
    cudaGetSymbolAddress((void**)&w16,  g_w16);

    static bool attr_set = false;
    if (!attr_set) {
        cudaFuncSetAttribute((const void*)gemm_f16,
                             cudaFuncAttributeMaxDynamicSharedMemorySize, QSMEM);
        cudaFuncSetAttribute((const void*)attn_mma,
                             cudaFuncAttributeMaxDynamicSharedMemorySize, AT_SMEM);
        attr_set = true;
    }

    const int WSZ = HIDD * HIDD;
    const int HN4 = MTOK * HIDD / 4;
    const int WN4 = WSZ / 4;

    // launches 0-2: converts; launch 3: big QKV GEMM (ncu capture slot)
    cvt16_all<<<dim3((WN4 + 255) / 256, 4), 256>>>(Wq, Wk, Wv, Wo, w16, WN4);
    cvt16_one<<<(HN4 / 2 + 255) / 256, 256>>>(hidden, hidh, HN4 / 2);
    cvt16_one<<<(HN4 / 2 + 255) / 256, 256>>>(hidden + MTOK * HIDD / 2,
                                              hidh + MTOK * HIDD / 2, HN4 / 2);

    // fused QKV GEMM with RoPE, fp16 outputs (q pre-scaled by SCALEF)
    gemm_f16<<<dim3(3072 / 256, MTOK / 128), 512, QSMEM>>>(hidh, w16, qb, kb, vb, nullptr,
                                                           cosT, sinT, 1, 1);

    rfa_kernel<<<BB * NHH * NCC, 128>>>(kb, vb, mu, phi, rkb, rvb);

    attn_mma<<<dim3(4, NWW, BB * NHH), 128, AT_SMEM>>>(qb, kb, vb, rkb, rvb, aoh);

    // O projection (fp32 out to d_out)
    gemm_f16<<<dim3(1024 / 256, MTOK / 128), 512, QSMEM>>>(aoh, w16 + 3 * WSZ,
                                                           nullptr, nullptr, nullptr, (float*)d_out,
                                                           cosT, sinT, 0, 0);
}